// round 11
// baseline (speedup 1.0000x reference)
#include <cuda_runtime.h>
#include <math.h>
#include <stdint.h>

#define BB      4
#define SS      1024
#define DD      512
#define HH      8
#define DEP     64
#define DFFN    2048
#define NLAYERS 4

#define XN  (BB*SS*DD)       /* 2097152  */
#define AWN (BB*HH*SS*SS)    /* 33554432 */

// ---------------- device scratch (no allocation allowed) ----------------
__device__ float    g_x   [XN];
__device__ uint32_t g_qkvhi[3*XN];         // tf32 hi: q | k | v (head-split layout)
__device__ uint32_t g_qkvlo[3*XN];         // tf32 lo
__device__ float    g_att [XN];
__device__ float    g_y   [XN];
__device__ float    g_o1  [XN];
__device__ float    g_hbuf[BB*SS*DFFN];
__device__ float    g_e   [AWN];           // logits (exp fused downstream)
__device__ int      g_maxbits[BB*HH];
__device__ float    g_sum    [BB*HH];
__device__ float    g_rowcount;
// tf32-packed weights (prepared once per launch)
__device__ uint32_t g_wqkv[512*1536];
__device__ uint32_t g_wo_t[512*512];
__device__ uint32_t g_w1t [512*2048];
__device__ uint32_t g_w2t [2048*512];
__device__ float    g_bqkv[1536];

// ---------------- helpers ----------------
__device__ __forceinline__ int f2o(float f) {
    int i = __float_as_int(f);
    return (i >= 0) ? i : (i ^ 0x7FFFFFFF);
}
__device__ __forceinline__ float o2f(int i) {
    return __int_as_float((i >= 0) ? i : (i ^ 0x7FFFFFFF));
}
__device__ __forceinline__ uint32_t f2tf(float f) {
    uint32_t u;
    asm("cvt.rna.tf32.f32 %0, %1;" : "=r"(u) : "f"(f));
    return u;
}
__device__ __forceinline__ void mma_tf32(float* c, const uint32_t* a, const uint32_t* b) {
    asm volatile(
        "mma.sync.aligned.m16n8k8.row.col.f32.tf32.tf32.f32 "
        "{%0,%1,%2,%3}, {%4,%5,%6,%7}, {%8,%9}, {%0,%1,%2,%3};\n"
        : "+f"(c[0]), "+f"(c[1]), "+f"(c[2]), "+f"(c[3])
        : "r"(a[0]), "r"(a[1]), "r"(a[2]), "r"(a[3]), "r"(b[0]), "r"(b[1]));
}

// ---------------- row_count = count_nonzero(protok[0, :]) ----------------
__global__ void rowcount_kernel(const int* __restrict__ protok) {
    __shared__ int red[32];
    int t = threadIdx.x;
    int c = (protok[t] != 0) ? 1 : 0;
    #pragma unroll
    for (int o = 16; o; o >>= 1) c += __shfl_xor_sync(0xffffffffu, c, o);
    if ((t & 31) == 0) red[t >> 5] = c;
    __syncthreads();
    if (t < 32) {
        int v = red[t];
        #pragma unroll
        for (int o = 16; o; o >>= 1) v += __shfl_xor_sync(0xffffffffu, v, o);
        if (t == 0) g_rowcount = (float)v;
    }
}

__global__ void init_reduce_kernel() {
    int t = threadIdx.x;
    if (t < BB * HH) { g_maxbits[t] = (int)0x80000000; g_sum[t] = 0.0f; }
}

__global__ void copy4_kernel(float4* __restrict__ dst, const float4* __restrict__ src, int n4) {
    int i = blockIdx.x * blockDim.x + threadIdx.x;
    if (i < n4) dst[i] = src[i];
}

// out[i] = R[i] + bias (broadcast over rows); element space = float4, N = 512
__global__ void initout_kernel(float4* __restrict__ dst, const float4* __restrict__ R,
                               const float* __restrict__ bias) {
    int i = blockIdx.x * 256 + threadIdx.x;
    float4 r = R[i];
    int col = (i & 127) << 2;     // N/4 - 1 = 127
    r.x += bias[col]; r.y += bias[col + 1]; r.z += bias[col + 2]; r.w += bias[col + 3];
    dst[i] = r;
}

// ---------------- weight preparation (once per launch) ----------------
__global__ void pack_qkv_kernel(const float* __restrict__ wq, const float* __restrict__ wk,
                                const float* __restrict__ wv, const float* __restrict__ bq,
                                const float* __restrict__ bk, const float* __restrict__ bv) {
    int i = blockIdx.x * 256 + threadIdx.x;
    if (i < 512 * 1536) {
        int k = i / 1536, n = i % 1536;
        const float* w = (n < 512) ? wq : (n < 1024) ? wk : wv;
        g_wqkv[i] = f2tf(w[k * 512 + (n & 511)]);
    }
    if (i < 1536) {
        g_bqkv[i] = (i < 512) ? bq[i] : (i < 1024) ? bk[i - 512] : bv[i - 1024];
    }
}
__global__ void cvtw_kernel(const float* __restrict__ w, uint32_t* __restrict__ dst, int n) {
    int i = blockIdx.x * 256 + threadIdx.x;
    if (i < n) dst[i] = f2tf(w[i]);
}

// ================= tf32 GEMM with register-prefetch double buffering =================
// mode: 0 = plain; 2 = QKV head-split, writes tf32 hi/lo pairs.
#define KC 32
#define APITCH 36    /* (4g+tg)%32 conflict-free */
#define BPITCH 72    /* (8tg+g)%32 conflict-free */

__global__ __launch_bounds__(256) void gemm_pf(
    const float* __restrict__ A, const uint32_t* __restrict__ W,
    const float* __restrict__ bias, const float* __restrict__ R,
    float* __restrict__ C, int M, int N, int K, int relu, int mode)
{
    __shared__ uint32_t As[128 * APITCH];
    __shared__ uint32_t Bs[KC * BPITCH];

    int tid  = threadIdx.x;
    int warp = tid >> 5, lane = tid & 31;
    int wm = (warp & 3) << 5;
    int wn = (warp >> 2) << 5;
    int g  = lane >> 2, tg = lane & 3;

    int m0 = blockIdx.y << 7, n0 = blockIdx.x << 6;

    int arow = tid >> 3, acol = (tid & 7) << 2;    // A: 128 x 32
    int brow = tid >> 4, bcol = (tid & 15) << 2;   // B: 32 x 64

    const float* Aptr = &A[(size_t)(m0 + arow) * K + acol];
    const uint32_t* Wptr = &W[(size_t)brow * N + n0 + bcol];

    float4 ra[4];
    uint4  rb[2];

    #pragma unroll
    for (int i = 0; i < 4; i++) ra[i] = *(const float4*)(Aptr + (size_t)(i << 5) * K);
    #pragma unroll
    for (int i = 0; i < 2; i++) rb[i] = *(const uint4*)(Wptr + (size_t)(i << 4) * N);

    float acc[2][4][4];
    #pragma unroll
    for (int i = 0; i < 2; i++)
        #pragma unroll
        for (int j = 0; j < 4; j++)
            #pragma unroll
            for (int r = 0; r < 4; r++) acc[i][j][r] = 0.0f;

    int nch = K / KC;
    for (int ch = 0; ch < nch; ch++) {
        #pragma unroll
        for (int i = 0; i < 4; i++) {
            uint32_t* p = &As[(arow + (i << 5)) * APITCH + acol];
            p[0] = f2tf(ra[i].x); p[1] = f2tf(ra[i].y);
            p[2] = f2tf(ra[i].z); p[3] = f2tf(ra[i].w);
        }
        #pragma unroll
        for (int i = 0; i < 2; i++)
            *(uint4*)&Bs[(brow + (i << 4)) * BPITCH + bcol] = rb[i];
        __syncthreads();

        if (ch + 1 < nch) {
            int k0 = (ch + 1) * KC;
            #pragma unroll
            for (int i = 0; i < 4; i++) ra[i] = *(const float4*)(Aptr + (size_t)(i << 5) * K + k0);
            #pragma unroll
            for (int i = 0; i < 2; i++) rb[i] = *(const uint4*)(Wptr + (size_t)((i << 4) + k0) * N);
        }

        #pragma unroll
        for (int kk = 0; kk < KC; kk += 8) {
            uint32_t af[2][4];
            #pragma unroll
            for (int mt = 0; mt < 2; mt++) {
                int r = wm + (mt << 4) + g;
                af[mt][0] = As[r * APITCH + kk + tg];
                af[mt][1] = As[(r + 8) * APITCH + kk + tg];
                af[mt][2] = As[r * APITCH + kk + tg + 4];
                af[mt][3] = As[(r + 8) * APITCH + kk + tg + 4];
            }
            uint32_t bf[4][2];
            #pragma unroll
            for (int nt = 0; nt < 4; nt++) {
                int cc = wn + (nt << 3) + g;
                bf[nt][0] = Bs[(kk + tg) * BPITCH + cc];
                bf[nt][1] = Bs[(kk + tg + 4) * BPITCH + cc];
            }
            #pragma unroll
            for (int mt = 0; mt < 2; mt++)
                #pragma unroll
                for (int nt = 0; nt < 4; nt++)
                    mma_tf32(acc[mt][nt], af[mt], bf[nt]);
        }
        __syncthreads();
    }

    #pragma unroll
    for (int mt = 0; mt < 2; mt++) {
        #pragma unroll
        for (int nt = 0; nt < 4; nt++) {
            int n = n0 + wn + (nt << 3) + (tg << 1);
            #pragma unroll
            for (int half = 0; half < 2; half++) {
                int mm = m0 + wm + (mt << 4) + g + half * 8;
                float2 v;
                v.x = acc[mt][nt][half * 2 + 0] + bias[n];
                v.y = acc[mt][nt][half * 2 + 1] + bias[n + 1];
                if (R) {
                    const float2 rr = *(const float2*)&R[(size_t)mm * N + n];
                    v.x += rr.x; v.y += rr.y;
                }
                if (relu) { v.x = fmaxf(v.x, 0.0f); v.y = fmaxf(v.y, 0.0f); }
                if (mode == 2) {
                    int which = n >> 9, nl = n & 511;
                    int bb = mm >> 10, s = mm & 1023, hh = nl >> 6, dd = nl & 63;
                    size_t off = (size_t)which * XN +
                                 (((size_t)(bb * HH + hh) << 10) | (size_t)s) * DEP + dd;
                    uint2 hi, lo;
                    hi.x = f2tf(v.x); lo.x = f2tf(v.x - __uint_as_float(hi.x));
                    hi.y = f2tf(v.y); lo.y = f2tf(v.y - __uint_as_float(hi.y));
                    *(uint2*)&g_qkvhi[off] = hi;
                    *(uint2*)&g_qkvlo[off] = lo;
                } else {
                    *(float2*)&C[(size_t)mm * N + n] = v;
                }
            }
        }
    }
}

// ================= split-K tf32 GEMM: partials atomically added into pre-initialized C ====
// scaled=1: A[m,k] *= rc/g_sum[(m>>10)*8 + (kglobal>>6)] (O-projection).
__global__ __launch_bounds__(256) void gemm_sk(
    const float* __restrict__ A, const uint32_t* __restrict__ W,
    float* __restrict__ C, int M, int N, int K, int Ksp, int scaled)
{
    __shared__ uint32_t As[128 * APITCH];
    __shared__ uint32_t Bs[KC * BPITCH];

    int tid  = threadIdx.x;
    int warp = tid >> 5, lane = tid & 31;
    int wm = (warp & 3) << 5;
    int wn = (warp >> 2) << 5;
    int g  = lane >> 2, tg = lane & 3;

    int m0 = blockIdx.y << 7, n0 = blockIdx.x << 6;
    int kbase = blockIdx.z * Ksp;

    int arow = tid >> 3, acol = (tid & 7) << 2;
    int brow = tid >> 4, bcol = (tid & 15) << 2;

    const float* Aptr = &A[(size_t)(m0 + arow) * K + kbase + acol];
    const uint32_t* Wptr = &W[(size_t)(kbase + brow) * N + n0 + bcol];

    float sc[8];
    if (scaled) {
        float rc = g_rowcount;
        int b = (m0 + arow) >> 10;
        #pragma unroll
        for (int h = 0; h < 8; h++) sc[h] = rc / g_sum[b * 8 + h];
    }

    float4 ra[4];
    uint4  rb[2];
    #pragma unroll
    for (int i = 0; i < 4; i++) ra[i] = *(const float4*)(Aptr + (size_t)(i << 5) * K);
    #pragma unroll
    for (int i = 0; i < 2; i++) rb[i] = *(const uint4*)(Wptr + (size_t)(i << 4) * N);

    float acc[2][4][4];
    #pragma unroll
    for (int i = 0; i < 2; i++)
        #pragma unroll
        for (int j = 0; j < 4; j++)
            #pragma unroll
            for (int r = 0; r < 4; r++) acc[i][j][r] = 0.0f;

    int nch = Ksp / KC;
    for (int ch = 0; ch < nch; ch++) {
        float s = 1.0f;
        if (scaled) s = sc[((kbase + ch * KC + acol) >> 6) & 7];
        #pragma unroll
        for (int i = 0; i < 4; i++) {
            uint32_t* p = &As[(arow + (i << 5)) * APITCH + acol];
            p[0] = f2tf(ra[i].x * s); p[1] = f2tf(ra[i].y * s);
            p[2] = f2tf(ra[i].z * s); p[3] = f2tf(ra[i].w * s);
        }
        #pragma unroll
        for (int i = 0; i < 2; i++)
            *(uint4*)&Bs[(brow + (i << 4)) * BPITCH + bcol] = rb[i];
        __syncthreads();

        if (ch + 1 < nch) {
            int k0 = (ch + 1) * KC;
            #pragma unroll
            for (int i = 0; i < 4; i++) ra[i] = *(const float4*)(Aptr + (size_t)(i << 5) * K + k0);
            #pragma unroll
            for (int i = 0; i < 2; i++) rb[i] = *(const uint4*)(Wptr + (size_t)((i << 4) + k0) * N);
        }

        #pragma unroll
        for (int kk = 0; kk < KC; kk += 8) {
            uint32_t af[2][4];
            #pragma unroll
            for (int mt = 0; mt < 2; mt++) {
                int r = wm + (mt << 4) + g;
                af[mt][0] = As[r * APITCH + kk + tg];
                af[mt][1] = As[(r + 8) * APITCH + kk + tg];
                af[mt][2] = As[r * APITCH + kk + tg + 4];
                af[mt][3] = As[(r + 8) * APITCH + kk + tg + 4];
            }
            uint32_t bf[4][2];
            #pragma unroll
            for (int nt = 0; nt < 4; nt++) {
                int cc = wn + (nt << 3) + g;
                bf[nt][0] = Bs[(kk + tg) * BPITCH + cc];
                bf[nt][1] = Bs[(kk + tg + 4) * BPITCH + cc];
            }
            #pragma unroll
            for (int mt = 0; mt < 2; mt++)
                #pragma unroll
                for (int nt = 0; nt < 4; nt++)
                    mma_tf32(acc[mt][nt], af[mt], bf[nt]);
        }
        __syncthreads();
    }

    #pragma unroll
    for (int mt = 0; mt < 2; mt++) {
        #pragma unroll
        for (int nt = 0; nt < 4; nt++) {
            int n = n0 + wn + (nt << 3) + (tg << 1);
            #pragma unroll
            for (int half = 0; half < 2; half++) {
                int mm = m0 + wm + (mt << 4) + g + half * 8;
                float* p = &C[(size_t)mm * N + n];
                atomicAdd(p,     acc[mt][nt][half * 2 + 0]);
                atomicAdd(p + 1, acc[mt][nt][half * 2 + 1]);
            }
        }
    }
}

// ========== logits (tf32x3, pre-split operands, reg-prefetch): (Q K^T + mask*-1e9)/8 ==========
#define LOGITS_SMEM ((128*APITCH*2 + 64*APITCH*2) * 4)
__global__ __launch_bounds__(256) void logits_mma(const float* __restrict__ mask) {
    extern __shared__ uint32_t dsm[];
    uint32_t* Qh = dsm;
    uint32_t* Ql = Qh + 128 * APITCH;
    uint32_t* Kh = Ql + 128 * APITCH;
    uint32_t* Kl = Kh + 64 * APITCH;
    __shared__ float red[8];

    int tid  = threadIdx.x;
    int warp = tid >> 5, lane = tid & 31;
    int wm = (warp & 3) << 5;
    int wn = (warp >> 2) << 5;
    int g  = lane >> 2, tg = lane & 3;

    int bh = blockIdx.z; int bi = bh >> 3;
    int i0 = blockIdx.y << 7, j0 = blockIdx.x << 6;
    const uint32_t* qh = g_qkvhi + (size_t)bh * SS * DEP;
    const uint32_t* ql = g_qkvlo + (size_t)bh * SS * DEP;
    const uint32_t* kh = g_qkvhi + XN + (size_t)bh * SS * DEP;
    const uint32_t* kl = g_qkvlo + XN + (size_t)bh * SS * DEP;

    int arow = tid >> 3, acol = (tid & 7) << 2;

    // prefetch chunk 0
    uint4 rqh[4], rql[4], rkh[2], rkl[2];
    #pragma unroll
    for (int i = 0; i < 4; i++) {
        size_t src = (size_t)(i0 + arow + (i << 5)) * DEP + acol;
        rqh[i] = *(const uint4*)&qh[src];
        rql[i] = *(const uint4*)&ql[src];
    }
    #pragma unroll
    for (int i = 0; i < 2; i++) {
        size_t src = (size_t)(j0 + arow + (i << 5)) * DEP + acol;
        rkh[i] = *(const uint4*)&kh[src];
        rkl[i] = *(const uint4*)&kl[src];
    }

    float acc[2][4][4];
    #pragma unroll
    for (int i = 0; i < 2; i++)
        #pragma unroll
        for (int j = 0; j < 4; j++)
            #pragma unroll
            for (int r = 0; r < 4; r++) acc[i][j][r] = 0.0f;

    #pragma unroll
    for (int c = 0; c < 2; c++) {
        #pragma unroll
        for (int i = 0; i < 4; i++) {
            int r = arow + (i << 5);
            *(uint4*)&Qh[r * APITCH + acol] = rqh[i];
            *(uint4*)&Ql[r * APITCH + acol] = rql[i];
        }
        #pragma unroll
        for (int i = 0; i < 2; i++) {
            int r = arow + (i << 5);
            *(uint4*)&Kh[r * APITCH + acol] = rkh[i];
            *(uint4*)&Kl[r * APITCH + acol] = rkl[i];
        }
        __syncthreads();

        if (c == 0) {
            #pragma unroll
            for (int i = 0; i < 4; i++) {
                size_t src = (size_t)(i0 + arow + (i << 5)) * DEP + KC + acol;
                rqh[i] = *(const uint4*)&qh[src];
                rql[i] = *(const uint4*)&ql[src];
            }
            #pragma unroll
            for (int i = 0; i < 2; i++) {
                size_t src = (size_t)(j0 + arow + (i << 5)) * DEP + KC + acol;
                rkh[i] = *(const uint4*)&kh[src];
                rkl[i] = *(const uint4*)&kl[src];
            }
        }

        #pragma unroll
        for (int kk = 0; kk < KC; kk += 8) {
            uint32_t ahi[2][4], alo[2][4], bhi[4][2], blo[4][2];
            #pragma unroll
            for (int mt = 0; mt < 2; mt++) {
                int r = wm + (mt << 4) + g;
                int o0 = r * APITCH + kk + tg, o1 = (r + 8) * APITCH + kk + tg;
                ahi[mt][0] = Qh[o0];     ahi[mt][1] = Qh[o1];
                ahi[mt][2] = Qh[o0 + 4]; ahi[mt][3] = Qh[o1 + 4];
                alo[mt][0] = Ql[o0];     alo[mt][1] = Ql[o1];
                alo[mt][2] = Ql[o0 + 4]; alo[mt][3] = Ql[o1 + 4];
            }
            #pragma unroll
            for (int nt = 0; nt < 4; nt++) {
                int cc = wn + (nt << 3) + g;
                int o0 = cc * APITCH + kk + tg;
                bhi[nt][0] = Kh[o0]; bhi[nt][1] = Kh[o0 + 4];
                blo[nt][0] = Kl[o0]; blo[nt][1] = Kl[o0 + 4];
            }
            #pragma unroll
            for (int mt = 0; mt < 2; mt++)
                #pragma unroll
                for (int nt = 0; nt < 4; nt++) {
                    mma_tf32(acc[mt][nt], alo[mt], bhi[nt]);
                    mma_tf32(acc[mt][nt], ahi[mt], blo[nt]);
                    mma_tf32(acc[mt][nt], ahi[mt], bhi[nt]);
                }
        }
        __syncthreads();
    }

    float* out = g_e + (size_t)bh * SS * SS;
    float lmax = -INFINITY;
    #pragma unroll
    for (int mt = 0; mt < 2; mt++) {
        #pragma unroll
        for (int nt = 0; nt < 4; nt++) {
            int j = j0 + wn + (nt << 3) + (tg << 1);
            #pragma unroll
            for (int half = 0; half < 2; half++) {
                int i = i0 + wm + (mt << 4) + g + half * 8;
                const float2 mk = *(const float2*)&mask[((size_t)bi * SS + i) * SS + j];
                float2 v;
                v.x = (acc[mt][nt][half * 2 + 0] + mk.x * (-1e9f)) * 0.125f;
                v.y = (acc[mt][nt][half * 2 + 1] + mk.y * (-1e9f)) * 0.125f;
                *(float2*)&out[(size_t)i * SS + j] = v;
                lmax = fmaxf(lmax, fmaxf(v.x, v.y));
            }
        }
    }
    #pragma unroll
    for (int o = 16; o; o >>= 1) lmax = fmaxf(lmax, __shfl_xor_sync(0xffffffffu, lmax, o));
    if (lane == 0) red[warp] = lmax;
    __syncthreads();
    if (tid == 0) {
        float m = red[0];
        #pragma unroll
        for (int w = 1; w < 8; w++) m = fmaxf(m, red[w]);
        atomicMax(&g_maxbits[bh], f2o(m));
    }
}

// ========== attv (tf32x3): exp fused + split at fill; V pre-split; reg-prefetch ==========
#define EPITCH 136
#define ATTV_SMEM ((KC*EPITCH*2 + KC*BPITCH*2) * 4)
__global__ __launch_bounds__(256) void attv_mma() {
    extern __shared__ uint32_t dsm[];
    uint32_t* Eh = dsm;
    uint32_t* El = Eh + KC * EPITCH;
    uint32_t* Vh = El + KC * EPITCH;
    uint32_t* Vl = Vh + KC * BPITCH;
    __shared__ float red[8];

    int tid  = threadIdx.x;
    int warp = tid >> 5, lane = tid & 31;
    int wm = (warp & 3) << 5;
    int wn = (warp >> 2) << 5;
    int g  = lane >> 2, tg = lane & 3;

    int bh = blockIdx.y; int bat = bh >> 3, hh = bh & 7;
    int j0 = blockIdx.x << 7;
    const float* e = g_e + (size_t)bh * SS * SS;
    const uint32_t* vh = g_qkvhi + 2 * (size_t)XN + (size_t)bh * SS * DEP;
    const uint32_t* vl = g_qkvlo + 2 * (size_t)XN + (size_t)bh * SS * DEP;
    float mx = o2f(g_maxbits[bh]);

    int erow = tid >> 5, ecol = (tid & 31) << 2;
    int vrow = tid >> 4, vcol = (tid & 15) << 2;

    // prefetch chunk 0
    float4 re[4];
    uint4 rvh[2], rvl[2];
    #pragma unroll
    for (int i = 0; i < 4; i++)
        re[i] = *(const float4*)&e[(size_t)(erow + (i << 3)) * SS + j0 + ecol];
    #pragma unroll
    for (int i = 0; i < 2; i++) {
        size_t src = (size_t)(vrow + (i << 4)) * DEP + vcol;
        rvh[i] = *(const uint4*)&vh[src];
        rvl[i] = *(const uint4*)&vl[src];
    }

    float acc[2][4][4];
    #pragma unroll
    for (int i = 0; i < 2; i++)
        #pragma unroll
        for (int j = 0; j < 4; j++)
            #pragma unroll
            for (int r = 0; r < 4; r++) acc[i][j][r] = 0.0f;

    float lsum = 0.0f;

    for (int i0 = 0; i0 < SS; i0 += KC) {
        #pragma unroll
        for (int i = 0; i < 4; i++) {
            int r = erow + (i << 3);
            float4 le = re[i];
            le.x = __expf(le.x - mx); le.y = __expf(le.y - mx);
            le.z = __expf(le.z - mx); le.w = __expf(le.w - mx);
            lsum += (le.x + le.y) + (le.z + le.w);
            uint4 hi, lo;
            hi.x = f2tf(le.x); lo.x = f2tf(le.x - __uint_as_float(hi.x));
            hi.y = f2tf(le.y); lo.y = f2tf(le.y - __uint_as_float(hi.y));
            hi.z = f2tf(le.z); lo.z = f2tf(le.z - __uint_as_float(hi.z));
            hi.w = f2tf(le.w); lo.w = f2tf(le.w - __uint_as_float(hi.w));
            *(uint4*)&Eh[r * EPITCH + ecol] = hi;
            *(uint4*)&El[r * EPITCH + ecol] = lo;
        }
        #pragma unroll
        for (int i = 0; i < 2; i++) {
            int r = vrow + (i << 4);
            *(uint4*)&Vh[r * BPITCH + vcol] = rvh[i];
            *(uint4*)&Vl[r * BPITCH + vcol] = rvl[i];
        }
        __syncthreads();

        if (i0 + KC < SS) {
            int ib = i0 + KC;
            #pragma unroll
            for (int i = 0; i < 4; i++)
                re[i] = *(const float4*)&e[(size_t)(ib + erow + (i << 3)) * SS + j0 + ecol];
            #pragma unroll
            for (int i = 0; i < 2; i++) {
                size_t src = (size_t)(ib + vrow + (i << 4)) * DEP + vcol;
                rvh[i] = *(const uint4*)&vh[src];
                rvl[i] = *(const uint4*)&vl[src];
            }
        }

        #pragma unroll
        for (int kk = 0; kk < KC; kk += 8) {
            uint32_t ahi[2][4], alo[2][4], bhi[4][2], blo[4][2];
            #pragma unroll
            for (int mt = 0; mt < 2; mt++) {
                int r = wm + (mt << 4) + g;
                int o0 = (kk + tg) * EPITCH + r, o1 = (kk + tg + 4) * EPITCH + r;
                ahi[mt][0] = Eh[o0];     ahi[mt][1] = Eh[o0 + 8];
                ahi[mt][2] = Eh[o1];     ahi[mt][3] = Eh[o1 + 8];
                alo[mt][0] = El[o0];     alo[mt][1] = El[o0 + 8];
                alo[mt][2] = El[o1];     alo[mt][3] = El[o1 + 8];
            }
            #pragma unroll
            for (int nt = 0; nt < 4; nt++) {
                int cc = wn + (nt << 3) + g;
                int o0 = (kk + tg) * BPITCH + cc, o1 = (kk + tg + 4) * BPITCH + cc;
                bhi[nt][0] = Vh[o0]; bhi[nt][1] = Vh[o1];
                blo[nt][0] = Vl[o0]; blo[nt][1] = Vl[o1];
            }
            #pragma unroll
            for (int mt = 0; mt < 2; mt++)
                #pragma unroll
                for (int nt = 0; nt < 4; nt++) {
                    mma_tf32(acc[mt][nt], alo[mt], bhi[nt]);
                    mma_tf32(acc[mt][nt], ahi[mt], blo[nt]);
                    mma_tf32(acc[mt][nt], ahi[mt], bhi[nt]);
                }
        }
        __syncthreads();
    }

    #pragma unroll
    for (int o = 16; o; o >>= 1) lsum += __shfl_xor_sync(0xffffffffu, lsum, o);
    if (lane == 0) red[warp] = lsum;
    __syncthreads();
    if (tid == 0) {
        float s = 0.0f;
        #pragma unroll
        for (int w = 0; w < 8; w++) s += red[w];
        atomicAdd(&g_sum[bh], s);
    }

    #pragma unroll
    for (int mt = 0; mt < 2; mt++) {
        #pragma unroll
        for (int nt = 0; nt < 4; nt++) {
            int d = wn + (nt << 3) + (tg << 1);
            #pragma unroll
            for (int half = 0; half < 2; half++) {
                int j = j0 + wm + (mt << 4) + g + half * 8;
                float2 o;
                o.x = acc[mt][nt][half * 2 + 0];
                o.y = acc[mt][nt][half * 2 + 1];
                *(float2*)&g_att[((size_t)bat * SS + j) * DD + hh * DEP + d] = o;
            }
        }
    }
}

// ---------------- LayerNorm over last dim (512) ----------------
__global__ __launch_bounds__(128) void ln_kernel(
    const float* __restrict__ in, const float* __restrict__ gam,
    const float* __restrict__ bet, float* __restrict__ out)
{
    __shared__ float red[4];
    __shared__ float bc;
    int row = blockIdx.x, t = threadIdx.x;
    const float* rp = in + (size_t)row * DD;
    float v0 = rp[t], v1 = rp[t + 128], v2 = rp[t + 256], v3 = rp[t + 384];
    float s = v0 + v1 + v2 + v3;
    #pragma unroll
    for (int o = 16; o; o >>= 1) s += __shfl_xor_sync(0xffffffffu, s, o);
    if ((t & 31) == 0) red[t >> 5] = s;
    __syncthreads();
    if (t == 0) bc = (red[0] + red[1] + red[2] + red[3]) * (1.0f / 512.0f);
    __syncthreads();
    float mean = bc;
    float d0 = v0 - mean, d1 = v1 - mean, d2 = v2 - mean, d3 = v3 - mean;
    float ss = d0 * d0 + d1 * d1 + d2 * d2 + d3 * d3;
    #pragma unroll
    for (int o = 16; o; o >>= 1) ss += __shfl_xor_sync(0xffffffffu, ss, o);
    __syncthreads();
    if ((t & 31) == 0) red[t >> 5] = ss;
    __syncthreads();
    if (t == 0) bc = (red[0] + red[1] + red[2] + red[3]) * (1.0f / 512.0f);
    __syncthreads();
    float inv = rsqrtf(bc + 1e-9f);
    float* op = out + (size_t)row * DD;
    op[t]       = gam[t]       * d0 * inv + bet[t];
    op[t + 128] = gam[t + 128] * d1 * inv + bet[t + 128];
    op[t + 256] = gam[t + 256] * d2 * inv + bet[t + 256];
    op[t + 384] = gam[t + 384] * d3 * inv + bet[t + 384];
}

// ---------------- final aw write: exp(logit - mx) * rc/Z (float4) ----------------
__global__ __launch_bounds__(256) void awout_kernel(float4* __restrict__ out) {
    size_t i = (size_t)blockIdx.x * 256 + threadIdx.x;   // float4 units
    int bh = (int)(i >> 18);                              // 2^18 float4 per (b,h)
    float s = g_rowcount / g_sum[bh];
    float mx = o2f(g_maxbits[bh]);
    float4 v = ((const float4*)g_e)[i];
    v.x = __expf(v.x - mx) * s; v.y = __expf(v.y - mx) * s;
    v.z = __expf(v.z - mx) * s; v.w = __expf(v.w - mx) * s;
    out[i] = v;
}

// ---------------- launch ----------------
extern "C" void kernel_launch(void* const* d_in, const int* in_sizes, int n_in,
                              void* d_out, int out_size)
{
    const float* x_in  = (const float*)d_in[0];
    const float* mask  = (const float*)d_in[1];
    const int*   protok= (const int*)  d_in[2];
    const float* wq_w  = (const float*)d_in[3];
    const float* wq_b  = (const float*)d_in[4];
    const float* wk_w  = (const float*)d_in[5];
    const float* wk_b  = (const float*)d_in[6];
    const float* wv_w  = (const float*)d_in[7];
    const float* wv_b  = (const float*)d_in[8];
    const float* wo_w  = (const float*)d_in[9];
    const float* wo_b  = (const float*)d_in[10];
    const float* w1    = (const float*)d_in[11];
    const float* b1    = (const float*)d_in[12];
    const float* w2    = (const float*)d_in[13];
    const float* b2    = (const float*)d_in[14];
    const float* ln1g  = (const float*)d_in[15];
    const float* ln1b  = (const float*)d_in[16];
    const float* ln2g  = (const float*)d_in[17];
    const float* ln2b  = (const float*)d_in[18];

    float *px, *patt, *py, *po1, *ph, *pbqkv;
    uint32_t *pwqkv, *pwo, *pw1, *pw2;
    cudaGetSymbolAddress((void**)&px,    g_x);
    cudaGetSymbolAddress((void**)&patt,  g_att);
    cudaGetSymbolAddress((void**)&py,    g_y);
    cudaGetSymbolAddress((void**)&po1,   g_o1);
    cudaGetSymbolAddress((void**)&ph,    g_hbuf);
    cudaGetSymbolAddress((void**)&pwqkv, g_wqkv);
    cudaGetSymbolAddress((void**)&pwo,   g_wo_t);
    cudaGetSymbolAddress((void**)&pw1,   g_w1t);
    cudaGetSymbolAddress((void**)&pw2,   g_w2t);
    cudaGetSymbolAddress((void**)&pbqkv, g_bqkv);

    cudaFuncSetAttribute(logits_mma, cudaFuncAttributeMaxDynamicSharedMemorySize, LOGITS_SMEM);
    cudaFuncSetAttribute(attv_mma,   cudaFuncAttributeMaxDynamicSharedMemorySize, ATTV_SMEM);

    // one-time prep
    rowcount_kernel<<<1, 1024>>>(protok);
    pack_qkv_kernel<<<3072, 256>>>(wq_w, wk_w, wv_w, wq_b, wk_b, wv_b);
    cvtw_kernel<<<1024, 256>>>(wo_w, pwo, 512 * 512);
    cvtw_kernel<<<4096, 256>>>(w1,   pw1, 512 * 2048);
    cvtw_kernel<<<4096, 256>>>(w2,   pw2, 2048 * 512);
    copy4_kernel<<<XN / 4 / 256, 256>>>((float4*)px, (const float4*)x_in, XN / 4);

    for (int l = 0; l < NLAYERS; l++) {
        gemm_pf<<<dim3(24, 32), 256>>>(px, pwqkv, pbqkv, nullptr, nullptr, BB*SS, 1536, DD, 0, 2);
        init_reduce_kernel<<<1, 64>>>();
        logits_mma<<<dim3(16, 8, 32), 256, LOGITS_SMEM>>>(mask);
        attv_mma<<<dim3(8, 32), 256, ATTV_SMEM>>>();
        // O-projection: py = px + wo_b + (att*scale) @ wo  (split-K x2)
        initout_kernel<<<XN / 4 / 256, 256>>>((float4*)py, (const float4*)px, wo_b);
        gemm_sk<<<dim3(8, 32, 2), 256>>>(patt, pwo, py, BB*SS, DD, DD, 256, 1);
        ln_kernel<<<BB*SS, 128>>>(py, ln1g, ln1b, po1);
        gemm_pf<<<dim3(32, 32), 256>>>(po1, pw1, b1, nullptr, ph, BB*SS, DFFN, DD, 1, 0);
        // FFN2: py = po1 + b2 + h @ w2  (split-K x4)
        initout_kernel<<<XN / 4 / 256, 256>>>((float4*)py, (const float4*)po1, b2);
        gemm_sk<<<dim3(8, 32, 4), 256>>>(ph, pw2, py, BB*SS, DD, DFFN, 512, 0);
        ln_kernel<<<BB*SS, 128>>>(py, ln2g, ln2b, px);
    }

    if (out_size >= XN) {
        copy4_kernel<<<XN / 4 / 256, 256>>>((float4*)d_out, (const float4*)px, XN / 4);
    }
    if (out_size >= XN + AWN) {
        awout_kernel<<<AWN / 4 / 256, 256>>>((float4*)((float*)d_out + XN));
    }
}

// round 12
// speedup vs baseline: 1.0016x; 1.0016x over previous
#include <cuda_runtime.h>
#include <math.h>
#include <stdint.h>

#define BB      4
#define SS      1024
#define DD      512
#define HH      8
#define DEP     64
#define DFFN    2048
#define NLAYERS 4

#define XN  (BB*SS*DD)       /* 2097152  */
#define AWN (BB*HH*SS*SS)    /* 33554432 */

// ---------------- device scratch (no allocation allowed) ----------------
__device__ float    g_x   [XN];
__device__ uint32_t g_qkvhi[3*XN];         // tf32 hi: q | k | v (head-split layout)
__device__ uint32_t g_qkvlo[3*XN];         // tf32 lo
__device__ float    g_att [XN];
__device__ float    g_y   [XN];
__device__ float    g_o1  [XN];
__device__ float    g_hbuf[BB*SS*DFFN];
__device__ float    g_e   [AWN];           // logits (exp fused downstream)
__device__ int      g_maxbits[BB*HH];
__device__ float    g_sum    [BB*HH];
__device__ float    g_rowcount;
// tf32-packed weights (prepared once per launch)
__device__ uint32_t g_wqkv[512*1536];
__device__ uint32_t g_wo_t[512*512];
__device__ uint32_t g_w1t [512*2048];
__device__ uint32_t g_w2t [2048*512];
__device__ float    g_bqkv[1536];

// ---------------- helpers ----------------
__device__ __forceinline__ int f2o(float f) {
    int i = __float_as_int(f);
    return (i >= 0) ? i : (i ^ 0x7FFFFFFF);
}
__device__ __forceinline__ float o2f(int i) {
    return __int_as_float((i >= 0) ? i : (i ^ 0x7FFFFFFF));
}
__device__ __forceinline__ uint32_t f2tf(float f) {
    uint32_t u;
    asm("cvt.rna.tf32.f32 %0, %1;" : "=r"(u) : "f"(f));
    return u;
}
__device__ __forceinline__ void mma_tf32(float* c, const uint32_t* a, const uint32_t* b) {
    asm volatile(
        "mma.sync.aligned.m16n8k8.row.col.f32.tf32.tf32.f32 "
        "{%0,%1,%2,%3}, {%4,%5,%6,%7}, {%8,%9}, {%0,%1,%2,%3};\n"
        : "+f"(c[0]), "+f"(c[1]), "+f"(c[2]), "+f"(c[3])
        : "r"(a[0]), "r"(a[1]), "r"(a[2]), "r"(a[3]), "r"(b[0]), "r"(b[1]));
}

// ---------------- row_count = count_nonzero(protok[0, :]) ----------------
__global__ void rowcount_kernel(const int* __restrict__ protok) {
    __shared__ int red[32];
    int t = threadIdx.x;
    int c = (protok[t] != 0) ? 1 : 0;
    #pragma unroll
    for (int o = 16; o; o >>= 1) c += __shfl_xor_sync(0xffffffffu, c, o);
    if ((t & 31) == 0) red[t >> 5] = c;
    __syncthreads();
    if (t < 32) {
        int v = red[t];
        #pragma unroll
        for (int o = 16; o; o >>= 1) v += __shfl_xor_sync(0xffffffffu, v, o);
        if (t == 0) g_rowcount = (float)v;
    }
}

__global__ void init_reduce_kernel() {
    int t = threadIdx.x;
    if (t < BB * HH) { g_maxbits[t] = (int)0x80000000; g_sum[t] = 0.0f; }
}

__global__ void copy4_kernel(float4* __restrict__ dst, const float4* __restrict__ src, int n4) {
    int i = blockIdx.x * blockDim.x + threadIdx.x;
    if (i < n4) dst[i] = src[i];
}

// ---------------- weight preparation (once per launch) ----------------
__global__ void pack_qkv_kernel(const float* __restrict__ wq, const float* __restrict__ wk,
                                const float* __restrict__ wv, const float* __restrict__ bq,
                                const float* __restrict__ bk, const float* __restrict__ bv) {
    int i = blockIdx.x * 256 + threadIdx.x;
    if (i < 512 * 1536) {
        int k = i / 1536, n = i % 1536;
        const float* w = (n < 512) ? wq : (n < 1024) ? wk : wv;
        g_wqkv[i] = f2tf(w[k * 512 + (n & 511)]);
    }
    if (i < 1536) {
        g_bqkv[i] = (i < 512) ? bq[i] : (i < 1024) ? bk[i - 512] : bv[i - 1024];
    }
}
__global__ void cvtw_kernel(const float* __restrict__ w, uint32_t* __restrict__ dst, int n) {
    int i = blockIdx.x * 256 + threadIdx.x;
    if (i < n) dst[i] = f2tf(w[i]);
}

// ================= tf32 GEMM with register-prefetch double buffering =================
// mode: 0 = plain; 2 = QKV head-split, writes tf32 hi/lo pairs; 3 = A scaled rc/Z per (b,h).
#define KC 32
#define APITCH 36    /* (4g+tg)%32 conflict-free */
#define BPITCH 72    /* (8tg+g)%32 conflict-free */

__global__ __launch_bounds__(256) void gemm_pf(
    const float* __restrict__ A, const uint32_t* __restrict__ W,
    const float* __restrict__ bias, const float* __restrict__ R,
    float* __restrict__ C, int M, int N, int K, int relu, int mode)
{
    __shared__ uint32_t As[128 * APITCH];
    __shared__ uint32_t Bs[KC * BPITCH];

    int tid  = threadIdx.x;
    int warp = tid >> 5, lane = tid & 31;
    int wm = (warp & 3) << 5;
    int wn = (warp >> 2) << 5;
    int g  = lane >> 2, tg = lane & 3;

    int m0 = blockIdx.y << 7, n0 = blockIdx.x << 6;

    int arow = tid >> 3, acol = (tid & 7) << 2;    // A: 128 x 32
    int brow = tid >> 4, bcol = (tid & 15) << 2;   // B: 32 x 64

    const float* Aptr = &A[(size_t)(m0 + arow) * K + acol];
    const uint32_t* Wptr = &W[(size_t)brow * N + n0 + bcol];

    float sc[8];
    if (mode == 3) {
        float rc = g_rowcount;
        int b = (m0 + arow) >> 10;
        #pragma unroll
        for (int h = 0; h < 8; h++) sc[h] = rc / g_sum[b * 8 + h];
    }

    float4 ra[4];
    uint4  rb[2];

    #pragma unroll
    for (int i = 0; i < 4; i++) ra[i] = *(const float4*)(Aptr + (size_t)(i << 5) * K);
    #pragma unroll
    for (int i = 0; i < 2; i++) rb[i] = *(const uint4*)(Wptr + (size_t)(i << 4) * N);

    float acc[2][4][4];
    #pragma unroll
    for (int i = 0; i < 2; i++)
        #pragma unroll
        for (int j = 0; j < 4; j++)
            #pragma unroll
            for (int r = 0; r < 4; r++) acc[i][j][r] = 0.0f;

    int nch = K / KC;
    for (int ch = 0; ch < nch; ch++) {
        float s = 1.0f;
        if (mode == 3) s = sc[(ch * KC + acol) >> 6];
        #pragma unroll
        for (int i = 0; i < 4; i++) {
            uint32_t* p = &As[(arow + (i << 5)) * APITCH + acol];
            p[0] = f2tf(ra[i].x * s); p[1] = f2tf(ra[i].y * s);
            p[2] = f2tf(ra[i].z * s); p[3] = f2tf(ra[i].w * s);
        }
        #pragma unroll
        for (int i = 0; i < 2; i++)
            *(uint4*)&Bs[(brow + (i << 4)) * BPITCH + bcol] = rb[i];
        __syncthreads();

        if (ch + 1 < nch) {
            int k0 = (ch + 1) * KC;
            #pragma unroll
            for (int i = 0; i < 4; i++) ra[i] = *(const float4*)(Aptr + (size_t)(i << 5) * K + k0);
            #pragma unroll
            for (int i = 0; i < 2; i++) rb[i] = *(const uint4*)(Wptr + (size_t)((i << 4) + k0) * N);
        }

        #pragma unroll
        for (int kk = 0; kk < KC; kk += 8) {
            uint32_t af[2][4];
            #pragma unroll
            for (int mt = 0; mt < 2; mt++) {
                int r = wm + (mt << 4) + g;
                af[mt][0] = As[r * APITCH + kk + tg];
                af[mt][1] = As[(r + 8) * APITCH + kk + tg];
                af[mt][2] = As[r * APITCH + kk + tg + 4];
                af[mt][3] = As[(r + 8) * APITCH + kk + tg + 4];
            }
            uint32_t bf[4][2];
            #pragma unroll
            for (int nt = 0; nt < 4; nt++) {
                int cc = wn + (nt << 3) + g;
                bf[nt][0] = Bs[(kk + tg) * BPITCH + cc];
                bf[nt][1] = Bs[(kk + tg + 4) * BPITCH + cc];
            }
            #pragma unroll
            for (int mt = 0; mt < 2; mt++)
                #pragma unroll
                for (int nt = 0; nt < 4; nt++)
                    mma_tf32(acc[mt][nt], af[mt], bf[nt]);
        }
        __syncthreads();
    }

    #pragma unroll
    for (int mt = 0; mt < 2; mt++) {
        #pragma unroll
        for (int nt = 0; nt < 4; nt++) {
            int n = n0 + wn + (nt << 3) + (tg << 1);
            #pragma unroll
            for (int half = 0; half < 2; half++) {
                int mm = m0 + wm + (mt << 4) + g + half * 8;
                float2 v;
                v.x = acc[mt][nt][half * 2 + 0] + bias[n];
                v.y = acc[mt][nt][half * 2 + 1] + bias[n + 1];
                if (R) {
                    const float2 rr = *(const float2*)&R[(size_t)mm * N + n];
                    v.x += rr.x; v.y += rr.y;
                }
                if (relu) { v.x = fmaxf(v.x, 0.0f); v.y = fmaxf(v.y, 0.0f); }
                if (mode == 2) {
                    int which = n >> 9, nl = n & 511;
                    int bb = mm >> 10, s = mm & 1023, hh = nl >> 6, dd = nl & 63;
                    size_t off = (size_t)which * XN +
                                 (((size_t)(bb * HH + hh) << 10) | (size_t)s) * DEP + dd;
                    uint2 hi, lo;
                    hi.x = f2tf(v.x); lo.x = f2tf(v.x - __uint_as_float(hi.x));
                    hi.y = f2tf(v.y); lo.y = f2tf(v.y - __uint_as_float(hi.y));
                    *(uint2*)&g_qkvhi[off] = hi;
                    *(uint2*)&g_qkvlo[off] = lo;
                } else {
                    *(float2*)&C[(size_t)mm * N + n] = v;
                }
            }
        }
    }
}

// ========== logits (tf32x3, pre-split operands, reg-prefetch): (Q K^T + mask*-1e9)/8 ==========
#define LOGITS_SMEM ((128*APITCH*2 + 64*APITCH*2) * 4)
__global__ __launch_bounds__(256) void logits_mma(const float* __restrict__ mask) {
    extern __shared__ uint32_t dsm[];
    uint32_t* Qh = dsm;
    uint32_t* Ql = Qh + 128 * APITCH;
    uint32_t* Kh = Ql + 128 * APITCH;
    uint32_t* Kl = Kh + 64 * APITCH;
    __shared__ float red[8];

    int tid  = threadIdx.x;
    int warp = tid >> 5, lane = tid & 31;
    int wm = (warp & 3) << 5;
    int wn = (warp >> 2) << 5;
    int g  = lane >> 2, tg = lane & 3;

    int bh = blockIdx.z; int bi = bh >> 3;
    int i0 = blockIdx.y << 7, j0 = blockIdx.x << 6;
    const uint32_t* qh = g_qkvhi + (size_t)bh * SS * DEP;
    const uint32_t* ql = g_qkvlo + (size_t)bh * SS * DEP;
    const uint32_t* kh = g_qkvhi + XN + (size_t)bh * SS * DEP;
    const uint32_t* kl = g_qkvlo + XN + (size_t)bh * SS * DEP;

    int arow = tid >> 3, acol = (tid & 7) << 2;

    // prefetch chunk 0
    uint4 rqh[4], rql[4], rkh[2], rkl[2];
    #pragma unroll
    for (int i = 0; i < 4; i++) {
        size_t src = (size_t)(i0 + arow + (i << 5)) * DEP + acol;
        rqh[i] = *(const uint4*)&qh[src];
        rql[i] = *(const uint4*)&ql[src];
    }
    #pragma unroll
    for (int i = 0; i < 2; i++) {
        size_t src = (size_t)(j0 + arow + (i << 5)) * DEP + acol;
        rkh[i] = *(const uint4*)&kh[src];
        rkl[i] = *(const uint4*)&kl[src];
    }

    float acc[2][4][4];
    #pragma unroll
    for (int i = 0; i < 2; i++)
        #pragma unroll
        for (int j = 0; j < 4; j++)
            #pragma unroll
            for (int r = 0; r < 4; r++) acc[i][j][r] = 0.0f;

    #pragma unroll
    for (int c = 0; c < 2; c++) {
        #pragma unroll
        for (int i = 0; i < 4; i++) {
            int r = arow + (i << 5);
            *(uint4*)&Qh[r * APITCH + acol] = rqh[i];
            *(uint4*)&Ql[r * APITCH + acol] = rql[i];
        }
        #pragma unroll
        for (int i = 0; i < 2; i++) {
            int r = arow + (i << 5);
            *(uint4*)&Kh[r * APITCH + acol] = rkh[i];
            *(uint4*)&Kl[r * APITCH + acol] = rkl[i];
        }
        __syncthreads();

        if (c == 0) {
            #pragma unroll
            for (int i = 0; i < 4; i++) {
                size_t src = (size_t)(i0 + arow + (i << 5)) * DEP + KC + acol;
                rqh[i] = *(const uint4*)&qh[src];
                rql[i] = *(const uint4*)&ql[src];
            }
            #pragma unroll
            for (int i = 0; i < 2; i++) {
                size_t src = (size_t)(j0 + arow + (i << 5)) * DEP + KC + acol;
                rkh[i] = *(const uint4*)&kh[src];
                rkl[i] = *(const uint4*)&kl[src];
            }
        }

        #pragma unroll
        for (int kk = 0; kk < KC; kk += 8) {
            uint32_t ahi[2][4], alo[2][4], bhi[4][2], blo[4][2];
            #pragma unroll
            for (int mt = 0; mt < 2; mt++) {
                int r = wm + (mt << 4) + g;
                int o0 = r * APITCH + kk + tg, o1 = (r + 8) * APITCH + kk + tg;
                ahi[mt][0] = Qh[o0];     ahi[mt][1] = Qh[o1];
                ahi[mt][2] = Qh[o0 + 4]; ahi[mt][3] = Qh[o1 + 4];
                alo[mt][0] = Ql[o0];     alo[mt][1] = Ql[o1];
                alo[mt][2] = Ql[o0 + 4]; alo[mt][3] = Ql[o1 + 4];
            }
            #pragma unroll
            for (int nt = 0; nt < 4; nt++) {
                int cc = wn + (nt << 3) + g;
                int o0 = cc * APITCH + kk + tg;
                bhi[nt][0] = Kh[o0]; bhi[nt][1] = Kh[o0 + 4];
                blo[nt][0] = Kl[o0]; blo[nt][1] = Kl[o0 + 4];
            }
            #pragma unroll
            for (int mt = 0; mt < 2; mt++)
                #pragma unroll
                for (int nt = 0; nt < 4; nt++) {
                    mma_tf32(acc[mt][nt], alo[mt], bhi[nt]);
                    mma_tf32(acc[mt][nt], ahi[mt], blo[nt]);
                    mma_tf32(acc[mt][nt], ahi[mt], bhi[nt]);
                }
        }
        __syncthreads();
    }

    float* out = g_e + (size_t)bh * SS * SS;
    float lmax = -INFINITY;
    #pragma unroll
    for (int mt = 0; mt < 2; mt++) {
        #pragma unroll
        for (int nt = 0; nt < 4; nt++) {
            int j = j0 + wn + (nt << 3) + (tg << 1);
            #pragma unroll
            for (int half = 0; half < 2; half++) {
                int i = i0 + wm + (mt << 4) + g + half * 8;
                const float2 mk = *(const float2*)&mask[((size_t)bi * SS + i) * SS + j];
                float2 v;
                v.x = (acc[mt][nt][half * 2 + 0] + mk.x * (-1e9f)) * 0.125f;
                v.y = (acc[mt][nt][half * 2 + 1] + mk.y * (-1e9f)) * 0.125f;
                *(float2*)&out[(size_t)i * SS + j] = v;
                lmax = fmaxf(lmax, fmaxf(v.x, v.y));
            }
        }
    }
    #pragma unroll
    for (int o = 16; o; o >>= 1) lmax = fmaxf(lmax, __shfl_xor_sync(0xffffffffu, lmax, o));
    if (lane == 0) red[warp] = lmax;
    __syncthreads();
    if (tid == 0) {
        float m = red[0];
        #pragma unroll
        for (int w = 1; w < 8; w++) m = fmaxf(m, red[w]);
        atomicMax(&g_maxbits[bh], f2o(m));
    }
}

// ========== attv (tf32x3): exp fused + split at fill; V pre-split; reg-prefetch ==========
#define EPITCH 136
#define ATTV_SMEM ((KC*EPITCH*2 + KC*BPITCH*2) * 4)
__global__ __launch_bounds__(256) void attv_mma() {
    extern __shared__ uint32_t dsm[];
    uint32_t* Eh = dsm;
    uint32_t* El = Eh + KC * EPITCH;
    uint32_t* Vh = El + KC * EPITCH;
    uint32_t* Vl = Vh + KC * BPITCH;
    __shared__ float red[8];

    int tid  = threadIdx.x;
    int warp = tid >> 5, lane = tid & 31;
    int wm = (warp & 3) << 5;
    int wn = (warp >> 2) << 5;
    int g  = lane >> 2, tg = lane & 3;

    int bh = blockIdx.y; int bat = bh >> 3, hh = bh & 7;
    int j0 = blockIdx.x << 7;
    const float* e = g_e + (size_t)bh * SS * SS;
    const uint32_t* vh = g_qkvhi + 2 * (size_t)XN + (size_t)bh * SS * DEP;
    const uint32_t* vl = g_qkvlo + 2 * (size_t)XN + (size_t)bh * SS * DEP;
    float mx = o2f(g_maxbits[bh]);

    int erow = tid >> 5, ecol = (tid & 31) << 2;
    int vrow = tid >> 4, vcol = (tid & 15) << 2;

    // prefetch chunk 0
    float4 re[4];
    uint4 rvh[2], rvl[2];
    #pragma unroll
    for (int i = 0; i < 4; i++)
        re[i] = *(const float4*)&e[(size_t)(erow + (i << 3)) * SS + j0 + ecol];
    #pragma unroll
    for (int i = 0; i < 2; i++) {
        size_t src = (size_t)(vrow + (i << 4)) * DEP + vcol;
        rvh[i] = *(const uint4*)&vh[src];
        rvl[i] = *(const uint4*)&vl[src];
    }

    float acc[2][4][4];
    #pragma unroll
    for (int i = 0; i < 2; i++)
        #pragma unroll
        for (int j = 0; j < 4; j++)
            #pragma unroll
            for (int r = 0; r < 4; r++) acc[i][j][r] = 0.0f;

    float lsum = 0.0f;

    for (int i0 = 0; i0 < SS; i0 += KC) {
        #pragma unroll
        for (int i = 0; i < 4; i++) {
            int r = erow + (i << 3);
            float4 le = re[i];
            le.x = __expf(le.x - mx); le.y = __expf(le.y - mx);
            le.z = __expf(le.z - mx); le.w = __expf(le.w - mx);
            lsum += (le.x + le.y) + (le.z + le.w);
            uint4 hi, lo;
            hi.x = f2tf(le.x); lo.x = f2tf(le.x - __uint_as_float(hi.x));
            hi.y = f2tf(le.y); lo.y = f2tf(le.y - __uint_as_float(hi.y));
            hi.z = f2tf(le.z); lo.z = f2tf(le.z - __uint_as_float(hi.z));
            hi.w = f2tf(le.w); lo.w = f2tf(le.w - __uint_as_float(hi.w));
            *(uint4*)&Eh[r * EPITCH + ecol] = hi;
            *(uint4*)&El[r * EPITCH + ecol] = lo;
        }
        #pragma unroll
        for (int i = 0; i < 2; i++) {
            int r = vrow + (i << 4);
            *(uint4*)&Vh[r * BPITCH + vcol] = rvh[i];
            *(uint4*)&Vl[r * BPITCH + vcol] = rvl[i];
        }
        __syncthreads();

        if (i0 + KC < SS) {
            int ib = i0 + KC;
            #pragma unroll
            for (int i = 0; i < 4; i++)
                re[i] = *(const float4*)&e[(size_t)(ib + erow + (i << 3)) * SS + j0 + ecol];
            #pragma unroll
            for (int i = 0; i < 2; i++) {
                size_t src = (size_t)(ib + vrow + (i << 4)) * DEP + vcol;
                rvh[i] = *(const uint4*)&vh[src];
                rvl[i] = *(const uint4*)&vl[src];
            }
        }

        #pragma unroll
        for (int kk = 0; kk < KC; kk += 8) {
            uint32_t ahi[2][4], alo[2][4], bhi[4][2], blo[4][2];
            #pragma unroll
            for (int mt = 0; mt < 2; mt++) {
                int r = wm + (mt << 4) + g;
                int o0 = (kk + tg) * EPITCH + r, o1 = (kk + tg + 4) * EPITCH + r;
                ahi[mt][0] = Eh[o0];     ahi[mt][1] = Eh[o0 + 8];
                ahi[mt][2] = Eh[o1];     ahi[mt][3] = Eh[o1 + 8];
                alo[mt][0] = El[o0];     alo[mt][1] = El[o0 + 8];
                alo[mt][2] = El[o1];     alo[mt][3] = El[o1 + 8];
            }
            #pragma unroll
            for (int nt = 0; nt < 4; nt++) {
                int cc = wn + (nt << 3) + g;
                int o0 = (kk + tg) * BPITCH + cc, o1 = (kk + tg + 4) * BPITCH + cc;
                bhi[nt][0] = Vh[o0]; bhi[nt][1] = Vh[o1];
                blo[nt][0] = Vl[o0]; blo[nt][1] = Vl[o1];
            }
            #pragma unroll
            for (int mt = 0; mt < 2; mt++)
                #pragma unroll
                for (int nt = 0; nt < 4; nt++) {
                    mma_tf32(acc[mt][nt], alo[mt], bhi[nt]);
                    mma_tf32(acc[mt][nt], ahi[mt], blo[nt]);
                    mma_tf32(acc[mt][nt], ahi[mt], bhi[nt]);
                }
        }
        __syncthreads();
    }

    #pragma unroll
    for (int o = 16; o; o >>= 1) lsum += __shfl_xor_sync(0xffffffffu, lsum, o);
    if (lane == 0) red[warp] = lsum;
    __syncthreads();
    if (tid == 0) {
        float s = 0.0f;
        #pragma unroll
        for (int w = 0; w < 8; w++) s += red[w];
        atomicAdd(&g_sum[bh], s);
    }

    #pragma unroll
    for (int mt = 0; mt < 2; mt++) {
        #pragma unroll
        for (int nt = 0; nt < 4; nt++) {
            int d = wn + (nt << 3) + (tg << 1);
            #pragma unroll
            for (int half = 0; half < 2; half++) {
                int j = j0 + wm + (mt << 4) + g + half * 8;
                float2 o;
                o.x = acc[mt][nt][half * 2 + 0];
                o.y = acc[mt][nt][half * 2 + 1];
                *(float2*)&g_att[((size_t)bat * SS + j) * DD + hh * DEP + d] = o;
            }
        }
    }
}

// ---------------- LayerNorm over last dim (512) ----------------
__global__ __launch_bounds__(128) void ln_kernel(
    const float* __restrict__ in, const float* __restrict__ gam,
    const float* __restrict__ bet, float* __restrict__ out)
{
    __shared__ float red[4];
    __shared__ float bc;
    int row = blockIdx.x, t = threadIdx.x;
    const float* rp = in + (size_t)row * DD;
    float v0 = rp[t], v1 = rp[t + 128], v2 = rp[t + 256], v3 = rp[t + 384];
    float s = v0 + v1 + v2 + v3;
    #pragma unroll
    for (int o = 16; o; o >>= 1) s += __shfl_xor_sync(0xffffffffu, s, o);
    if ((t & 31) == 0) red[t >> 5] = s;
    __syncthreads();
    if (t == 0) bc = (red[0] + red[1] + red[2] + red[3]) * (1.0f / 512.0f);
    __syncthreads();
    float mean = bc;
    float d0 = v0 - mean, d1 = v1 - mean, d2 = v2 - mean, d3 = v3 - mean;
    float ss = d0 * d0 + d1 * d1 + d2 * d2 + d3 * d3;
    #pragma unroll
    for (int o = 16; o; o >>= 1) ss += __shfl_xor_sync(0xffffffffu, ss, o);
    __syncthreads();
    if ((t & 31) == 0) red[t >> 5] = ss;
    __syncthreads();
    if (t == 0) bc = (red[0] + red[1] + red[2] + red[3]) * (1.0f / 512.0f);
    __syncthreads();
    float inv = rsqrtf(bc + 1e-9f);
    float* op = out + (size_t)row * DD;
    op[t]       = gam[t]       * d0 * inv + bet[t];
    op[t + 128] = gam[t + 128] * d1 * inv + bet[t + 128];
    op[t + 256] = gam[t + 256] * d2 * inv + bet[t + 256];
    op[t + 384] = gam[t + 384] * d3 * inv + bet[t + 384];
}

// ---------------- final aw write: exp(logit - mx) * rc/Z (float4) ----------------
__global__ __launch_bounds__(256) void awout_kernel(float4* __restrict__ out) {
    size_t i = (size_t)blockIdx.x * 256 + threadIdx.x;   // float4 units
    int bh = (int)(i >> 18);                              // 2^18 float4 per (b,h)
    float s = g_rowcount / g_sum[bh];
    float mx = o2f(g_maxbits[bh]);
    float4 v = ((const float4*)g_e)[i];
    v.x = __expf(v.x - mx) * s; v.y = __expf(v.y - mx) * s;
    v.z = __expf(v.z - mx) * s; v.w = __expf(v.w - mx) * s;
    out[i] = v;
}

// ---------------- launch ----------------
extern "C" void kernel_launch(void* const* d_in, const int* in_sizes, int n_in,
                              void* d_out, int out_size)
{
    const float* x_in  = (const float*)d_in[0];
    const float* mask  = (const float*)d_in[1];
    const int*   protok= (const int*)  d_in[2];
    const float* wq_w  = (const float*)d_in[3];
    const float* wq_b  = (const float*)d_in[4];
    const float* wk_w  = (const float*)d_in[5];
    const float* wk_b  = (const float*)d_in[6];
    const float* wv_w  = (const float*)d_in[7];
    const float* wv_b  = (const float*)d_in[8];
    const float* wo_w  = (const float*)d_in[9];
    const float* wo_b  = (const float*)d_in[10];
    const float* w1    = (const float*)d_in[11];
    const float* b1    = (const float*)d_in[12];
    const float* w2    = (const float*)d_in[13];
    const float* b2    = (const float*)d_in[14];
    const float* ln1g  = (const float*)d_in[15];
    const float* ln1b  = (const float*)d_in[16];
    const float* ln2g  = (const float*)d_in[17];
    const float* ln2b  = (const float*)d_in[18];

    float *px, *patt, *py, *po1, *ph, *pbqkv;
    uint32_t *pwqkv, *pwo, *pw1, *pw2;
    cudaGetSymbolAddress((void**)&px,    g_x);
    cudaGetSymbolAddress((void**)&patt,  g_att);
    cudaGetSymbolAddress((void**)&py,    g_y);
    cudaGetSymbolAddress((void**)&po1,   g_o1);
    cudaGetSymbolAddress((void**)&ph,    g_hbuf);
    cudaGetSymbolAddress((void**)&pwqkv, g_wqkv);
    cudaGetSymbolAddress((void**)&pwo,   g_wo_t);
    cudaGetSymbolAddress((void**)&pw1,   g_w1t);
    cudaGetSymbolAddress((void**)&pw2,   g_w2t);
    cudaGetSymbolAddress((void**)&pbqkv, g_bqkv);

    cudaFuncSetAttribute(logits_mma, cudaFuncAttributeMaxDynamicSharedMemorySize, LOGITS_SMEM);
    cudaFuncSetAttribute(attv_mma,   cudaFuncAttributeMaxDynamicSharedMemorySize, ATTV_SMEM);

    // one-time prep
    rowcount_kernel<<<1, 1024>>>(protok);
    pack_qkv_kernel<<<3072, 256>>>(wq_w, wk_w, wv_w, wq_b, wk_b, wv_b);
    cvtw_kernel<<<1024, 256>>>(wo_w, pwo, 512 * 512);
    cvtw_kernel<<<4096, 256>>>(w1,   pw1, 512 * 2048);
    cvtw_kernel<<<4096, 256>>>(w2,   pw2, 2048 * 512);
    copy4_kernel<<<XN / 4 / 256, 256>>>((float4*)px, (const float4*)x_in, XN / 4);

    for (int l = 0; l < NLAYERS; l++) {
        gemm_pf<<<dim3(24, 32), 256>>>(px, pwqkv, pbqkv, nullptr, nullptr, BB*SS, 1536, DD, 0, 2);
        init_reduce_kernel<<<1, 64>>>();
        logits_mma<<<dim3(16, 8, 32), 256, LOGITS_SMEM>>>(mask);
        attv_mma<<<dim3(8, 32), 256, ATTV_SMEM>>>();
        gemm_pf<<<dim3(8, 32), 256>>>(patt, pwo, wo_b, px, py, BB*SS, DD, DD, 0, 3);
        ln_kernel<<<BB*SS, 128>>>(py, ln1g, ln1b, po1);
        gemm_pf<<<dim3(32, 32), 256>>>(po1, pw1, b1, nullptr, ph, BB*SS, DFFN, DD, 1, 0);
        gemm_pf<<<dim3(8, 32), 256>>>(ph, pw2, b2, po1, py, BB*SS, DD, DFFN, 0, 0);
        ln_kernel<<<BB*SS, 128>>>(py, ln2g, ln2b, px);
    }

    if (out_size >= XN) {
        copy4_kernel<<<XN / 4 / 256, 256>>>((float4*)d_out, (const float4*)px, XN / 4);
    }
    if (out_size >= XN + AWN) {
        awout_kernel<<<AWN / 4 / 256, 256>>>((float4*)((float*)d_out + XN));
    }
}

// round 13
// speedup vs baseline: 1.0338x; 1.0321x over previous
#include <cuda_runtime.h>
#include <math.h>
#include <stdint.h>

#define BB      4
#define SS      1024
#define DD      512
#define HH      8
#define DEP     64
#define DFFN    2048
#define NLAYERS 4

#define XN  (BB*SS*DD)       /* 2097152  */
#define AWN (BB*HH*SS*SS)    /* 33554432 */

// ---------------- device scratch (no allocation allowed) ----------------
__device__ float    g_x   [XN];
__device__ uint32_t g_qkvhi[3*XN];         // tf32 hi: q | k | v (head-split layout)
__device__ uint32_t g_qkvlo[3*XN];         // tf32 lo
__device__ float    g_att [XN];
__device__ float    g_y   [XN];
__device__ float    g_o1  [XN];
__device__ float    g_hbuf[BB*SS*DFFN];
__device__ float    g_e   [AWN];           // logits (exp fused downstream)
__device__ int      g_maxbits[BB*HH];
__device__ float    g_sum    [BB*HH];
__device__ float    g_rowcount;
// tf32-packed weights (prepared once per launch)
__device__ uint32_t g_wqkv[512*1536];
__device__ uint32_t g_wo_t[512*512];
__device__ uint32_t g_w1t [512*2048];
__device__ uint32_t g_w2t [2048*512];
__device__ float    g_bqkv[1536];

// ---------------- helpers ----------------
__device__ __forceinline__ int f2o(float f) {
    int i = __float_as_int(f);
    return (i >= 0) ? i : (i ^ 0x7FFFFFFF);
}
__device__ __forceinline__ float o2f(int i) {
    return __int_as_float((i >= 0) ? i : (i ^ 0x7FFFFFFF));
}
__device__ __forceinline__ uint32_t f2tf(float f) {
    uint32_t u;
    asm("cvt.rna.tf32.f32 %0, %1;" : "=r"(u) : "f"(f));
    return u;
}
__device__ __forceinline__ void mma_tf32(float* c, const uint32_t* a, const uint32_t* b) {
    asm volatile(
        "mma.sync.aligned.m16n8k8.row.col.f32.tf32.tf32.f32 "
        "{%0,%1,%2,%3}, {%4,%5,%6,%7}, {%8,%9}, {%0,%1,%2,%3};\n"
        : "+f"(c[0]), "+f"(c[1]), "+f"(c[2]), "+f"(c[3])
        : "r"(a[0]), "r"(a[1]), "r"(a[2]), "r"(a[3]), "r"(b[0]), "r"(b[1]));
}

// ---------------- row_count = count_nonzero(protok[0, :]) ----------------
__global__ void rowcount_kernel(const int* __restrict__ protok) {
    __shared__ int red[32];
    int t = threadIdx.x;
    int c = (protok[t] != 0) ? 1 : 0;
    #pragma unroll
    for (int o = 16; o; o >>= 1) c += __shfl_xor_sync(0xffffffffu, c, o);
    if ((t & 31) == 0) red[t >> 5] = c;
    __syncthreads();
    if (t < 32) {
        int v = red[t];
        #pragma unroll
        for (int o = 16; o; o >>= 1) v += __shfl_xor_sync(0xffffffffu, v, o);
        if (t == 0) g_rowcount = (float)v;
    }
}

__global__ void init_reduce_kernel() {
    int t = threadIdx.x;
    if (t < BB * HH) { g_maxbits[t] = (int)0x80000000; g_sum[t] = 0.0f; }
}

__global__ void copy4_kernel(float4* __restrict__ dst, const float4* __restrict__ src, int n4) {
    int i = blockIdx.x * blockDim.x + threadIdx.x;
    if (i < n4) dst[i] = src[i];
}

// ---------------- weight preparation (once per launch) ----------------
__global__ void pack_qkv_kernel(const float* __restrict__ wq, const float* __restrict__ wk,
                                const float* __restrict__ wv, const float* __restrict__ bq,
                                const float* __restrict__ bk, const float* __restrict__ bv) {
    int i = blockIdx.x * 256 + threadIdx.x;
    if (i < 512 * 1536) {
        int k = i / 1536, n = i % 1536;
        const float* w = (n < 512) ? wq : (n < 1024) ? wk : wv;
        g_wqkv[i] = f2tf(w[k * 512 + (n & 511)]);
    }
    if (i < 1536) {
        g_bqkv[i] = (i < 512) ? bq[i] : (i < 1024) ? bk[i - 512] : bv[i - 1024];
    }
}
__global__ void cvtw_kernel(const float* __restrict__ w, uint32_t* __restrict__ dst, int n) {
    int i = blockIdx.x * 256 + threadIdx.x;
    if (i < n) dst[i] = f2tf(w[i]);
}

// ================= tf32 GEMM with register-prefetch double buffering =================
// mode: 0 = plain; 2 = QKV head-split, writes tf32 hi/lo pairs; 3 = A scaled rc/Z per (b,h).
#define KC 32
#define APITCH 36    /* (4g+tg)%32 conflict-free */
#define BPITCH 72    /* (8tg+g)%32 conflict-free */

__global__ __launch_bounds__(256) void gemm_pf(
    const float* __restrict__ A, const uint32_t* __restrict__ W,
    const float* __restrict__ bias, const float* __restrict__ R,
    float* __restrict__ C, int M, int N, int K, int relu, int mode)
{
    __shared__ uint32_t As[128 * APITCH];
    __shared__ uint32_t Bs[KC * BPITCH];

    int tid  = threadIdx.x;
    int warp = tid >> 5, lane = tid & 31;
    int wm = (warp & 3) << 5;
    int wn = (warp >> 2) << 5;
    int g  = lane >> 2, tg = lane & 3;

    int m0 = blockIdx.y << 7, n0 = blockIdx.x << 6;

    int arow = tid >> 3, acol = (tid & 7) << 2;    // A: 128 x 32
    int brow = tid >> 4, bcol = (tid & 15) << 2;   // B: 32 x 64

    const float* Aptr = &A[(size_t)(m0 + arow) * K + acol];
    const uint32_t* Wptr = &W[(size_t)brow * N + n0 + bcol];

    float sc[8];
    if (mode == 3) {
        float rc = g_rowcount;
        int b = (m0 + arow) >> 10;
        #pragma unroll
        for (int h = 0; h < 8; h++) sc[h] = rc / g_sum[b * 8 + h];
    }

    float4 ra[4];
    uint4  rb[2];

    #pragma unroll
    for (int i = 0; i < 4; i++) ra[i] = *(const float4*)(Aptr + (size_t)(i << 5) * K);
    #pragma unroll
    for (int i = 0; i < 2; i++) rb[i] = *(const uint4*)(Wptr + (size_t)(i << 4) * N);

    float acc[2][4][4];
    #pragma unroll
    for (int i = 0; i < 2; i++)
        #pragma unroll
        for (int j = 0; j < 4; j++)
            #pragma unroll
            for (int r = 0; r < 4; r++) acc[i][j][r] = 0.0f;

    int nch = K / KC;
    for (int ch = 0; ch < nch; ch++) {
        float s = 1.0f;
        if (mode == 3) s = sc[(ch * KC + acol) >> 6];
        #pragma unroll
        for (int i = 0; i < 4; i++) {
            uint32_t* p = &As[(arow + (i << 5)) * APITCH + acol];
            p[0] = f2tf(ra[i].x * s); p[1] = f2tf(ra[i].y * s);
            p[2] = f2tf(ra[i].z * s); p[3] = f2tf(ra[i].w * s);
        }
        #pragma unroll
        for (int i = 0; i < 2; i++)
            *(uint4*)&Bs[(brow + (i << 4)) * BPITCH + bcol] = rb[i];
        __syncthreads();

        if (ch + 1 < nch) {
            int k0 = (ch + 1) * KC;
            #pragma unroll
            for (int i = 0; i < 4; i++) ra[i] = *(const float4*)(Aptr + (size_t)(i << 5) * K + k0);
            #pragma unroll
            for (int i = 0; i < 2; i++) rb[i] = *(const uint4*)(Wptr + (size_t)((i << 4) + k0) * N);
        }

        #pragma unroll
        for (int kk = 0; kk < KC; kk += 8) {
            uint32_t af[2][4];
            #pragma unroll
            for (int mt = 0; mt < 2; mt++) {
                int r = wm + (mt << 4) + g;
                af[mt][0] = As[r * APITCH + kk + tg];
                af[mt][1] = As[(r + 8) * APITCH + kk + tg];
                af[mt][2] = As[r * APITCH + kk + tg + 4];
                af[mt][3] = As[(r + 8) * APITCH + kk + tg + 4];
            }
            uint32_t bf[4][2];
            #pragma unroll
            for (int nt = 0; nt < 4; nt++) {
                int cc = wn + (nt << 3) + g;
                bf[nt][0] = Bs[(kk + tg) * BPITCH + cc];
                bf[nt][1] = Bs[(kk + tg + 4) * BPITCH + cc];
            }
            #pragma unroll
            for (int mt = 0; mt < 2; mt++)
                #pragma unroll
                for (int nt = 0; nt < 4; nt++)
                    mma_tf32(acc[mt][nt], af[mt], bf[nt]);
        }
        __syncthreads();
    }

    #pragma unroll
    for (int mt = 0; mt < 2; mt++) {
        #pragma unroll
        for (int nt = 0; nt < 4; nt++) {
            int n = n0 + wn + (nt << 3) + (tg << 1);
            #pragma unroll
            for (int half = 0; half < 2; half++) {
                int mm = m0 + wm + (mt << 4) + g + half * 8;
                float2 v;
                v.x = acc[mt][nt][half * 2 + 0] + bias[n];
                v.y = acc[mt][nt][half * 2 + 1] + bias[n + 1];
                if (R) {
                    const float2 rr = *(const float2*)&R[(size_t)mm * N + n];
                    v.x += rr.x; v.y += rr.y;
                }
                if (relu) { v.x = fmaxf(v.x, 0.0f); v.y = fmaxf(v.y, 0.0f); }
                if (mode == 2) {
                    int which = n >> 9, nl = n & 511;
                    int bb = mm >> 10, s = mm & 1023, hh = nl >> 6, dd = nl & 63;
                    size_t off = (size_t)which * XN +
                                 (((size_t)(bb * HH + hh) << 10) | (size_t)s) * DEP + dd;
                    uint2 hi, lo;
                    hi.x = f2tf(v.x); lo.x = f2tf(v.x - __uint_as_float(hi.x));
                    hi.y = f2tf(v.y); lo.y = f2tf(v.y - __uint_as_float(hi.y));
                    *(uint2*)&g_qkvhi[off] = hi;
                    *(uint2*)&g_qkvlo[off] = lo;
                } else {
                    *(float2*)&C[(size_t)mm * N + n] = v;
                }
            }
        }
    }
}

// ========== logits (tf32x3): full-DEP single-load smem, one sync ==========
#define LPITCH 68    /* (68g+tg)%32 = (4g+tg)%32 conflict-free */
#define LOGITS_SMEM ((128*LPITCH*2 + 64*LPITCH*2) * 4)   /* 104448 B */
__global__ __launch_bounds__(256) void logits_mma(const float* __restrict__ mask) {
    extern __shared__ uint32_t dsm[];
    uint32_t* Qh = dsm;
    uint32_t* Ql = Qh + 128 * LPITCH;
    uint32_t* Kh = Ql + 128 * LPITCH;
    uint32_t* Kl = Kh + 64 * LPITCH;
    __shared__ float red[8];

    int tid  = threadIdx.x;
    int warp = tid >> 5, lane = tid & 31;
    int wm = (warp & 3) << 5;
    int wn = (warp >> 2) << 5;
    int g  = lane >> 2, tg = lane & 3;

    int bh = blockIdx.z; int bi = bh >> 3;
    int i0 = blockIdx.y << 7, j0 = blockIdx.x << 6;
    const uint32_t* qh = g_qkvhi + (size_t)bh * SS * DEP;
    const uint32_t* ql = g_qkvlo + (size_t)bh * SS * DEP;
    const uint32_t* kh = g_qkvhi + XN + (size_t)bh * SS * DEP;
    const uint32_t* kl = g_qkvlo + XN + (size_t)bh * SS * DEP;

    // fill: 16 rows x 64 cols per pass (full DEP row per thread-group)
    int frow = tid >> 4, fcol = (tid & 15) << 2;
    #pragma unroll
    for (int i = 0; i < 8; i++) {
        int r = frow + (i << 4);
        size_t src = (size_t)(i0 + r) * DEP + fcol;
        *(uint4*)&Qh[r * LPITCH + fcol] = *(const uint4*)&qh[src];
        *(uint4*)&Ql[r * LPITCH + fcol] = *(const uint4*)&ql[src];
    }
    #pragma unroll
    for (int i = 0; i < 4; i++) {
        int r = frow + (i << 4);
        size_t src = (size_t)(j0 + r) * DEP + fcol;
        *(uint4*)&Kh[r * LPITCH + fcol] = *(const uint4*)&kh[src];
        *(uint4*)&Kl[r * LPITCH + fcol] = *(const uint4*)&kl[src];
    }
    __syncthreads();

    float acc[2][4][4];
    #pragma unroll
    for (int i = 0; i < 2; i++)
        #pragma unroll
        for (int j = 0; j < 4; j++)
            #pragma unroll
            for (int r = 0; r < 4; r++) acc[i][j][r] = 0.0f;

    #pragma unroll
    for (int kk = 0; kk < DEP; kk += 8) {
        uint32_t ahi[2][4], alo[2][4], bhi[4][2], blo[4][2];
        #pragma unroll
        for (int mt = 0; mt < 2; mt++) {
            int r = wm + (mt << 4) + g;
            int o0 = r * LPITCH + kk + tg, o1 = (r + 8) * LPITCH + kk + tg;
            ahi[mt][0] = Qh[o0];     ahi[mt][1] = Qh[o1];
            ahi[mt][2] = Qh[o0 + 4]; ahi[mt][3] = Qh[o1 + 4];
            alo[mt][0] = Ql[o0];     alo[mt][1] = Ql[o1];
            alo[mt][2] = Ql[o0 + 4]; alo[mt][3] = Ql[o1 + 4];
        }
        #pragma unroll
        for (int nt = 0; nt < 4; nt++) {
            int cc = wn + (nt << 3) + g;
            int o0 = cc * LPITCH + kk + tg;
            bhi[nt][0] = Kh[o0]; bhi[nt][1] = Kh[o0 + 4];
            blo[nt][0] = Kl[o0]; blo[nt][1] = Kl[o0 + 4];
        }
        #pragma unroll
        for (int mt = 0; mt < 2; mt++)
            #pragma unroll
            for (int nt = 0; nt < 4; nt++) {
                mma_tf32(acc[mt][nt], alo[mt], bhi[nt]);
                mma_tf32(acc[mt][nt], ahi[mt], blo[nt]);
                mma_tf32(acc[mt][nt], ahi[mt], bhi[nt]);
            }
    }

    float* out = g_e + (size_t)bh * SS * SS;
    float lmax = -INFINITY;
    #pragma unroll
    for (int mt = 0; mt < 2; mt++) {
        #pragma unroll
        for (int nt = 0; nt < 4; nt++) {
            int j = j0 + wn + (nt << 3) + (tg << 1);
            #pragma unroll
            for (int half = 0; half < 2; half++) {
                int i = i0 + wm + (mt << 4) + g + half * 8;
                const float2 mk = *(const float2*)&mask[((size_t)bi * SS + i) * SS + j];
                float2 v;
                v.x = (acc[mt][nt][half * 2 + 0] + mk.x * (-1e9f)) * 0.125f;
                v.y = (acc[mt][nt][half * 2 + 1] + mk.y * (-1e9f)) * 0.125f;
                *(float2*)&out[(size_t)i * SS + j] = v;
                lmax = fmaxf(lmax, fmaxf(v.x, v.y));
            }
        }
    }
    #pragma unroll
    for (int o = 16; o; o >>= 1) lmax = fmaxf(lmax, __shfl_xor_sync(0xffffffffu, lmax, o));
    if (lane == 0) red[warp] = lmax;
    __syncthreads();
    if (tid == 0) {
        float m = red[0];
        #pragma unroll
        for (int w = 1; w < 8; w++) m = fmaxf(m, red[w]);
        atomicMax(&g_maxbits[bh], f2o(m));
    }
}

// ========== attv (tf32x3): exp fused + split at fill; V pre-split; reg-prefetch ==========
#define EPITCH 136
#define ATTV_SMEM ((KC*EPITCH*2 + KC*BPITCH*2) * 4)
__global__ __launch_bounds__(256) void attv_mma() {
    extern __shared__ uint32_t dsm[];
    uint32_t* Eh = dsm;
    uint32_t* El = Eh + KC * EPITCH;
    uint32_t* Vh = El + KC * EPITCH;
    uint32_t* Vl = Vh + KC * BPITCH;
    __shared__ float red[8];

    int tid  = threadIdx.x;
    int warp = tid >> 5, lane = tid & 31;
    int wm = (warp & 3) << 5;
    int wn = (warp >> 2) << 5;
    int g  = lane >> 2, tg = lane & 3;

    int bh = blockIdx.y; int bat = bh >> 3, hh = bh & 7;
    int j0 = blockIdx.x << 7;
    const float* e = g_e + (size_t)bh * SS * SS;
    const uint32_t* vh = g_qkvhi + 2 * (size_t)XN + (size_t)bh * SS * DEP;
    const uint32_t* vl = g_qkvlo + 2 * (size_t)XN + (size_t)bh * SS * DEP;
    float mx = o2f(g_maxbits[bh]);

    int erow = tid >> 5, ecol = (tid & 31) << 2;
    int vrow = tid >> 4, vcol = (tid & 15) << 2;

    // prefetch chunk 0
    float4 re[4];
    uint4 rvh[2], rvl[2];
    #pragma unroll
    for (int i = 0; i < 4; i++)
        re[i] = *(const float4*)&e[(size_t)(erow + (i << 3)) * SS + j0 + ecol];
    #pragma unroll
    for (int i = 0; i < 2; i++) {
        size_t src = (size_t)(vrow + (i << 4)) * DEP + vcol;
        rvh[i] = *(const uint4*)&vh[src];
        rvl[i] = *(const uint4*)&vl[src];
    }

    float acc[2][4][4];
    #pragma unroll
    for (int i = 0; i < 2; i++)
        #pragma unroll
        for (int j = 0; j < 4; j++)
            #pragma unroll
            for (int r = 0; r < 4; r++) acc[i][j][r] = 0.0f;

    float lsum = 0.0f;

    for (int i0 = 0; i0 < SS; i0 += KC) {
        #pragma unroll
        for (int i = 0; i < 4; i++) {
            int r = erow + (i << 3);
            float4 le = re[i];
            le.x = __expf(le.x - mx); le.y = __expf(le.y - mx);
            le.z = __expf(le.z - mx); le.w = __expf(le.w - mx);
            lsum += (le.x + le.y) + (le.z + le.w);
            uint4 hi, lo;
            hi.x = f2tf(le.x); lo.x = f2tf(le.x - __uint_as_float(hi.x));
            hi.y = f2tf(le.y); lo.y = f2tf(le.y - __uint_as_float(hi.y));
            hi.z = f2tf(le.z); lo.z = f2tf(le.z - __uint_as_float(hi.z));
            hi.w = f2tf(le.w); lo.w = f2tf(le.w - __uint_as_float(hi.w));
            *(uint4*)&Eh[r * EPITCH + ecol] = hi;
            *(uint4*)&El[r * EPITCH + ecol] = lo;
        }
        #pragma unroll
        for (int i = 0; i < 2; i++) {
            int r = vrow + (i << 4);
            *(uint4*)&Vh[r * BPITCH + vcol] = rvh[i];
            *(uint4*)&Vl[r * BPITCH + vcol] = rvl[i];
        }
        __syncthreads();

        if (i0 + KC < SS) {
            int ib = i0 + KC;
            #pragma unroll
            for (int i = 0; i < 4; i++)
                re[i] = *(const float4*)&e[(size_t)(ib + erow + (i << 3)) * SS + j0 + ecol];
            #pragma unroll
            for (int i = 0; i < 2; i++) {
                size_t src = (size_t)(ib + vrow + (i << 4)) * DEP + vcol;
                rvh[i] = *(const uint4*)&vh[src];
                rvl[i] = *(const uint4*)&vl[src];
            }
        }

        #pragma unroll
        for (int kk = 0; kk < KC; kk += 8) {
            uint32_t ahi[2][4], alo[2][4], bhi[4][2], blo[4][2];
            #pragma unroll
            for (int mt = 0; mt < 2; mt++) {
                int r = wm + (mt << 4) + g;
                int o0 = (kk + tg) * EPITCH + r, o1 = (kk + tg + 4) * EPITCH + r;
                ahi[mt][0] = Eh[o0];     ahi[mt][1] = Eh[o0 + 8];
                ahi[mt][2] = Eh[o1];     ahi[mt][3] = Eh[o1 + 8];
                alo[mt][0] = El[o0];     alo[mt][1] = El[o0 + 8];
                alo[mt][2] = El[o1];     alo[mt][3] = El[o1 + 8];
            }
            #pragma unroll
            for (int nt = 0; nt < 4; nt++) {
                int cc = wn + (nt << 3) + g;
                int o0 = (kk + tg) * BPITCH + cc, o1 = (kk + tg + 4) * BPITCH + cc;
                bhi[nt][0] = Vh[o0]; bhi[nt][1] = Vh[o1];
                blo[nt][0] = Vl[o0]; blo[nt][1] = Vl[o1];
            }
            #pragma unroll
            for (int mt = 0; mt < 2; mt++)
                #pragma unroll
                for (int nt = 0; nt < 4; nt++) {
                    mma_tf32(acc[mt][nt], alo[mt], bhi[nt]);
                    mma_tf32(acc[mt][nt], ahi[mt], blo[nt]);
                    mma_tf32(acc[mt][nt], ahi[mt], bhi[nt]);
                }
        }
        __syncthreads();
    }

    #pragma unroll
    for (int o = 16; o; o >>= 1) lsum += __shfl_xor_sync(0xffffffffu, lsum, o);
    if (lane == 0) red[warp] = lsum;
    __syncthreads();
    if (tid == 0) {
        float s = 0.0f;
        #pragma unroll
        for (int w = 0; w < 8; w++) s += red[w];
        atomicAdd(&g_sum[bh], s);
    }

    #pragma unroll
    for (int mt = 0; mt < 2; mt++) {
        #pragma unroll
        for (int nt = 0; nt < 4; nt++) {
            int d = wn + (nt << 3) + (tg << 1);
            #pragma unroll
            for (int half = 0; half < 2; half++) {
                int j = j0 + wm + (mt << 4) + g + half * 8;
                float2 o;
                o.x = acc[mt][nt][half * 2 + 0];
                o.y = acc[mt][nt][half * 2 + 1];
                *(float2*)&g_att[((size_t)bat * SS + j) * DD + hh * DEP + d] = o;
            }
        }
    }
}

// ---------------- LayerNorm over last dim (512) ----------------
__global__ __launch_bounds__(128) void ln_kernel(
    const float* __restrict__ in, const float* __restrict__ gam,
    const float* __restrict__ bet, float* __restrict__ out)
{
    __shared__ float red[4];
    __shared__ float bc;
    int row = blockIdx.x, t = threadIdx.x;
    const float* rp = in + (size_t)row * DD;
    float v0 = rp[t], v1 = rp[t + 128], v2 = rp[t + 256], v3 = rp[t + 384];
    float s = v0 + v1 + v2 + v3;
    #pragma unroll
    for (int o = 16; o; o >>= 1) s += __shfl_xor_sync(0xffffffffu, s, o);
    if ((t & 31) == 0) red[t >> 5] = s;
    __syncthreads();
    if (t == 0) bc = (red[0] + red[1] + red[2] + red[3]) * (1.0f / 512.0f);
    __syncthreads();
    float mean = bc;
    float d0 = v0 - mean, d1 = v1 - mean, d2 = v2 - mean, d3 = v3 - mean;
    float ss = d0 * d0 + d1 * d1 + d2 * d2 + d3 * d3;
    #pragma unroll
    for (int o = 16; o; o >>= 1) ss += __shfl_xor_sync(0xffffffffu, ss, o);
    __syncthreads();
    if ((t & 31) == 0) red[t >> 5] = ss;
    __syncthreads();
    if (t == 0) bc = (red[0] + red[1] + red[2] + red[3]) * (1.0f / 512.0f);
    __syncthreads();
    float inv = rsqrtf(bc + 1e-9f);
    float* op = out + (size_t)row * DD;
    op[t]       = gam[t]       * d0 * inv + bet[t];
    op[t + 128] = gam[t + 128] * d1 * inv + bet[t + 128];
    op[t + 256] = gam[t + 256] * d2 * inv + bet[t + 256];
    op[t + 384] = gam[t + 384] * d3 * inv + bet[t + 384];
}

// ---------------- final aw write: exp(logit - mx) * rc/Z (float4) ----------------
__global__ __launch_bounds__(256) void awout_kernel(float4* __restrict__ out) {
    size_t i = (size_t)blockIdx.x * 256 + threadIdx.x;   // float4 units
    int bh = (int)(i >> 18);                              // 2^18 float4 per (b,h)
    float s = g_rowcount / g_sum[bh];
    float mx = o2f(g_maxbits[bh]);
    float4 v = ((const float4*)g_e)[i];
    v.x = __expf(v.x - mx) * s; v.y = __expf(v.y - mx) * s;
    v.z = __expf(v.z - mx) * s; v.w = __expf(v.w - mx) * s;
    out[i] = v;
}

// ---------------- launch ----------------
extern "C" void kernel_launch(void* const* d_in, const int* in_sizes, int n_in,
                              void* d_out, int out_size)
{
    const float* x_in  = (const float*)d_in[0];
    const float* mask  = (const float*)d_in[1];
    const int*   protok= (const int*)  d_in[2];
    const float* wq_w  = (const float*)d_in[3];
    const float* wq_b  = (const float*)d_in[4];
    const float* wk_w  = (const float*)d_in[5];
    const float* wk_b  = (const float*)d_in[6];
    const float* wv_w  = (const float*)d_in[7];
    const float* wv_b  = (const float*)d_in[8];
    const float* wo_w  = (const float*)d_in[9];
    const float* wo_b  = (const float*)d_in[10];
    const float* w1    = (const float*)d_in[11];
    const float* b1    = (const float*)d_in[12];
    const float* w2    = (const float*)d_in[13];
    const float* b2    = (const float*)d_in[14];
    const float* ln1g  = (const float*)d_in[15];
    const float* ln1b  = (const float*)d_in[16];
    const float* ln2g  = (const float*)d_in[17];
    const float* ln2b  = (const float*)d_in[18];

    float *px, *patt, *py, *po1, *ph, *pbqkv;
    uint32_t *pwqkv, *pwo, *pw1, *pw2;
    cudaGetSymbolAddress((void**)&px,    g_x);
    cudaGetSymbolAddress((void**)&patt,  g_att);
    cudaGetSymbolAddress((void**)&py,    g_y);
    cudaGetSymbolAddress((void**)&po1,   g_o1);
    cudaGetSymbolAddress((void**)&ph,    g_hbuf);
    cudaGetSymbolAddress((void**)&pwqkv, g_wqkv);
    cudaGetSymbolAddress((void**)&pwo,   g_wo_t);
    cudaGetSymbolAddress((void**)&pw1,   g_w1t);
    cudaGetSymbolAddress((void**)&pw2,   g_w2t);
    cudaGetSymbolAddress((void**)&pbqkv, g_bqkv);

    cudaFuncSetAttribute(logits_mma, cudaFuncAttributeMaxDynamicSharedMemorySize, LOGITS_SMEM);
    cudaFuncSetAttribute(attv_mma,   cudaFuncAttributeMaxDynamicSharedMemorySize, ATTV_SMEM);

    // one-time prep
    rowcount_kernel<<<1, 1024>>>(protok);
    pack_qkv_kernel<<<3072, 256>>>(wq_w, wk_w, wv_w, wq_b, wk_b, wv_b);
    cvtw_kernel<<<1024, 256>>>(wo_w, pwo, 512 * 512);
    cvtw_kernel<<<4096, 256>>>(w1,   pw1, 512 * 2048);
    cvtw_kernel<<<4096, 256>>>(w2,   pw2, 2048 * 512);
    copy4_kernel<<<XN / 4 / 256, 256>>>((float4*)px, (const float4*)x_in, XN / 4);

    for (int l = 0; l < NLAYERS; l++) {
        gemm_pf<<<dim3(24, 32), 256>>>(px, pwqkv, pbqkv, nullptr, nullptr, BB*SS, 1536, DD, 0, 2);
        init_reduce_kernel<<<1, 64>>>();
        logits_mma<<<dim3(16, 8, 32), 256, LOGITS_SMEM>>>(mask);
        attv_mma<<<dim3(8, 32), 256, ATTV_SMEM>>>();
        gemm_pf<<<dim3(8, 32), 256>>>(patt, pwo, wo_b, px, py, BB*SS, DD, DD, 0, 3);
        ln_kernel<<<BB*SS, 128>>>(py, ln1g, ln1b, po1);
        gemm_pf<<<dim3(32, 32), 256>>>(po1, pw1, b1, nullptr, ph, BB*SS, DFFN, DD, 1, 0);
        gemm_pf<<<dim3(8, 32), 256>>>(ph, pw2, b2, po1, py, BB*SS, DD, DFFN, 0, 0);
        ln_kernel<<<BB*SS, 128>>>(py, ln2g, ln2b, px);
    }

    if (out_size >= XN) {
        copy4_kernel<<<XN / 4 / 256, 256>>>((float4*)d_out, (const float4*)px, XN / 4);
    }
    if (out_size >= XN + AWN) {
        awout_kernel<<<AWN / 4 / 256, 256>>>((float4*)((float*)d_out + XN));
    }
}

// round 14
// speedup vs baseline: 1.0920x; 1.0564x over previous
#include <cuda_runtime.h>
#include <math.h>
#include <stdint.h>

#define BB      4
#define SS      1024
#define DD      512
#define HH      8
#define DEP     64
#define DFFN    2048
#define NLAYERS 4

#define XN  (BB*SS*DD)       /* 2097152  */
#define AWN (BB*HH*SS*SS)    /* 33554432 */

// ---------------- device scratch (no allocation allowed) ----------------
__device__ float    g_x   [XN];
__device__ uint32_t g_qkvhi[3*XN];         // tf32 hi: q | k | v (head-split layout)
__device__ uint32_t g_qkvlo[3*XN];         // tf32 lo
__device__ float    g_att [XN];
__device__ float    g_y   [XN];
__device__ float    g_o1  [XN];
__device__ float    g_hbuf[BB*SS*DFFN];
__device__ float    g_e   [AWN];           // logits (exp fused downstream)
__device__ int      g_maxbits[NLAYERS*BB*HH];
__device__ float    g_sum    [NLAYERS*BB*HH];
__device__ float    g_rowcount;
// tf32-packed weights (prepared once per launch)
__device__ uint32_t g_wqkv[512*1536];
__device__ uint32_t g_wo_t[512*512];
__device__ uint32_t g_w1t [512*2048];
__device__ uint32_t g_w2t [2048*512];
__device__ float    g_bqkv[1536];

// ---------------- helpers ----------------
__device__ __forceinline__ int f2o(float f) {
    int i = __float_as_int(f);
    return (i >= 0) ? i : (i ^ 0x7FFFFFFF);
}
__device__ __forceinline__ float o2f(int i) {
    return __int_as_float((i >= 0) ? i : (i ^ 0x7FFFFFFF));
}
__device__ __forceinline__ uint32_t f2tf(float f) {
    uint32_t u;
    asm("cvt.rna.tf32.f32 %0, %1;" : "=r"(u) : "f"(f));
    return u;
}
__device__ __forceinline__ void mma_tf32(float* c, const uint32_t* a, const uint32_t* b) {
    asm volatile(
        "mma.sync.aligned.m16n8k8.row.col.f32.tf32.tf32.f32 "
        "{%0,%1,%2,%3}, {%4,%5,%6,%7}, {%8,%9}, {%0,%1,%2,%3};\n"
        : "+f"(c[0]), "+f"(c[1]), "+f"(c[2]), "+f"(c[3])
        : "r"(a[0]), "r"(a[1]), "r"(a[2]), "r"(a[3]), "r"(b[0]), "r"(b[1]));
}

// ---------------- row_count + all-layer reduction init ----------------
__global__ void rowcount_kernel(const int* __restrict__ protok) {
    __shared__ int red[32];
    int t = threadIdx.x;
    int c = (protok[t] != 0) ? 1 : 0;
    #pragma unroll
    for (int o = 16; o; o >>= 1) c += __shfl_xor_sync(0xffffffffu, c, o);
    if ((t & 31) == 0) red[t >> 5] = c;
    __syncthreads();
    if (t < 32) {
        int v = red[t];
        #pragma unroll
        for (int o = 16; o; o >>= 1) v += __shfl_xor_sync(0xffffffffu, v, o);
        if (t == 0) g_rowcount = (float)v;
    }
    if (t < NLAYERS * BB * HH) { g_maxbits[t] = (int)0x80000000; g_sum[t] = 0.0f; }
}

__global__ void copy4_kernel(float4* __restrict__ dst, const float4* __restrict__ src, int n4) {
    int i = blockIdx.x * blockDim.x + threadIdx.x;
    if (i < n4) dst[i] = src[i];
}

// ---------------- weight preparation (once per launch) ----------------
__global__ void pack_qkv_kernel(const float* __restrict__ wq, const float* __restrict__ wk,
                                const float* __restrict__ wv, const float* __restrict__ bq,
                                const float* __restrict__ bk, const float* __restrict__ bv) {
    int i = blockIdx.x * 256 + threadIdx.x;
    if (i < 512 * 1536) {
        int k = i / 1536, n = i % 1536;
        const float* w = (n < 512) ? wq : (n < 1024) ? wk : wv;
        g_wqkv[i] = f2tf(w[k * 512 + (n & 511)]);
    }
    if (i < 1536) {
        g_bqkv[i] = (i < 512) ? bq[i] : (i < 1024) ? bk[i - 512] : bv[i - 1024];
    }
}
__global__ void cvtw_kernel(const float* __restrict__ w, uint32_t* __restrict__ dst, int n) {
    int i = blockIdx.x * 256 + threadIdx.x;
    if (i < n) dst[i] = f2tf(w[i]);
}

// ================= tf32 GEMM with register-prefetch double buffering =================
// mode: 0 = plain; 2 = QKV head-split, writes tf32 hi/lo pairs; 3 = A scaled rc/Z per (b,h).
#define KC 32
#define APITCH 36    /* (4g+tg)%32 conflict-free */
#define BPITCH 72    /* (8tg+g)%32 conflict-free */

__global__ __launch_bounds__(256) void gemm_pf(
    const float* __restrict__ A, const uint32_t* __restrict__ W,
    const float* __restrict__ bias, const float* __restrict__ R,
    float* __restrict__ C, int M, int N, int K, int relu, int mode, int loff)
{
    __shared__ uint32_t As[128 * APITCH];
    __shared__ uint32_t Bs[KC * BPITCH];

    int tid  = threadIdx.x;
    int warp = tid >> 5, lane = tid & 31;
    int wm = (warp & 3) << 5;
    int wn = (warp >> 2) << 5;
    int g  = lane >> 2, tg = lane & 3;

    int m0 = blockIdx.y << 7, n0 = blockIdx.x << 6;

    int arow = tid >> 3, acol = (tid & 7) << 2;    // A: 128 x 32
    int brow = tid >> 4, bcol = (tid & 15) << 2;   // B: 32 x 64

    const float* Aptr = &A[(size_t)(m0 + arow) * K + acol];
    const uint32_t* Wptr = &W[(size_t)brow * N + n0 + bcol];

    float sc[8];
    if (mode == 3) {
        float rc = g_rowcount;
        int b = (m0 + arow) >> 10;
        #pragma unroll
        for (int h = 0; h < 8; h++) sc[h] = rc / g_sum[loff + b * 8 + h];
    }

    float4 ra[4];
    uint4  rb[2];

    #pragma unroll
    for (int i = 0; i < 4; i++) ra[i] = *(const float4*)(Aptr + (size_t)(i << 5) * K);
    #pragma unroll
    for (int i = 0; i < 2; i++) rb[i] = *(const uint4*)(Wptr + (size_t)(i << 4) * N);

    float acc[2][4][4];
    #pragma unroll
    for (int i = 0; i < 2; i++)
        #pragma unroll
        for (int j = 0; j < 4; j++)
            #pragma unroll
            for (int r = 0; r < 4; r++) acc[i][j][r] = 0.0f;

    int nch = K / KC;
    for (int ch = 0; ch < nch; ch++) {
        float s = 1.0f;
        if (mode == 3) s = sc[(ch * KC + acol) >> 6];
        #pragma unroll
        for (int i = 0; i < 4; i++) {
            uint32_t* p = &As[(arow + (i << 5)) * APITCH + acol];
            p[0] = f2tf(ra[i].x * s); p[1] = f2tf(ra[i].y * s);
            p[2] = f2tf(ra[i].z * s); p[3] = f2tf(ra[i].w * s);
        }
        #pragma unroll
        for (int i = 0; i < 2; i++)
            *(uint4*)&Bs[(brow + (i << 4)) * BPITCH + bcol] = rb[i];
        __syncthreads();

        if (ch + 1 < nch) {
            int k0 = (ch + 1) * KC;
            #pragma unroll
            for (int i = 0; i < 4; i++) ra[i] = *(const float4*)(Aptr + (size_t)(i << 5) * K + k0);
            #pragma unroll
            for (int i = 0; i < 2; i++) rb[i] = *(const uint4*)(Wptr + (size_t)((i << 4) + k0) * N);
        }

        #pragma unroll
        for (int kk = 0; kk < KC; kk += 8) {
            uint32_t af[2][4];
            #pragma unroll
            for (int mt = 0; mt < 2; mt++) {
                int r = wm + (mt << 4) + g;
                af[mt][0] = As[r * APITCH + kk + tg];
                af[mt][1] = As[(r + 8) * APITCH + kk + tg];
                af[mt][2] = As[r * APITCH + kk + tg + 4];
                af[mt][3] = As[(r + 8) * APITCH + kk + tg + 4];
            }
            uint32_t bf[4][2];
            #pragma unroll
            for (int nt = 0; nt < 4; nt++) {
                int cc = wn + (nt << 3) + g;
                bf[nt][0] = Bs[(kk + tg) * BPITCH + cc];
                bf[nt][1] = Bs[(kk + tg + 4) * BPITCH + cc];
            }
            #pragma unroll
            for (int mt = 0; mt < 2; mt++)
                #pragma unroll
                for (int nt = 0; nt < 4; nt++)
                    mma_tf32(acc[mt][nt], af[mt], bf[nt]);
        }
        __syncthreads();
    }

    #pragma unroll
    for (int mt = 0; mt < 2; mt++) {
        #pragma unroll
        for (int nt = 0; nt < 4; nt++) {
            int n = n0 + wn + (nt << 3) + (tg << 1);
            #pragma unroll
            for (int half = 0; half < 2; half++) {
                int mm = m0 + wm + (mt << 4) + g + half * 8;
                float2 v;
                v.x = acc[mt][nt][half * 2 + 0] + bias[n];
                v.y = acc[mt][nt][half * 2 + 1] + bias[n + 1];
                if (R) {
                    const float2 rr = *(const float2*)&R[(size_t)mm * N + n];
                    v.x += rr.x; v.y += rr.y;
                }
                if (relu) { v.x = fmaxf(v.x, 0.0f); v.y = fmaxf(v.y, 0.0f); }
                if (mode == 2) {
                    int which = n >> 9, nl = n & 511;
                    int bb = mm >> 10, s = mm & 1023, hh = nl >> 6, dd = nl & 63;
                    size_t off = (size_t)which * XN +
                                 (((size_t)(bb * HH + hh) << 10) | (size_t)s) * DEP + dd;
                    uint2 hi, lo;
                    hi.x = f2tf(v.x); lo.x = f2tf(v.x - __uint_as_float(hi.x));
                    hi.y = f2tf(v.y); lo.y = f2tf(v.y - __uint_as_float(hi.y));
                    *(uint2*)&g_qkvhi[off] = hi;
                    *(uint2*)&g_qkvlo[off] = lo;
                } else {
                    *(float2*)&C[(size_t)mm * N + n] = v;
                }
            }
        }
    }
}

// ========== logits (tf32x3, pre-split operands): (Q K^T + mask*-1e9)/8, fused max ==========
// mask[b,i,j] == mask[b,0,j] (broadcast of pad over i) -> read row 0 only.
#define LOGITS_SMEM ((128*APITCH*2 + 64*APITCH*2) * 4)
__global__ __launch_bounds__(256) void logits_mma(const float* __restrict__ mask, int loff) {
    extern __shared__ uint32_t dsm[];
    uint32_t* Qh = dsm;
    uint32_t* Ql = Qh + 128 * APITCH;
    uint32_t* Kh = Ql + 128 * APITCH;
    uint32_t* Kl = Kh + 64 * APITCH;
    __shared__ float red[8];

    int tid  = threadIdx.x;
    int warp = tid >> 5, lane = tid & 31;
    int wm = (warp & 3) << 5;
    int wn = (warp >> 2) << 5;
    int g  = lane >> 2, tg = lane & 3;

    int bh = blockIdx.z; int bi = bh >> 3;
    int i0 = blockIdx.y << 7, j0 = blockIdx.x << 6;
    const uint32_t* qh = g_qkvhi + (size_t)bh * SS * DEP;
    const uint32_t* ql = g_qkvlo + (size_t)bh * SS * DEP;
    const uint32_t* kh = g_qkvhi + XN + (size_t)bh * SS * DEP;
    const uint32_t* kl = g_qkvlo + XN + (size_t)bh * SS * DEP;

    int arow = tid >> 3, acol = (tid & 7) << 2;

    float acc[2][4][4];
    #pragma unroll
    for (int i = 0; i < 2; i++)
        #pragma unroll
        for (int j = 0; j < 4; j++)
            #pragma unroll
            for (int r = 0; r < 4; r++) acc[i][j][r] = 0.0f;

    for (int k0 = 0; k0 < DEP; k0 += KC) {
        #pragma unroll
        for (int i = 0; i < 4; i++) {
            int r = arow + (i << 5);
            size_t src = (size_t)(i0 + r) * DEP + k0 + acol;
            *(uint4*)&Qh[r * APITCH + acol] = *(const uint4*)&qh[src];
            *(uint4*)&Ql[r * APITCH + acol] = *(const uint4*)&ql[src];
        }
        #pragma unroll
        for (int i = 0; i < 2; i++) {
            int r = arow + (i << 5);
            size_t src = (size_t)(j0 + r) * DEP + k0 + acol;
            *(uint4*)&Kh[r * APITCH + acol] = *(const uint4*)&kh[src];
            *(uint4*)&Kl[r * APITCH + acol] = *(const uint4*)&kl[src];
        }
        __syncthreads();

        #pragma unroll
        for (int kk = 0; kk < KC; kk += 8) {
            uint32_t ahi[2][4], alo[2][4], bhi[4][2], blo[4][2];
            #pragma unroll
            for (int mt = 0; mt < 2; mt++) {
                int r = wm + (mt << 4) + g;
                int o0 = r * APITCH + kk + tg, o1 = (r + 8) * APITCH + kk + tg;
                ahi[mt][0] = Qh[o0];     ahi[mt][1] = Qh[o1];
                ahi[mt][2] = Qh[o0 + 4]; ahi[mt][3] = Qh[o1 + 4];
                alo[mt][0] = Ql[o0];     alo[mt][1] = Ql[o1];
                alo[mt][2] = Ql[o0 + 4]; alo[mt][3] = Ql[o1 + 4];
            }
            #pragma unroll
            for (int nt = 0; nt < 4; nt++) {
                int cc = wn + (nt << 3) + g;
                int o0 = cc * APITCH + kk + tg;
                bhi[nt][0] = Kh[o0]; bhi[nt][1] = Kh[o0 + 4];
                blo[nt][0] = Kl[o0]; blo[nt][1] = Kl[o0 + 4];
            }
            #pragma unroll
            for (int mt = 0; mt < 2; mt++)
                #pragma unroll
                for (int nt = 0; nt < 4; nt++) {
                    mma_tf32(acc[mt][nt], alo[mt], bhi[nt]);
                    mma_tf32(acc[mt][nt], ahi[mt], blo[nt]);
                    mma_tf32(acc[mt][nt], ahi[mt], bhi[nt]);
                }
        }
        __syncthreads();
    }

    float* out = g_e + (size_t)bh * SS * SS;
    float lmax = -INFINITY;
    #pragma unroll
    for (int nt = 0; nt < 4; nt++) {
        int j = j0 + wn + (nt << 3) + (tg << 1);
        // mask row 0 of this batch: identical for every i (broadcast)
        const float2 mk = *(const float2*)&mask[(size_t)bi * SS * SS + j];
        #pragma unroll
        for (int mt = 0; mt < 2; mt++) {
            #pragma unroll
            for (int half = 0; half < 2; half++) {
                int i = i0 + wm + (mt << 4) + g + half * 8;
                float2 v;
                v.x = (acc[mt][nt][half * 2 + 0] + mk.x * (-1e9f)) * 0.125f;
                v.y = (acc[mt][nt][half * 2 + 1] + mk.y * (-1e9f)) * 0.125f;
                *(float2*)&out[(size_t)i * SS + j] = v;
                lmax = fmaxf(lmax, fmaxf(v.x, v.y));
            }
        }
    }
    #pragma unroll
    for (int o = 16; o; o >>= 1) lmax = fmaxf(lmax, __shfl_xor_sync(0xffffffffu, lmax, o));
    if (lane == 0) red[warp] = lmax;
    __syncthreads();
    if (tid == 0) {
        float m = red[0];
        #pragma unroll
        for (int w = 1; w < 8; w++) m = fmaxf(m, red[w]);
        atomicMax(&g_maxbits[loff + bh], f2o(m));
    }
}

// ========== attv (tf32x3): exp fused + split at fill; V pre-split; reg-prefetch ==========
#define EPITCH 136
#define ATTV_SMEM ((KC*EPITCH*2 + KC*BPITCH*2) * 4)
__global__ __launch_bounds__(256) void attv_mma(int loff) {
    extern __shared__ uint32_t dsm[];
    uint32_t* Eh = dsm;
    uint32_t* El = Eh + KC * EPITCH;
    uint32_t* Vh = El + KC * EPITCH;
    uint32_t* Vl = Vh + KC * BPITCH;
    __shared__ float red[8];

    int tid  = threadIdx.x;
    int warp = tid >> 5, lane = tid & 31;
    int wm = (warp & 3) << 5;
    int wn = (warp >> 2) << 5;
    int g  = lane >> 2, tg = lane & 3;

    int bh = blockIdx.y; int bat = bh >> 3, hh = bh & 7;
    int j0 = blockIdx.x << 7;
    const float* e = g_e + (size_t)bh * SS * SS;
    const uint32_t* vh = g_qkvhi + 2 * (size_t)XN + (size_t)bh * SS * DEP;
    const uint32_t* vl = g_qkvlo + 2 * (size_t)XN + (size_t)bh * SS * DEP;
    float mx = o2f(g_maxbits[loff + bh]);

    int erow = tid >> 5, ecol = (tid & 31) << 2;
    int vrow = tid >> 4, vcol = (tid & 15) << 2;

    // prefetch chunk 0
    float4 re[4];
    uint4 rvh[2], rvl[2];
    #pragma unroll
    for (int i = 0; i < 4; i++)
        re[i] = *(const float4*)&e[(size_t)(erow + (i << 3)) * SS + j0 + ecol];
    #pragma unroll
    for (int i = 0; i < 2; i++) {
        size_t src = (size_t)(vrow + (i << 4)) * DEP + vcol;
        rvh[i] = *(const uint4*)&vh[src];
        rvl[i] = *(const uint4*)&vl[src];
    }

    float acc[2][4][4];
    #pragma unroll
    for (int i = 0; i < 2; i++)
        #pragma unroll
        for (int j = 0; j < 4; j++)
            #pragma unroll
            for (int r = 0; r < 4; r++) acc[i][j][r] = 0.0f;

    float lsum = 0.0f;

    for (int i0 = 0; i0 < SS; i0 += KC) {
        #pragma unroll
        for (int i = 0; i < 4; i++) {
            int r = erow + (i << 3);
            float4 le = re[i];
            le.x = __expf(le.x - mx); le.y = __expf(le.y - mx);
            le.z = __expf(le.z - mx); le.w = __expf(le.w - mx);
            lsum += (le.x + le.y) + (le.z + le.w);
            uint4 hi, lo;
            hi.x = f2tf(le.x); lo.x = f2tf(le.x - __uint_as_float(hi.x));
            hi.y = f2tf(le.y); lo.y = f2tf(le.y - __uint_as_float(hi.y));
            hi.z = f2tf(le.z); lo.z = f2tf(le.z - __uint_as_float(hi.z));
            hi.w = f2tf(le.w); lo.w = f2tf(le.w - __uint_as_float(hi.w));
            *(uint4*)&Eh[r * EPITCH + ecol] = hi;
            *(uint4*)&El[r * EPITCH + ecol] = lo;
        }
        #pragma unroll
        for (int i = 0; i < 2; i++) {
            int r = vrow + (i << 4);
            *(uint4*)&Vh[r * BPITCH + vcol] = rvh[i];
            *(uint4*)&Vl[r * BPITCH + vcol] = rvl[i];
        }
        __syncthreads();

        if (i0 + KC < SS) {
            int ib = i0 + KC;
            #pragma unroll
            for (int i = 0; i < 4; i++)
                re[i] = *(const float4*)&e[(size_t)(ib + erow + (i << 3)) * SS + j0 + ecol];
            #pragma unroll
            for (int i = 0; i < 2; i++) {
                size_t src = (size_t)(ib + vrow + (i << 4)) * DEP + vcol;
                rvh[i] = *(const uint4*)&vh[src];
                rvl[i] = *(const uint4*)&vl[src];
            }
        }

        #pragma unroll
        for (int kk = 0; kk < KC; kk += 8) {
            uint32_t ahi[2][4], alo[2][4], bhi[4][2], blo[4][2];
            #pragma unroll
            for (int mt = 0; mt < 2; mt++) {
                int r = wm + (mt << 4) + g;
                int o0 = (kk + tg) * EPITCH + r, o1 = (kk + tg + 4) * EPITCH + r;
                ahi[mt][0] = Eh[o0];     ahi[mt][1] = Eh[o0 + 8];
                ahi[mt][2] = Eh[o1];     ahi[mt][3] = Eh[o1 + 8];
                alo[mt][0] = El[o0];     alo[mt][1] = El[o0 + 8];
                alo[mt][2] = El[o1];     alo[mt][3] = El[o1 + 8];
            }
            #pragma unroll
            for (int nt = 0; nt < 4; nt++) {
                int cc = wn + (nt << 3) + g;
                int o0 = (kk + tg) * BPITCH + cc, o1 = (kk + tg + 4) * BPITCH + cc;
                bhi[nt][0] = Vh[o0]; bhi[nt][1] = Vh[o1];
                blo[nt][0] = Vl[o0]; blo[nt][1] = Vl[o1];
            }
            #pragma unroll
            for (int mt = 0; mt < 2; mt++)
                #pragma unroll
                for (int nt = 0; nt < 4; nt++) {
                    mma_tf32(acc[mt][nt], alo[mt], bhi[nt]);
                    mma_tf32(acc[mt][nt], ahi[mt], blo[nt]);
                    mma_tf32(acc[mt][nt], ahi[mt], bhi[nt]);
                }
        }
        __syncthreads();
    }

    #pragma unroll
    for (int o = 16; o; o >>= 1) lsum += __shfl_xor_sync(0xffffffffu, lsum, o);
    if (lane == 0) red[warp] = lsum;
    __syncthreads();
    if (tid == 0) {
        float s = 0.0f;
        #pragma unroll
        for (int w = 0; w < 8; w++) s += red[w];
        atomicAdd(&g_sum[loff + bh], s);
    }

    #pragma unroll
    for (int mt = 0; mt < 2; mt++) {
        #pragma unroll
        for (int nt = 0; nt < 4; nt++) {
            int d = wn + (nt << 3) + (tg << 1);
            #pragma unroll
            for (int half = 0; half < 2; half++) {
                int j = j0 + wm + (mt << 4) + g + half * 8;
                float2 o;
                o.x = acc[mt][nt][half * 2 + 0];
                o.y = acc[mt][nt][half * 2 + 1];
                *(float2*)&g_att[((size_t)bat * SS + j) * DD + hh * DEP + d] = o;
            }
        }
    }
}

// ---------------- LayerNorm over last dim (512) ----------------
__global__ __launch_bounds__(128) void ln_kernel(
    const float* __restrict__ in, const float* __restrict__ gam,
    const float* __restrict__ bet, float* __restrict__ out)
{
    __shared__ float red[4];
    __shared__ float bc;
    int row = blockIdx.x, t = threadIdx.x;
    const float* rp = in + (size_t)row * DD;
    float v0 = rp[t], v1 = rp[t + 128], v2 = rp[t + 256], v3 = rp[t + 384];
    float s = v0 + v1 + v2 + v3;
    #pragma unroll
    for (int o = 16; o; o >>= 1) s += __shfl_xor_sync(0xffffffffu, s, o);
    if ((t & 31) == 0) red[t >> 5] = s;
    __syncthreads();
    if (t == 0) bc = (red[0] + red[1] + red[2] + red[3]) * (1.0f / 512.0f);
    __syncthreads();
    float mean = bc;
    float d0 = v0 - mean, d1 = v1 - mean, d2 = v2 - mean, d3 = v3 - mean;
    float ss = d0 * d0 + d1 * d1 + d2 * d2 + d3 * d3;
    #pragma unroll
    for (int o = 16; o; o >>= 1) ss += __shfl_xor_sync(0xffffffffu, ss, o);
    __syncthreads();
    if ((t & 31) == 0) red[t >> 5] = ss;
    __syncthreads();
    if (t == 0) bc = (red[0] + red[1] + red[2] + red[3]) * (1.0f / 512.0f);
    __syncthreads();
    float inv = rsqrtf(bc + 1e-9f);
    float* op = out + (size_t)row * DD;
    op[t]       = gam[t]       * d0 * inv + bet[t];
    op[t + 128] = gam[t + 128] * d1 * inv + bet[t + 128];
    op[t + 256] = gam[t + 256] * d2 * inv + bet[t + 256];
    op[t + 384] = gam[t + 384] * d3 * inv + bet[t + 384];
}

// ---------------- final aw write: exp(logit - mx) * rc/Z (float4), last layer slice ----------------
__global__ __launch_bounds__(256) void awout_kernel(float4* __restrict__ out, int loff) {
    size_t i = (size_t)blockIdx.x * 256 + threadIdx.x;   // float4 units
    int bh = (int)(i >> 18);                              // 2^18 float4 per (b,h)
    float s = g_rowcount / g_sum[loff + bh];
    float mx = o2f(g_maxbits[loff + bh]);
    float4 v = ((const float4*)g_e)[i];
    v.x = __expf(v.x - mx) * s; v.y = __expf(v.y - mx) * s;
    v.z = __expf(v.z - mx) * s; v.w = __expf(v.w - mx) * s;
    out[i] = v;
}

// ---------------- launch ----------------
extern "C" void kernel_launch(void* const* d_in, const int* in_sizes, int n_in,
                              void* d_out, int out_size)
{
    const float* x_in  = (const float*)d_in[0];
    const float* mask  = (const float*)d_in[1];
    const int*   protok= (const int*)  d_in[2];
    const float* wq_w  = (const float*)d_in[3];
    const float* wq_b  = (const float*)d_in[4];
    const float* wk_w  = (const float*)d_in[5];
    const float* wk_b  = (const float*)d_in[6];
    const float* wv_w  = (const float*)d_in[7];
    const float* wv_b  = (const float*)d_in[8];
    const float* wo_w  = (const float*)d_in[9];
    const float* wo_b  = (const float*)d_in[10];
    const float* w1    = (const float*)d_in[11];
    const float* b1    = (const float*)d_in[12];
    const float* w2    = (const float*)d_in[13];
    const float* b2    = (const float*)d_in[14];
    const float* ln1g  = (const float*)d_in[15];
    const float* ln1b  = (const float*)d_in[16];
    const float* ln2g  = (const float*)d_in[17];
    const float* ln2b  = (const float*)d_in[18];

    float *px, *patt, *py, *po1, *ph, *pbqkv;
    uint32_t *pwqkv, *pwo, *pw1, *pw2;
    cudaGetSymbolAddress((void**)&px,    g_x);
    cudaGetSymbolAddress((void**)&patt,  g_att);
    cudaGetSymbolAddress((void**)&py,    g_y);
    cudaGetSymbolAddress((void**)&po1,   g_o1);
    cudaGetSymbolAddress((void**)&ph,    g_hbuf);
    cudaGetSymbolAddress((void**)&pwqkv, g_wqkv);
    cudaGetSymbolAddress((void**)&pwo,   g_wo_t);
    cudaGetSymbolAddress((void**)&pw1,   g_w1t);
    cudaGetSymbolAddress((void**)&pw2,   g_w2t);
    cudaGetSymbolAddress((void**)&pbqkv, g_bqkv);

    cudaFuncSetAttribute(logits_mma, cudaFuncAttributeMaxDynamicSharedMemorySize, LOGITS_SMEM);
    cudaFuncSetAttribute(attv_mma,   cudaFuncAttributeMaxDynamicSharedMemorySize, ATTV_SMEM);

    // one-time prep
    rowcount_kernel<<<1, 1024>>>(protok);
    pack_qkv_kernel<<<3072, 256>>>(wq_w, wk_w, wv_w, wq_b, wk_b, wv_b);
    cvtw_kernel<<<1024, 256>>>(wo_w, pwo, 512 * 512);
    cvtw_kernel<<<4096, 256>>>(w1,   pw1, 512 * 2048);
    cvtw_kernel<<<4096, 256>>>(w2,   pw2, 2048 * 512);
    copy4_kernel<<<XN / 4 / 256, 256>>>((float4*)px, (const float4*)x_in, XN / 4);

    for (int l = 0; l < NLAYERS; l++) {
        int loff = l * BB * HH;
        gemm_pf<<<dim3(24, 32), 256>>>(px, pwqkv, pbqkv, nullptr, nullptr, BB*SS, 1536, DD, 0, 2, 0);
        logits_mma<<<dim3(16, 8, 32), 256, LOGITS_SMEM>>>(mask, loff);
        attv_mma<<<dim3(8, 32), 256, ATTV_SMEM>>>(loff);
        gemm_pf<<<dim3(8, 32), 256>>>(patt, pwo, wo_b, px, py, BB*SS, DD, DD, 0, 3, loff);
        ln_kernel<<<BB*SS, 128>>>(py, ln1g, ln1b, po1);
        gemm_pf<<<dim3(32, 32), 256>>>(po1, pw1, b1, nullptr, ph, BB*SS, DFFN, DD, 1, 0, 0);
        gemm_pf<<<dim3(8, 32), 256>>>(ph, pw2, b2, po1, py, BB*SS, DD, DFFN, 0, 0, 0);
        ln_kernel<<<BB*SS, 128>>>(py, ln2g, ln2b, px);
    }

    if (out_size >= XN) {
        copy4_kernel<<<XN / 4 / 256, 256>>>((float4*)d_out, (const float4*)px, XN / 4);
    }
    if (out_size >= XN + AWN) {
        awout_kernel<<<AWN / 4 / 256, 256>>>((float4*)((float*)d_out + XN), (NLAYERS - 1) * BB * HH);
    }
}

// round 15
// speedup vs baseline: 1.1383x; 1.0424x over previous
#include <cuda_runtime.h>
#include <math.h>
#include <stdint.h>

#define BB      4
#define SS      1024
#define DD      512
#define HH      8
#define DEP     64
#define DFFN    2048
#define NLAYERS 4

#define XN  (BB*SS*DD)       /* 2097152  */
#define AWN (BB*HH*SS*SS)    /* 33554432 */

// ---------------- device scratch (no allocation allowed) ----------------
__device__ float    g_x   [XN];
__device__ uint32_t g_xt  [XN];            // tf32 copy of g_x
__device__ uint32_t g_qkvhi[3*XN];         // tf32 hi: q | k | v (head-split layout)
__device__ uint32_t g_qkvlo[3*XN];         // tf32 lo
__device__ float    g_att [XN];
__device__ float    g_y   [XN];
__device__ float    g_o1  [XN];
__device__ uint32_t g_o1t [XN];            // tf32 copy of o1
__device__ uint32_t g_ht  [BB*SS*DFFN];    // tf32 relu(h)
__device__ float    g_e   [AWN];           // logits (exp fused downstream)
__device__ int      g_maxbits[NLAYERS*BB*HH];
__device__ float    g_sum    [NLAYERS*BB*HH];
__device__ float    g_rowcount;
// tf32-packed weights (prepared once per launch)
__device__ uint32_t g_wqkv[512*1536];
__device__ uint32_t g_wo_t[512*512];
__device__ uint32_t g_w1t [512*2048];
__device__ uint32_t g_w2t [2048*512];
__device__ float    g_bqkv[1536];

// ---------------- helpers ----------------
__device__ __forceinline__ int f2o(float f) {
    int i = __float_as_int(f);
    return (i >= 0) ? i : (i ^ 0x7FFFFFFF);
}
__device__ __forceinline__ float o2f(int i) {
    return __int_as_float((i >= 0) ? i : (i ^ 0x7FFFFFFF));
}
__device__ __forceinline__ uint32_t f2tf(float f) {
    uint32_t u;
    asm("cvt.rna.tf32.f32 %0, %1;" : "=r"(u) : "f"(f));
    return u;
}
__device__ __forceinline__ void mma_tf32(float* c, const uint32_t* a, const uint32_t* b) {
    asm volatile(
        "mma.sync.aligned.m16n8k8.row.col.f32.tf32.tf32.f32 "
        "{%0,%1,%2,%3}, {%4,%5,%6,%7}, {%8,%9}, {%0,%1,%2,%3};\n"
        : "+f"(c[0]), "+f"(c[1]), "+f"(c[2]), "+f"(c[3])
        : "r"(a[0]), "r"(a[1]), "r"(a[2]), "r"(a[3]), "r"(b[0]), "r"(b[1]));
}

// ---------------- row_count + all-layer reduction init ----------------
__global__ void rowcount_kernel(const int* __restrict__ protok) {
    __shared__ int red[32];
    int t = threadIdx.x;
    int c = (protok[t] != 0) ? 1 : 0;
    #pragma unroll
    for (int o = 16; o; o >>= 1) c += __shfl_xor_sync(0xffffffffu, c, o);
    if ((t & 31) == 0) red[t >> 5] = c;
    __syncthreads();
    if (t < 32) {
        int v = red[t];
        #pragma unroll
        for (int o = 16; o; o >>= 1) v += __shfl_xor_sync(0xffffffffu, v, o);
        if (t == 0) g_rowcount = (float)v;
    }
    if (t < NLAYERS * BB * HH) { g_maxbits[t] = (int)0x80000000; g_sum[t] = 0.0f; }
}

__global__ void copy4_kernel(float4* __restrict__ dst, const float4* __restrict__ src, int n4) {
    int i = blockIdx.x * blockDim.x + threadIdx.x;
    if (i < n4) dst[i] = src[i];
}

// initial x: write fp32 + tf32 twin
__global__ void copyx_kernel(const float4* __restrict__ src) {
    int i = blockIdx.x * 256 + threadIdx.x;
    float4 v = src[i];
    ((float4*)g_x)[i] = v;
    uint4 t;
    t.x = f2tf(v.x); t.y = f2tf(v.y); t.z = f2tf(v.z); t.w = f2tf(v.w);
    ((uint4*)g_xt)[i] = t;
}

// ---------------- weight preparation (once per launch) ----------------
__global__ void pack_qkv_kernel(const float* __restrict__ wq, const float* __restrict__ wk,
                                const float* __restrict__ wv, const float* __restrict__ bq,
                                const float* __restrict__ bk, const float* __restrict__ bv) {
    int i = blockIdx.x * 256 + threadIdx.x;
    if (i < 512 * 1536) {
        int k = i / 1536, n = i % 1536;
        const float* w = (n < 512) ? wq : (n < 1024) ? wk : wv;
        g_wqkv[i] = f2tf(w[k * 512 + (n & 511)]);
    }
    if (i < 1536) {
        g_bqkv[i] = (i < 512) ? bq[i] : (i < 1024) ? bk[i - 512] : bv[i - 1024];
    }
}
__global__ void cvtw_kernel(const float* __restrict__ w, uint32_t* __restrict__ dst, int n) {
    int i = blockIdx.x * 256 + threadIdx.x;
    if (i < n) dst[i] = f2tf(w[i]);
}

#define KC 32
#define APITCH 36    /* (4g+tg)%32 conflict-free */
#define BPITCH 72    /* (8tg+g)%32 conflict-free */

// ================= gemm_pt: A already tf32 (uint32) — zero-ALU fill =================
// mode: 0 = fp32 C (+R); 2 = QKV head-split hi/lo; 4 = tf32-only out (Ct), with relu.
__global__ __launch_bounds__(256) void gemm_pt(
    const uint32_t* __restrict__ A, const uint32_t* __restrict__ W,
    const float* __restrict__ bias, const float* __restrict__ R,
    float* __restrict__ C, uint32_t* __restrict__ Ct,
    int M, int N, int K, int relu, int mode)
{
    __shared__ uint32_t As[128 * APITCH];
    __shared__ uint32_t Bs[KC * BPITCH];

    int tid  = threadIdx.x;
    int warp = tid >> 5, lane = tid & 31;
    int wm = (warp & 3) << 5;
    int wn = (warp >> 2) << 5;
    int g  = lane >> 2, tg = lane & 3;

    int m0 = blockIdx.y << 7, n0 = blockIdx.x << 6;

    int arow = tid >> 3, acol = (tid & 7) << 2;    // A: 128 x 32
    int brow = tid >> 4, bcol = (tid & 15) << 2;   // B: 32 x 64

    const uint32_t* Aptr = &A[(size_t)(m0 + arow) * K + acol];
    const uint32_t* Wptr = &W[(size_t)brow * N + n0 + bcol];

    uint4 ra[4];
    uint4 rb[2];

    #pragma unroll
    for (int i = 0; i < 4; i++) ra[i] = *(const uint4*)(Aptr + (size_t)(i << 5) * K);
    #pragma unroll
    for (int i = 0; i < 2; i++) rb[i] = *(const uint4*)(Wptr + (size_t)(i << 4) * N);

    float acc[2][4][4];
    #pragma unroll
    for (int i = 0; i < 2; i++)
        #pragma unroll
        for (int j = 0; j < 4; j++)
            #pragma unroll
            for (int r = 0; r < 4; r++) acc[i][j][r] = 0.0f;

    int nch = K / KC;
    for (int ch = 0; ch < nch; ch++) {
        #pragma unroll
        for (int i = 0; i < 4; i++)
            *(uint4*)&As[(arow + (i << 5)) * APITCH + acol] = ra[i];
        #pragma unroll
        for (int i = 0; i < 2; i++)
            *(uint4*)&Bs[(brow + (i << 4)) * BPITCH + bcol] = rb[i];
        __syncthreads();

        if (ch + 1 < nch) {
            int k0 = (ch + 1) * KC;
            #pragma unroll
            for (int i = 0; i < 4; i++) ra[i] = *(const uint4*)(Aptr + (size_t)(i << 5) * K + k0);
            #pragma unroll
            for (int i = 0; i < 2; i++) rb[i] = *(const uint4*)(Wptr + (size_t)((i << 4) + k0) * N);
        }

        #pragma unroll
        for (int kk = 0; kk < KC; kk += 8) {
            uint32_t af[2][4];
            #pragma unroll
            for (int mt = 0; mt < 2; mt++) {
                int r = wm + (mt << 4) + g;
                af[mt][0] = As[r * APITCH + kk + tg];
                af[mt][1] = As[(r + 8) * APITCH + kk + tg];
                af[mt][2] = As[r * APITCH + kk + tg + 4];
                af[mt][3] = As[(r + 8) * APITCH + kk + tg + 4];
            }
            uint32_t bf[4][2];
            #pragma unroll
            for (int nt = 0; nt < 4; nt++) {
                int cc = wn + (nt << 3) + g;
                bf[nt][0] = Bs[(kk + tg) * BPITCH + cc];
                bf[nt][1] = Bs[(kk + tg + 4) * BPITCH + cc];
            }
            #pragma unroll
            for (int mt = 0; mt < 2; mt++)
                #pragma unroll
                for (int nt = 0; nt < 4; nt++)
                    mma_tf32(acc[mt][nt], af[mt], bf[nt]);
        }
        __syncthreads();
    }

    #pragma unroll
    for (int mt = 0; mt < 2; mt++) {
        #pragma unroll
        for (int nt = 0; nt < 4; nt++) {
            int n = n0 + wn + (nt << 3) + (tg << 1);
            #pragma unroll
            for (int half = 0; half < 2; half++) {
                int mm = m0 + wm + (mt << 4) + g + half * 8;
                float2 v;
                v.x = acc[mt][nt][half * 2 + 0] + bias[n];
                v.y = acc[mt][nt][half * 2 + 1] + bias[n + 1];
                if (R) {
                    const float2 rr = *(const float2*)&R[(size_t)mm * N + n];
                    v.x += rr.x; v.y += rr.y;
                }
                if (relu) { v.x = fmaxf(v.x, 0.0f); v.y = fmaxf(v.y, 0.0f); }
                if (mode == 2) {
                    int which = n >> 9, nl = n & 511;
                    int bb = mm >> 10, s = mm & 1023, hh = nl >> 6, dd = nl & 63;
                    size_t off = (size_t)which * XN +
                                 (((size_t)(bb * HH + hh) << 10) | (size_t)s) * DEP + dd;
                    uint2 hi, lo;
                    hi.x = f2tf(v.x); lo.x = f2tf(v.x - __uint_as_float(hi.x));
                    hi.y = f2tf(v.y); lo.y = f2tf(v.y - __uint_as_float(hi.y));
                    *(uint2*)&g_qkvhi[off] = hi;
                    *(uint2*)&g_qkvlo[off] = lo;
                } else if (mode == 4) {
                    uint2 t;
                    t.x = f2tf(v.x); t.y = f2tf(v.y);
                    *(uint2*)&Ct[(size_t)mm * N + n] = t;
                } else {
                    *(float2*)&C[(size_t)mm * N + n] = v;
                }
            }
        }
    }
}

// ================= gemm_pf: fp32 A with per-(b,h) scaling (O-projection only) =================
__global__ __launch_bounds__(256) void gemm_pf(
    const float* __restrict__ A, const uint32_t* __restrict__ W,
    const float* __restrict__ bias, const float* __restrict__ R,
    float* __restrict__ C, int M, int N, int K, int loff)
{
    __shared__ uint32_t As[128 * APITCH];
    __shared__ uint32_t Bs[KC * BPITCH];

    int tid  = threadIdx.x;
    int warp = tid >> 5, lane = tid & 31;
    int wm = (warp & 3) << 5;
    int wn = (warp >> 2) << 5;
    int g  = lane >> 2, tg = lane & 3;

    int m0 = blockIdx.y << 7, n0 = blockIdx.x << 6;

    int arow = tid >> 3, acol = (tid & 7) << 2;
    int brow = tid >> 4, bcol = (tid & 15) << 2;

    const float* Aptr = &A[(size_t)(m0 + arow) * K + acol];
    const uint32_t* Wptr = &W[(size_t)brow * N + n0 + bcol];

    float sc[8];
    {
        float rc = g_rowcount;
        int b = (m0 + arow) >> 10;
        #pragma unroll
        for (int h = 0; h < 8; h++) sc[h] = rc / g_sum[loff + b * 8 + h];
    }

    float4 ra[4];
    uint4  rb[2];

    #pragma unroll
    for (int i = 0; i < 4; i++) ra[i] = *(const float4*)(Aptr + (size_t)(i << 5) * K);
    #pragma unroll
    for (int i = 0; i < 2; i++) rb[i] = *(const uint4*)(Wptr + (size_t)(i << 4) * N);

    float acc[2][4][4];
    #pragma unroll
    for (int i = 0; i < 2; i++)
        #pragma unroll
        for (int j = 0; j < 4; j++)
            #pragma unroll
            for (int r = 0; r < 4; r++) acc[i][j][r] = 0.0f;

    int nch = K / KC;
    for (int ch = 0; ch < nch; ch++) {
        float s = sc[(ch * KC + acol) >> 6];
        #pragma unroll
        for (int i = 0; i < 4; i++) {
            uint32_t* p = &As[(arow + (i << 5)) * APITCH + acol];
            p[0] = f2tf(ra[i].x * s); p[1] = f2tf(ra[i].y * s);
            p[2] = f2tf(ra[i].z * s); p[3] = f2tf(ra[i].w * s);
        }
        #pragma unroll
        for (int i = 0; i < 2; i++)
            *(uint4*)&Bs[(brow + (i << 4)) * BPITCH + bcol] = rb[i];
        __syncthreads();

        if (ch + 1 < nch) {
            int k0 = (ch + 1) * KC;
            #pragma unroll
            for (int i = 0; i < 4; i++) ra[i] = *(const float4*)(Aptr + (size_t)(i << 5) * K + k0);
            #pragma unroll
            for (int i = 0; i < 2; i++) rb[i] = *(const uint4*)(Wptr + (size_t)((i << 4) + k0) * N);
        }

        #pragma unroll
        for (int kk = 0; kk < KC; kk += 8) {
            uint32_t af[2][4];
            #pragma unroll
            for (int mt = 0; mt < 2; mt++) {
                int r = wm + (mt << 4) + g;
                af[mt][0] = As[r * APITCH + kk + tg];
                af[mt][1] = As[(r + 8) * APITCH + kk + tg];
                af[mt][2] = As[r * APITCH + kk + tg + 4];
                af[mt][3] = As[(r + 8) * APITCH + kk + tg + 4];
            }
            uint32_t bf[4][2];
            #pragma unroll
            for (int nt = 0; nt < 4; nt++) {
                int cc = wn + (nt << 3) + g;
                bf[nt][0] = Bs[(kk + tg) * BPITCH + cc];
                bf[nt][1] = Bs[(kk + tg + 4) * BPITCH + cc];
            }
            #pragma unroll
            for (int mt = 0; mt < 2; mt++)
                #pragma unroll
                for (int nt = 0; nt < 4; nt++)
                    mma_tf32(acc[mt][nt], af[mt], bf[nt]);
        }
        __syncthreads();
    }

    #pragma unroll
    for (int mt = 0; mt < 2; mt++) {
        #pragma unroll
        for (int nt = 0; nt < 4; nt++) {
            int n = n0 + wn + (nt << 3) + (tg << 1);
            #pragma unroll
            for (int half = 0; half < 2; half++) {
                int mm = m0 + wm + (mt << 4) + g + half * 8;
                float2 v;
                v.x = acc[mt][nt][half * 2 + 0] + bias[n];
                v.y = acc[mt][nt][half * 2 + 1] + bias[n + 1];
                const float2 rr = *(const float2*)&R[(size_t)mm * N + n];
                v.x += rr.x; v.y += rr.y;
                *(float2*)&C[(size_t)mm * N + n] = v;
            }
        }
    }
}

// ========== logits (tf32x3, pre-split operands): (Q K^T + mask*-1e9)/8, fused max ==========
// mask[b,i,j] == mask[b,0,j] (broadcast of pad over i) -> read row 0 only.
#define LOGITS_SMEM ((128*APITCH*2 + 64*APITCH*2) * 4)
__global__ __launch_bounds__(256) void logits_mma(const float* __restrict__ mask, int loff) {
    extern __shared__ uint32_t dsm[];
    uint32_t* Qh = dsm;
    uint32_t* Ql = Qh + 128 * APITCH;
    uint32_t* Kh = Ql + 128 * APITCH;
    uint32_t* Kl = Kh + 64 * APITCH;
    __shared__ float red[8];

    int tid  = threadIdx.x;
    int warp = tid >> 5, lane = tid & 31;
    int wm = (warp & 3) << 5;
    int wn = (warp >> 2) << 5;
    int g  = lane >> 2, tg = lane & 3;

    int bh = blockIdx.z; int bi = bh >> 3;
    int i0 = blockIdx.y << 7, j0 = blockIdx.x << 6;
    const uint32_t* qh = g_qkvhi + (size_t)bh * SS * DEP;
    const uint32_t* ql = g_qkvlo + (size_t)bh * SS * DEP;
    const uint32_t* kh = g_qkvhi + XN + (size_t)bh * SS * DEP;
    const uint32_t* kl = g_qkvlo + XN + (size_t)bh * SS * DEP;

    int arow = tid >> 3, acol = (tid & 7) << 2;

    float acc[2][4][4];
    #pragma unroll
    for (int i = 0; i < 2; i++)
        #pragma unroll
        for (int j = 0; j < 4; j++)
            #pragma unroll
            for (int r = 0; r < 4; r++) acc[i][j][r] = 0.0f;

    for (int k0 = 0; k0 < DEP; k0 += KC) {
        #pragma unroll
        for (int i = 0; i < 4; i++) {
            int r = arow + (i << 5);
            size_t src = (size_t)(i0 + r) * DEP + k0 + acol;
            *(uint4*)&Qh[r * APITCH + acol] = *(const uint4*)&qh[src];
            *(uint4*)&Ql[r * APITCH + acol] = *(const uint4*)&ql[src];
        }
        #pragma unroll
        for (int i = 0; i < 2; i++) {
            int r = arow + (i << 5);
            size_t src = (size_t)(j0 + r) * DEP + k0 + acol;
            *(uint4*)&Kh[r * APITCH + acol] = *(const uint4*)&kh[src];
            *(uint4*)&Kl[r * APITCH + acol] = *(const uint4*)&kl[src];
        }
        __syncthreads();

        #pragma unroll
        for (int kk = 0; kk < KC; kk += 8) {
            uint32_t ahi[2][4], alo[2][4], bhi[4][2], blo[4][2];
            #pragma unroll
            for (int mt = 0; mt < 2; mt++) {
                int r = wm + (mt << 4) + g;
                int o0 = r * APITCH + kk + tg, o1 = (r + 8) * APITCH + kk + tg;
                ahi[mt][0] = Qh[o0];     ahi[mt][1] = Qh[o1];
                ahi[mt][2] = Qh[o0 + 4]; ahi[mt][3] = Qh[o1 + 4];
                alo[mt][0] = Ql[o0];     alo[mt][1] = Ql[o1];
                alo[mt][2] = Ql[o0 + 4]; alo[mt][3] = Ql[o1 + 4];
            }
            #pragma unroll
            for (int nt = 0; nt < 4; nt++) {
                int cc = wn + (nt << 3) + g;
                int o0 = cc * APITCH + kk + tg;
                bhi[nt][0] = Kh[o0]; bhi[nt][1] = Kh[o0 + 4];
                blo[nt][0] = Kl[o0]; blo[nt][1] = Kl[o0 + 4];
            }
            #pragma unroll
            for (int mt = 0; mt < 2; mt++)
                #pragma unroll
                for (int nt = 0; nt < 4; nt++) {
                    mma_tf32(acc[mt][nt], alo[mt], bhi[nt]);
                    mma_tf32(acc[mt][nt], ahi[mt], blo[nt]);
                    mma_tf32(acc[mt][nt], ahi[mt], bhi[nt]);
                }
        }
        __syncthreads();
    }

    float* out = g_e + (size_t)bh * SS * SS;
    float lmax = -INFINITY;
    #pragma unroll
    for (int nt = 0; nt < 4; nt++) {
        int j = j0 + wn + (nt << 3) + (tg << 1);
        const float2 mk = *(const float2*)&mask[(size_t)bi * SS * SS + j];
        #pragma unroll
        for (int mt = 0; mt < 2; mt++) {
            #pragma unroll
            for (int half = 0; half < 2; half++) {
                int i = i0 + wm + (mt << 4) + g + half * 8;
                float2 v;
                v.x = (acc[mt][nt][half * 2 + 0] + mk.x * (-1e9f)) * 0.125f;
                v.y = (acc[mt][nt][half * 2 + 1] + mk.y * (-1e9f)) * 0.125f;
                *(float2*)&out[(size_t)i * SS + j] = v;
                lmax = fmaxf(lmax, fmaxf(v.x, v.y));
            }
        }
    }
    #pragma unroll
    for (int o = 16; o; o >>= 1) lmax = fmaxf(lmax, __shfl_xor_sync(0xffffffffu, lmax, o));
    if (lane == 0) red[warp] = lmax;
    __syncthreads();
    if (tid == 0) {
        float m = red[0];
        #pragma unroll
        for (int w = 1; w < 8; w++) m = fmaxf(m, red[w]);
        atomicMax(&g_maxbits[loff + bh], f2o(m));
    }
}

// ========== attv (tf32x3): exp fused + split at fill; V pre-split; reg-prefetch ==========
#define EPITCH 136
#define ATTV_SMEM ((KC*EPITCH*2 + KC*BPITCH*2) * 4)
__global__ __launch_bounds__(256) void attv_mma(int loff) {
    extern __shared__ uint32_t dsm[];
    uint32_t* Eh = dsm;
    uint32_t* El = Eh + KC * EPITCH;
    uint32_t* Vh = El + KC * EPITCH;
    uint32_t* Vl = Vh + KC * BPITCH;
    __shared__ float red[8];

    int tid  = threadIdx.x;
    int warp = tid >> 5, lane = tid & 31;
    int wm = (warp & 3) << 5;
    int wn = (warp >> 2) << 5;
    int g  = lane >> 2, tg = lane & 3;

    int bh = blockIdx.y; int bat = bh >> 3, hh = bh & 7;
    int j0 = blockIdx.x << 7;
    const float* e = g_e + (size_t)bh * SS * SS;
    const uint32_t* vh = g_qkvhi + 2 * (size_t)XN + (size_t)bh * SS * DEP;
    const uint32_t* vl = g_qkvlo + 2 * (size_t)XN + (size_t)bh * SS * DEP;
    float mx = o2f(g_maxbits[loff + bh]);

    int erow = tid >> 5, ecol = (tid & 31) << 2;
    int vrow = tid >> 4, vcol = (tid & 15) << 2;

    // prefetch chunk 0
    float4 re[4];
    uint4 rvh[2], rvl[2];
    #pragma unroll
    for (int i = 0; i < 4; i++)
        re[i] = *(const float4*)&e[(size_t)(erow + (i << 3)) * SS + j0 + ecol];
    #pragma unroll
    for (int i = 0; i < 2; i++) {
        size_t src = (size_t)(vrow + (i << 4)) * DEP + vcol;
        rvh[i] = *(const uint4*)&vh[src];
        rvl[i] = *(const uint4*)&vl[src];
    }

    float acc[2][4][4];
    #pragma unroll
    for (int i = 0; i < 2; i++)
        #pragma unroll
        for (int j = 0; j < 4; j++)
            #pragma unroll
            for (int r = 0; r < 4; r++) acc[i][j][r] = 0.0f;

    float lsum = 0.0f;

    for (int i0 = 0; i0 < SS; i0 += KC) {
        #pragma unroll
        for (int i = 0; i < 4; i++) {
            int r = erow + (i << 3);
            float4 le = re[i];
            le.x = __expf(le.x - mx); le.y = __expf(le.y - mx);
            le.z = __expf(le.z - mx); le.w = __expf(le.w - mx);
            lsum += (le.x + le.y) + (le.z + le.w);
            uint4 hi, lo;
            hi.x = f2tf(le.x); lo.x = f2tf(le.x - __uint_as_float(hi.x));
            hi.y = f2tf(le.y); lo.y = f2tf(le.y - __uint_as_float(hi.y));
            hi.z = f2tf(le.z); lo.z = f2tf(le.z - __uint_as_float(hi.z));
            hi.w = f2tf(le.w); lo.w = f2tf(le.w - __uint_as_float(hi.w));
            *(uint4*)&Eh[r * EPITCH + ecol] = hi;
            *(uint4*)&El[r * EPITCH + ecol] = lo;
        }
        #pragma unroll
        for (int i = 0; i < 2; i++) {
            int r = vrow + (i << 4);
            *(uint4*)&Vh[r * BPITCH + vcol] = rvh[i];
            *(uint4*)&Vl[r * BPITCH + vcol] = rvl[i];
        }
        __syncthreads();

        if (i0 + KC < SS) {
            int ib = i0 + KC;
            #pragma unroll
            for (int i = 0; i < 4; i++)
                re[i] = *(const float4*)&e[(size_t)(ib + erow + (i << 3)) * SS + j0 + ecol];
            #pragma unroll
            for (int i = 0; i < 2; i++) {
                size_t src = (size_t)(ib + vrow + (i << 4)) * DEP + vcol;
                rvh[i] = *(const uint4*)&vh[src];
                rvl[i] = *(const uint4*)&vl[src];
            }
        }

        #pragma unroll
        for (int kk = 0; kk < KC; kk += 8) {
            uint32_t ahi[2][4], alo[2][4], bhi[4][2], blo[4][2];
            #pragma unroll
            for (int mt = 0; mt < 2; mt++) {
                int r = wm + (mt << 4) + g;
                int o0 = (kk + tg) * EPITCH + r, o1 = (kk + tg + 4) * EPITCH + r;
                ahi[mt][0] = Eh[o0];     ahi[mt][1] = Eh[o0 + 8];
                ahi[mt][2] = Eh[o1];     ahi[mt][3] = Eh[o1 + 8];
                alo[mt][0] = El[o0];     alo[mt][1] = El[o0 + 8];
                alo[mt][2] = El[o1];     alo[mt][3] = El[o1 + 8];
            }
            #pragma unroll
            for (int nt = 0; nt < 4; nt++) {
                int cc = wn + (nt << 3) + g;
                int o0 = (kk + tg) * BPITCH + cc, o1 = (kk + tg + 4) * BPITCH + cc;
                bhi[nt][0] = Vh[o0]; bhi[nt][1] = Vh[o1];
                blo[nt][0] = Vl[o0]; blo[nt][1] = Vl[o1];
            }
            #pragma unroll
            for (int mt = 0; mt < 2; mt++)
                #pragma unroll
                for (int nt = 0; nt < 4; nt++) {
                    mma_tf32(acc[mt][nt], alo[mt], bhi[nt]);
                    mma_tf32(acc[mt][nt], ahi[mt], blo[nt]);
                    mma_tf32(acc[mt][nt], ahi[mt], bhi[nt]);
                }
        }
        __syncthreads();
    }

    #pragma unroll
    for (int o = 16; o; o >>= 1) lsum += __shfl_xor_sync(0xffffffffu, lsum, o);
    if (lane == 0) red[warp] = lsum;
    __syncthreads();
    if (tid == 0) {
        float s = 0.0f;
        #pragma unroll
        for (int w = 0; w < 8; w++) s += red[w];
        atomicAdd(&g_sum[loff + bh], s);
    }

    #pragma unroll
    for (int mt = 0; mt < 2; mt++) {
        #pragma unroll
        for (int nt = 0; nt < 4; nt++) {
            int d = wn + (nt << 3) + (tg << 1);
            #pragma unroll
            for (int half = 0; half < 2; half++) {
                int j = j0 + wm + (mt << 4) + g + half * 8;
                float2 o;
                o.x = acc[mt][nt][half * 2 + 0];
                o.y = acc[mt][nt][half * 2 + 1];
                *(float2*)&g_att[((size_t)bat * SS + j) * DD + hh * DEP + d] = o;
            }
        }
    }
}

// ---------------- LayerNorm over last dim (512); writes fp32 + tf32 twin ----------------
__global__ __launch_bounds__(128) void ln_kernel(
    const float* __restrict__ in, const float* __restrict__ gam,
    const float* __restrict__ bet, float* __restrict__ out, uint32_t* __restrict__ tout)
{
    __shared__ float red[4];
    __shared__ float bc;
    int row = blockIdx.x, t = threadIdx.x;
    const float* rp = in + (size_t)row * DD;
    float v0 = rp[t], v1 = rp[t + 128], v2 = rp[t + 256], v3 = rp[t + 384];
    float s = v0 + v1 + v2 + v3;
    #pragma unroll
    for (int o = 16; o; o >>= 1) s += __shfl_xor_sync(0xffffffffu, s, o);
    if ((t & 31) == 0) red[t >> 5] = s;
    __syncthreads();
    if (t == 0) bc = (red[0] + red[1] + red[2] + red[3]) * (1.0f / 512.0f);
    __syncthreads();
    float mean = bc;
    float d0 = v0 - mean, d1 = v1 - mean, d2 = v2 - mean, d3 = v3 - mean;
    float ss = d0 * d0 + d1 * d1 + d2 * d2 + d3 * d3;
    #pragma unroll
    for (int o = 16; o; o >>= 1) ss += __shfl_xor_sync(0xffffffffu, ss, o);
    __syncthreads();
    if ((t & 31) == 0) red[t >> 5] = ss;
    __syncthreads();
    if (t == 0) bc = (red[0] + red[1] + red[2] + red[3]) * (1.0f / 512.0f);
    __syncthreads();
    float inv = rsqrtf(bc + 1e-9f);
    float* op = out + (size_t)row * DD;
    uint32_t* tp = tout + (size_t)row * DD;
    float r0 = gam[t]       * d0 * inv + bet[t];
    float r1 = gam[t + 128] * d1 * inv + bet[t + 128];
    float r2 = gam[t + 256] * d2 * inv + bet[t + 256];
    float r3 = gam[t + 384] * d3 * inv + bet[t + 384];
    op[t] = r0; op[t + 128] = r1; op[t + 256] = r2; op[t + 384] = r3;
    tp[t] = f2tf(r0); tp[t + 128] = f2tf(r1); tp[t + 256] = f2tf(r2); tp[t + 384] = f2tf(r3);
}

// ---------------- final aw write: exp(logit - mx) * rc/Z (float4), last layer slice ----------------
__global__ __launch_bounds__(256) void awout_kernel(float4* __restrict__ out, int loff) {
    size_t i = (size_t)blockIdx.x * 256 + threadIdx.x;   // float4 units
    int bh = (int)(i >> 18);                              // 2^18 float4 per (b,h)
    float s = g_rowcount / g_sum[loff + bh];
    float mx = o2f(g_maxbits[loff + bh]);
    float4 v = ((const float4*)g_e)[i];
    v.x = __expf(v.x - mx) * s; v.y = __expf(v.y - mx) * s;
    v.z = __expf(v.z - mx) * s; v.w = __expf(v.w - mx) * s;
    out[i] = v;
}

// ---------------- launch ----------------
extern "C" void kernel_launch(void* const* d_in, const int* in_sizes, int n_in,
                              void* d_out, int out_size)
{
    const float* x_in  = (const float*)d_in[0];
    const float* mask  = (const float*)d_in[1];
    const int*   protok= (const int*)  d_in[2];
    const float* wq_w  = (const float*)d_in[3];
    const float* wq_b  = (const float*)d_in[4];
    const float* wk_w  = (const float*)d_in[5];
    const float* wk_b  = (const float*)d_in[6];
    const float* wv_w  = (const float*)d_in[7];
    const float* wv_b  = (const float*)d_in[8];
    const float* wo_w  = (const float*)d_in[9];
    const float* wo_b  = (const float*)d_in[10];
    const float* w1    = (const float*)d_in[11];
    const float* b1    = (const float*)d_in[12];
    const float* w2    = (const float*)d_in[13];
    const float* b2    = (const float*)d_in[14];
    const float* ln1g  = (const float*)d_in[15];
    const float* ln1b  = (const float*)d_in[16];
    const float* ln2g  = (const float*)d_in[17];
    const float* ln2b  = (const float*)d_in[18];

    float *px, *patt, *py, *po1;
    uint32_t *pxt, *po1t, *pht;
    float *pbqkv;
    uint32_t *pwqkv, *pwo, *pw1, *pw2;
    cudaGetSymbolAddress((void**)&px,    g_x);
    cudaGetSymbolAddress((void**)&pxt,   g_xt);
    cudaGetSymbolAddress((void**)&patt,  g_att);
    cudaGetSymbolAddress((void**)&py,    g_y);
    cudaGetSymbolAddress((void**)&po1,   g_o1);
    cudaGetSymbolAddress((void**)&po1t,  g_o1t);
    cudaGetSymbolAddress((void**)&pht,   g_ht);
    cudaGetSymbolAddress((void**)&pwqkv, g_wqkv);
    cudaGetSymbolAddress((void**)&pwo,   g_wo_t);
    cudaGetSymbolAddress((void**)&pw1,   g_w1t);
    cudaGetSymbolAddress((void**)&pw2,   g_w2t);
    cudaGetSymbolAddress((void**)&pbqkv, g_bqkv);

    cudaFuncSetAttribute(logits_mma, cudaFuncAttributeMaxDynamicSharedMemorySize, LOGITS_SMEM);
    cudaFuncSetAttribute(attv_mma,   cudaFuncAttributeMaxDynamicSharedMemorySize, ATTV_SMEM);

    // one-time prep
    rowcount_kernel<<<1, 1024>>>(protok);
    pack_qkv_kernel<<<3072, 256>>>(wq_w, wk_w, wv_w, wq_b, wk_b, wv_b);
    cvtw_kernel<<<1024, 256>>>(wo_w, pwo, 512 * 512);
    cvtw_kernel<<<4096, 256>>>(w1,   pw1, 512 * 2048);
    cvtw_kernel<<<4096, 256>>>(w2,   pw2, 2048 * 512);
    copyx_kernel<<<XN / 4 / 256, 256>>>((const float4*)x_in);

    for (int l = 0; l < NLAYERS; l++) {
        int loff = l * BB * HH;
        gemm_pt<<<dim3(24, 32), 256>>>(pxt, pwqkv, pbqkv, nullptr, nullptr, nullptr,
                                       BB*SS, 1536, DD, 0, 2);
        logits_mma<<<dim3(16, 8, 32), 256, LOGITS_SMEM>>>(mask, loff);
        attv_mma<<<dim3(8, 32), 256, ATTV_SMEM>>>(loff);
        gemm_pf<<<dim3(8, 32), 256>>>(patt, pwo, wo_b, px, py, BB*SS, DD, DD, loff);
        ln_kernel<<<BB*SS, 128>>>(py, ln1g, ln1b, po1, po1t);
        gemm_pt<<<dim3(32, 32), 256>>>(po1t, pw1, b1, nullptr, nullptr, pht,
                                       BB*SS, DFFN, DD, 1, 4);
        gemm_pt<<<dim3(8, 32), 256>>>(pht, pw2, b2, po1, py, nullptr,
                                      BB*SS, DD, DFFN, 0, 0);
        ln_kernel<<<BB*SS, 128>>>(py, ln2g, ln2b, px, pxt);
    }

    if (out_size >= XN) {
        copy4_kernel<<<XN / 4 / 256, 256>>>((float4*)d_out, (const float4*)px, XN / 4);
    }
    if (out_size >= XN + AWN) {
        awout_kernel<<<AWN / 4 / 256, 256>>>((float4*)((float*)d_out + XN), (NLAYERS - 1) * BB * HH);
    }
}

// round 16
// speedup vs baseline: 1.1993x; 1.0535x over previous
#include <cuda_runtime.h>
#include <math.h>
#include <stdint.h>

#define BB      4
#define SS      1024
#define DD      512
#define HH      8
#define DEP     64
#define DFFN    2048
#define NLAYERS 4

#define XN  (BB*SS*DD)       /* 2097152  */
#define AWN (BB*HH*SS*SS)    /* 33554432 */

// ---------------- device scratch (no allocation allowed) ----------------
__device__ float    g_x   [XN];
__device__ uint32_t g_xt  [XN];            // tf32 copy of g_x
__device__ uint32_t g_qkvhi[3*XN];         // tf32 hi: q | k | v (head-split layout)
__device__ uint32_t g_qkvlo[2*XN];         // tf32 lo: q | k only (V consumed as hi-only)
__device__ float    g_att [XN];
__device__ float    g_y   [XN];
__device__ float    g_o1  [XN];
__device__ uint32_t g_o1t [XN];            // tf32 copy of o1
__device__ uint32_t g_ht  [BB*SS*DFFN];    // tf32 relu(h)
__device__ float    g_e   [AWN];           // logits (exp fused downstream)
__device__ int      g_maxbits[NLAYERS*BB*HH];
__device__ float    g_sum    [NLAYERS*BB*HH];
__device__ float    g_rowcount;
// tf32-packed weights (prepared once per launch)
__device__ uint32_t g_wqkv[512*1536];
__device__ uint32_t g_wo_t[512*512];
__device__ uint32_t g_w1t [512*2048];
__device__ uint32_t g_w2t [2048*512];
__device__ float    g_bqkv[1536];

// ---------------- helpers ----------------
__device__ __forceinline__ int f2o(float f) {
    int i = __float_as_int(f);
    return (i >= 0) ? i : (i ^ 0x7FFFFFFF);
}
__device__ __forceinline__ float o2f(int i) {
    return __int_as_float((i >= 0) ? i : (i ^ 0x7FFFFFFF));
}
__device__ __forceinline__ uint32_t f2tf(float f) {
    uint32_t u;
    asm("cvt.rna.tf32.f32 %0, %1;" : "=r"(u) : "f"(f));
    return u;
}
__device__ __forceinline__ void mma_tf32(float* c, const uint32_t* a, const uint32_t* b) {
    asm volatile(
        "mma.sync.aligned.m16n8k8.row.col.f32.tf32.tf32.f32 "
        "{%0,%1,%2,%3}, {%4,%5,%6,%7}, {%8,%9}, {%0,%1,%2,%3};\n"
        : "+f"(c[0]), "+f"(c[1]), "+f"(c[2]), "+f"(c[3])
        : "r"(a[0]), "r"(a[1]), "r"(a[2]), "r"(a[3]), "r"(b[0]), "r"(b[1]));
}

// ---------------- row_count + all-layer reduction init ----------------
__global__ void rowcount_kernel(const int* __restrict__ protok) {
    __shared__ int red[32];
    int t = threadIdx.x;
    int c = (protok[t] != 0) ? 1 : 0;
    #pragma unroll
    for (int o = 16; o; o >>= 1) c += __shfl_xor_sync(0xffffffffu, c, o);
    if ((t & 31) == 0) red[t >> 5] = c;
    __syncthreads();
    if (t < 32) {
        int v = red[t];
        #pragma unroll
        for (int o = 16; o; o >>= 1) v += __shfl_xor_sync(0xffffffffu, v, o);
        if (t == 0) g_rowcount = (float)v;
    }
    if (t < NLAYERS * BB * HH) { g_maxbits[t] = (int)0x80000000; g_sum[t] = 0.0f; }
}

__global__ void copy4_kernel(float4* __restrict__ dst, const float4* __restrict__ src, int n4) {
    int i = blockIdx.x * blockDim.x + threadIdx.x;
    if (i < n4) dst[i] = src[i];
}

// initial x: write fp32 + tf32 twin
__global__ void copyx_kernel(const float4* __restrict__ src) {
    int i = blockIdx.x * 256 + threadIdx.x;
    float4 v = src[i];
    ((float4*)g_x)[i] = v;
    uint4 t;
    t.x = f2tf(v.x); t.y = f2tf(v.y); t.z = f2tf(v.z); t.w = f2tf(v.w);
    ((uint4*)g_xt)[i] = t;
}

// ---------------- weight preparation (once per launch) ----------------
__global__ void pack_qkv_kernel(const float* __restrict__ wq, const float* __restrict__ wk,
                                const float* __restrict__ wv, const float* __restrict__ bq,
                                const float* __restrict__ bk, const float* __restrict__ bv) {
    int i = blockIdx.x * 256 + threadIdx.x;
    if (i < 512 * 1536) {
        int k = i / 1536, n = i % 1536;
        const float* w = (n < 512) ? wq : (n < 1024) ? wk : wv;
        g_wqkv[i] = f2tf(w[k * 512 + (n & 511)]);
    }
    if (i < 1536) {
        g_bqkv[i] = (i < 512) ? bq[i] : (i < 1024) ? bk[i - 512] : bv[i - 1024];
    }
}
__global__ void cvtw_kernel(const float* __restrict__ w, uint32_t* __restrict__ dst, int n) {
    int i = blockIdx.x * 256 + threadIdx.x;
    if (i < n) dst[i] = f2tf(w[i]);
}

#define KC 32
#define APITCH 36    /* (4g+tg)%32 conflict-free */
#define BPITCH 72    /* (8tg+g)%32 conflict-free */

// ================= gemm_pt: A already tf32 (uint32) — zero-ALU fill =================
// mode: 0 = fp32 C (+R); 2 = QKV head-split (Q,K: hi+lo; V: hi only); 4 = tf32-only out.
__global__ __launch_bounds__(256) void gemm_pt(
    const uint32_t* __restrict__ A, const uint32_t* __restrict__ W,
    const float* __restrict__ bias, const float* __restrict__ R,
    float* __restrict__ C, uint32_t* __restrict__ Ct,
    int M, int N, int K, int relu, int mode)
{
    __shared__ uint32_t As[128 * APITCH];
    __shared__ uint32_t Bs[KC * BPITCH];

    int tid  = threadIdx.x;
    int warp = tid >> 5, lane = tid & 31;
    int wm = (warp & 3) << 5;
    int wn = (warp >> 2) << 5;
    int g  = lane >> 2, tg = lane & 3;

    int m0 = blockIdx.y << 7, n0 = blockIdx.x << 6;

    int arow = tid >> 3, acol = (tid & 7) << 2;    // A: 128 x 32
    int brow = tid >> 4, bcol = (tid & 15) << 2;   // B: 32 x 64

    const uint32_t* Aptr = &A[(size_t)(m0 + arow) * K + acol];
    const uint32_t* Wptr = &W[(size_t)brow * N + n0 + bcol];

    uint4 ra[4];
    uint4 rb[2];

    #pragma unroll
    for (int i = 0; i < 4; i++) ra[i] = *(const uint4*)(Aptr + (size_t)(i << 5) * K);
    #pragma unroll
    for (int i = 0; i < 2; i++) rb[i] = *(const uint4*)(Wptr + (size_t)(i << 4) * N);

    float acc[2][4][4];
    #pragma unroll
    for (int i = 0; i < 2; i++)
        #pragma unroll
        for (int j = 0; j < 4; j++)
            #pragma unroll
            for (int r = 0; r < 4; r++) acc[i][j][r] = 0.0f;

    int nch = K / KC;
    for (int ch = 0; ch < nch; ch++) {
        #pragma unroll
        for (int i = 0; i < 4; i++)
            *(uint4*)&As[(arow + (i << 5)) * APITCH + acol] = ra[i];
        #pragma unroll
        for (int i = 0; i < 2; i++)
            *(uint4*)&Bs[(brow + (i << 4)) * BPITCH + bcol] = rb[i];
        __syncthreads();

        if (ch + 1 < nch) {
            int k0 = (ch + 1) * KC;
            #pragma unroll
            for (int i = 0; i < 4; i++) ra[i] = *(const uint4*)(Aptr + (size_t)(i << 5) * K + k0);
            #pragma unroll
            for (int i = 0; i < 2; i++) rb[i] = *(const uint4*)(Wptr + (size_t)((i << 4) + k0) * N);
        }

        #pragma unroll
        for (int kk = 0; kk < KC; kk += 8) {
            uint32_t af[2][4];
            #pragma unroll
            for (int mt = 0; mt < 2; mt++) {
                int r = wm + (mt << 4) + g;
                af[mt][0] = As[r * APITCH + kk + tg];
                af[mt][1] = As[(r + 8) * APITCH + kk + tg];
                af[mt][2] = As[r * APITCH + kk + tg + 4];
                af[mt][3] = As[(r + 8) * APITCH + kk + tg + 4];
            }
            uint32_t bf[4][2];
            #pragma unroll
            for (int nt = 0; nt < 4; nt++) {
                int cc = wn + (nt << 3) + g;
                bf[nt][0] = Bs[(kk + tg) * BPITCH + cc];
                bf[nt][1] = Bs[(kk + tg + 4) * BPITCH + cc];
            }
            #pragma unroll
            for (int mt = 0; mt < 2; mt++)
                #pragma unroll
                for (int nt = 0; nt < 4; nt++)
                    mma_tf32(acc[mt][nt], af[mt], bf[nt]);
        }
        __syncthreads();
    }

    #pragma unroll
    for (int mt = 0; mt < 2; mt++) {
        #pragma unroll
        for (int nt = 0; nt < 4; nt++) {
            int n = n0 + wn + (nt << 3) + (tg << 1);
            #pragma unroll
            for (int half = 0; half < 2; half++) {
                int mm = m0 + wm + (mt << 4) + g + half * 8;
                float2 v;
                v.x = acc[mt][nt][half * 2 + 0] + bias[n];
                v.y = acc[mt][nt][half * 2 + 1] + bias[n + 1];
                if (R) {
                    const float2 rr = *(const float2*)&R[(size_t)mm * N + n];
                    v.x += rr.x; v.y += rr.y;
                }
                if (relu) { v.x = fmaxf(v.x, 0.0f); v.y = fmaxf(v.y, 0.0f); }
                if (mode == 2) {
                    int which = n >> 9, nl = n & 511;
                    int bb = mm >> 10, s = mm & 1023, hh = nl >> 6, dd = nl & 63;
                    size_t off = (size_t)which * XN +
                                 (((size_t)(bb * HH + hh) << 10) | (size_t)s) * DEP + dd;
                    uint2 hi;
                    hi.x = f2tf(v.x); hi.y = f2tf(v.y);
                    *(uint2*)&g_qkvhi[off] = hi;
                    if (which < 2) {   // lo only for Q,K (attv consumes V as hi-only)
                        uint2 lo;
                        lo.x = f2tf(v.x - __uint_as_float(hi.x));
                        lo.y = f2tf(v.y - __uint_as_float(hi.y));
                        *(uint2*)&g_qkvlo[off] = lo;
                    }
                } else if (mode == 4) {
                    uint2 t;
                    t.x = f2tf(v.x); t.y = f2tf(v.y);
                    *(uint2*)&Ct[(size_t)mm * N + n] = t;
                } else {
                    *(float2*)&C[(size_t)mm * N + n] = v;
                }
            }
        }
    }
}

// ================= gemm_pf: fp32 A with per-(b,h) scaling (O-projection only) =================
__global__ __launch_bounds__(256) void gemm_pf(
    const float* __restrict__ A, const uint32_t* __restrict__ W,
    const float* __restrict__ bias, const float* __restrict__ R,
    float* __restrict__ C, int M, int N, int K, int loff)
{
    __shared__ uint32_t As[128 * APITCH];
    __shared__ uint32_t Bs[KC * BPITCH];

    int tid  = threadIdx.x;
    int warp = tid >> 5, lane = tid & 31;
    int wm = (warp & 3) << 5;
    int wn = (warp >> 2) << 5;
    int g  = lane >> 2, tg = lane & 3;

    int m0 = blockIdx.y << 7, n0 = blockIdx.x << 6;

    int arow = tid >> 3, acol = (tid & 7) << 2;
    int brow = tid >> 4, bcol = (tid & 15) << 2;

    const float* Aptr = &A[(size_t)(m0 + arow) * K + acol];
    const uint32_t* Wptr = &W[(size_t)brow * N + n0 + bcol];

    float sc[8];
    {
        float rc = g_rowcount;
        int b = (m0 + arow) >> 10;
        #pragma unroll
        for (int h = 0; h < 8; h++) sc[h] = rc / g_sum[loff + b * 8 + h];
    }

    float4 ra[4];
    uint4  rb[2];

    #pragma unroll
    for (int i = 0; i < 4; i++) ra[i] = *(const float4*)(Aptr + (size_t)(i << 5) * K);
    #pragma unroll
    for (int i = 0; i < 2; i++) rb[i] = *(const uint4*)(Wptr + (size_t)(i << 4) * N);

    float acc[2][4][4];
    #pragma unroll
    for (int i = 0; i < 2; i++)
        #pragma unroll
        for (int j = 0; j < 4; j++)
            #pragma unroll
            for (int r = 0; r < 4; r++) acc[i][j][r] = 0.0f;

    int nch = K / KC;
    for (int ch = 0; ch < nch; ch++) {
        float s = sc[(ch * KC + acol) >> 6];
        #pragma unroll
        for (int i = 0; i < 4; i++) {
            uint32_t* p = &As[(arow + (i << 5)) * APITCH + acol];
            p[0] = f2tf(ra[i].x * s); p[1] = f2tf(ra[i].y * s);
            p[2] = f2tf(ra[i].z * s); p[3] = f2tf(ra[i].w * s);
        }
        #pragma unroll
        for (int i = 0; i < 2; i++)
            *(uint4*)&Bs[(brow + (i << 4)) * BPITCH + bcol] = rb[i];
        __syncthreads();

        if (ch + 1 < nch) {
            int k0 = (ch + 1) * KC;
            #pragma unroll
            for (int i = 0; i < 4; i++) ra[i] = *(const float4*)(Aptr + (size_t)(i << 5) * K + k0);
            #pragma unroll
            for (int i = 0; i < 2; i++) rb[i] = *(const uint4*)(Wptr + (size_t)((i << 4) + k0) * N);
        }

        #pragma unroll
        for (int kk = 0; kk < KC; kk += 8) {
            uint32_t af[2][4];
            #pragma unroll
            for (int mt = 0; mt < 2; mt++) {
                int r = wm + (mt << 4) + g;
                af[mt][0] = As[r * APITCH + kk + tg];
                af[mt][1] = As[(r + 8) * APITCH + kk + tg];
                af[mt][2] = As[r * APITCH + kk + tg + 4];
                af[mt][3] = As[(r + 8) * APITCH + kk + tg + 4];
            }
            uint32_t bf[4][2];
            #pragma unroll
            for (int nt = 0; nt < 4; nt++) {
                int cc = wn + (nt << 3) + g;
                bf[nt][0] = Bs[(kk + tg) * BPITCH + cc];
                bf[nt][1] = Bs[(kk + tg + 4) * BPITCH + cc];
            }
            #pragma unroll
            for (int mt = 0; mt < 2; mt++)
                #pragma unroll
                for (int nt = 0; nt < 4; nt++)
                    mma_tf32(acc[mt][nt], af[mt], bf[nt]);
        }
        __syncthreads();
    }

    #pragma unroll
    for (int mt = 0; mt < 2; mt++) {
        #pragma unroll
        for (int nt = 0; nt < 4; nt++) {
            int n = n0 + wn + (nt << 3) + (tg << 1);
            #pragma unroll
            for (int half = 0; half < 2; half++) {
                int mm = m0 + wm + (mt << 4) + g + half * 8;
                float2 v;
                v.x = acc[mt][nt][half * 2 + 0] + bias[n];
                v.y = acc[mt][nt][half * 2 + 1] + bias[n + 1];
                const float2 rr = *(const float2*)&R[(size_t)mm * N + n];
                v.x += rr.x; v.y += rr.y;
                *(float2*)&C[(size_t)mm * N + n] = v;
            }
        }
    }
}

// ========== logits (tf32x3, pre-split operands): (Q K^T + mask*-1e9)/8, fused max ==========
// mask[b,i,j] == mask[b,0,j] (broadcast of pad over i) -> read row 0 only.
#define LOGITS_SMEM ((128*APITCH*2 + 64*APITCH*2) * 4)
__global__ __launch_bounds__(256) void logits_mma(const float* __restrict__ mask, int loff) {
    extern __shared__ uint32_t dsm[];
    uint32_t* Qh = dsm;
    uint32_t* Ql = Qh + 128 * APITCH;
    uint32_t* Kh = Ql + 128 * APITCH;
    uint32_t* Kl = Kh + 64 * APITCH;
    __shared__ float red[8];

    int tid  = threadIdx.x;
    int warp = tid >> 5, lane = tid & 31;
    int wm = (warp & 3) << 5;
    int wn = (warp >> 2) << 5;
    int g  = lane >> 2, tg = lane & 3;

    int bh = blockIdx.z; int bi = bh >> 3;
    int i0 = blockIdx.y << 7, j0 = blockIdx.x << 6;
    const uint32_t* qh = g_qkvhi + (size_t)bh * SS * DEP;
    const uint32_t* ql = g_qkvlo + (size_t)bh * SS * DEP;
    const uint32_t* kh = g_qkvhi + XN + (size_t)bh * SS * DEP;
    const uint32_t* kl = g_qkvlo + XN + (size_t)bh * SS * DEP;

    int arow = tid >> 3, acol = (tid & 7) << 2;

    float acc[2][4][4];
    #pragma unroll
    for (int i = 0; i < 2; i++)
        #pragma unroll
        for (int j = 0; j < 4; j++)
            #pragma unroll
            for (int r = 0; r < 4; r++) acc[i][j][r] = 0.0f;

    for (int k0 = 0; k0 < DEP; k0 += KC) {
        #pragma unroll
        for (int i = 0; i < 4; i++) {
            int r = arow + (i << 5);
            size_t src = (size_t)(i0 + r) * DEP + k0 + acol;
            *(uint4*)&Qh[r * APITCH + acol] = *(const uint4*)&qh[src];
            *(uint4*)&Ql[r * APITCH + acol] = *(const uint4*)&ql[src];
        }
        #pragma unroll
        for (int i = 0; i < 2; i++) {
            int r = arow + (i << 5);
            size_t src = (size_t)(j0 + r) * DEP + k0 + acol;
            *(uint4*)&Kh[r * APITCH + acol] = *(const uint4*)&kh[src];
            *(uint4*)&Kl[r * APITCH + acol] = *(const uint4*)&kl[src];
        }
        __syncthreads();

        #pragma unroll
        for (int kk = 0; kk < KC; kk += 8) {
            uint32_t ahi[2][4], alo[2][4], bhi[4][2], blo[4][2];
            #pragma unroll
            for (int mt = 0; mt < 2; mt++) {
                int r = wm + (mt << 4) + g;
                int o0 = r * APITCH + kk + tg, o1 = (r + 8) * APITCH + kk + tg;
                ahi[mt][0] = Qh[o0];     ahi[mt][1] = Qh[o1];
                ahi[mt][2] = Qh[o0 + 4]; ahi[mt][3] = Qh[o1 + 4];
                alo[mt][0] = Ql[o0];     alo[mt][1] = Ql[o1];
                alo[mt][2] = Ql[o0 + 4]; alo[mt][3] = Ql[o1 + 4];
            }
            #pragma unroll
            for (int nt = 0; nt < 4; nt++) {
                int cc = wn + (nt << 3) + g;
                int o0 = cc * APITCH + kk + tg;
                bhi[nt][0] = Kh[o0]; bhi[nt][1] = Kh[o0 + 4];
                blo[nt][0] = Kl[o0]; blo[nt][1] = Kl[o0 + 4];
            }
            #pragma unroll
            for (int mt = 0; mt < 2; mt++)
                #pragma unroll
                for (int nt = 0; nt < 4; nt++) {
                    mma_tf32(acc[mt][nt], alo[mt], bhi[nt]);
                    mma_tf32(acc[mt][nt], ahi[mt], blo[nt]);
                    mma_tf32(acc[mt][nt], ahi[mt], bhi[nt]);
                }
        }
        __syncthreads();
    }

    float* out = g_e + (size_t)bh * SS * SS;
    float lmax = -INFINITY;
    #pragma unroll
    for (int nt = 0; nt < 4; nt++) {
        int j = j0 + wn + (nt << 3) + (tg << 1);
        const float2 mk = *(const float2*)&mask[(size_t)bi * SS * SS + j];
        #pragma unroll
        for (int mt = 0; mt < 2; mt++) {
            #pragma unroll
            for (int half = 0; half < 2; half++) {
                int i = i0 + wm + (mt << 4) + g + half * 8;
                float2 v;
                v.x = (acc[mt][nt][half * 2 + 0] + mk.x * (-1e9f)) * 0.125f;
                v.y = (acc[mt][nt][half * 2 + 1] + mk.y * (-1e9f)) * 0.125f;
                *(float2*)&out[(size_t)i * SS + j] = v;
                lmax = fmaxf(lmax, fmaxf(v.x, v.y));
            }
        }
    }
    #pragma unroll
    for (int o = 16; o; o >>= 1) lmax = fmaxf(lmax, __shfl_xor_sync(0xffffffffu, lmax, o));
    if (lane == 0) red[warp] = lmax;
    __syncthreads();
    if (tid == 0) {
        float m = red[0];
        #pragma unroll
        for (int w = 1; w < 8; w++) m = fmaxf(m, red[w]);
        atomicMax(&g_maxbits[loff + bh], f2o(m));
    }
}

// ========== attv: O = E·V_hi (E split x2, V hi-only); exp fused; reg-prefetch ==========
#define EPITCH 136
#define ATTV_SMEM ((KC*EPITCH*2 + KC*BPITCH) * 4)
__global__ __launch_bounds__(256) void attv_mma(int loff) {
    extern __shared__ uint32_t dsm[];
    uint32_t* Eh = dsm;
    uint32_t* El = Eh + KC * EPITCH;
    uint32_t* Vh = El + KC * EPITCH;
    __shared__ float red[8];

    int tid  = threadIdx.x;
    int warp = tid >> 5, lane = tid & 31;
    int wm = (warp & 3) << 5;
    int wn = (warp >> 2) << 5;
    int g  = lane >> 2, tg = lane & 3;

    int bh = blockIdx.y; int bat = bh >> 3, hh = bh & 7;
    int j0 = blockIdx.x << 7;
    const float* e = g_e + (size_t)bh * SS * SS;
    const uint32_t* vh = g_qkvhi + 2 * (size_t)XN + (size_t)bh * SS * DEP;
    float mx = o2f(g_maxbits[loff + bh]);

    int erow = tid >> 5, ecol = (tid & 31) << 2;
    int vrow = tid >> 4, vcol = (tid & 15) << 2;

    // prefetch chunk 0
    float4 re[4];
    uint4 rvh[2];
    #pragma unroll
    for (int i = 0; i < 4; i++)
        re[i] = *(const float4*)&e[(size_t)(erow + (i << 3)) * SS + j0 + ecol];
    #pragma unroll
    for (int i = 0; i < 2; i++)
        rvh[i] = *(const uint4*)&vh[(size_t)(vrow + (i << 4)) * DEP + vcol];

    float acc[2][4][4];
    #pragma unroll
    for (int i = 0; i < 2; i++)
        #pragma unroll
        for (int j = 0; j < 4; j++)
            #pragma unroll
            for (int r = 0; r < 4; r++) acc[i][j][r] = 0.0f;

    float lsum = 0.0f;

    for (int i0 = 0; i0 < SS; i0 += KC) {
        #pragma unroll
        for (int i = 0; i < 4; i++) {
            int r = erow + (i << 3);
            float4 le = re[i];
            le.x = __expf(le.x - mx); le.y = __expf(le.y - mx);
            le.z = __expf(le.z - mx); le.w = __expf(le.w - mx);
            lsum += (le.x + le.y) + (le.z + le.w);
            uint4 hi, lo;
            hi.x = f2tf(le.x); lo.x = f2tf(le.x - __uint_as_float(hi.x));
            hi.y = f2tf(le.y); lo.y = f2tf(le.y - __uint_as_float(hi.y));
            hi.z = f2tf(le.z); lo.z = f2tf(le.z - __uint_as_float(hi.z));
            hi.w = f2tf(le.w); lo.w = f2tf(le.w - __uint_as_float(hi.w));
            *(uint4*)&Eh[r * EPITCH + ecol] = hi;
            *(uint4*)&El[r * EPITCH + ecol] = lo;
        }
        #pragma unroll
        for (int i = 0; i < 2; i++)
            *(uint4*)&Vh[(vrow + (i << 4)) * BPITCH + vcol] = rvh[i];
        __syncthreads();

        if (i0 + KC < SS) {
            int ib = i0 + KC;
            #pragma unroll
            for (int i = 0; i < 4; i++)
                re[i] = *(const float4*)&e[(size_t)(ib + erow + (i << 3)) * SS + j0 + ecol];
            #pragma unroll
            for (int i = 0; i < 2; i++)
                rvh[i] = *(const uint4*)&vh[(size_t)(ib + vrow + (i << 4)) * DEP + vcol];
        }

        #pragma unroll
        for (int kk = 0; kk < KC; kk += 8) {
            uint32_t ahi[2][4], alo[2][4], bhi[4][2];
            #pragma unroll
            for (int mt = 0; mt < 2; mt++) {
                int r = wm + (mt << 4) + g;
                int o0 = (kk + tg) * EPITCH + r, o1 = (kk + tg + 4) * EPITCH + r;
                ahi[mt][0] = Eh[o0];     ahi[mt][1] = Eh[o0 + 8];
                ahi[mt][2] = Eh[o1];     ahi[mt][3] = Eh[o1 + 8];
                alo[mt][0] = El[o0];     alo[mt][1] = El[o0 + 8];
                alo[mt][2] = El[o1];     alo[mt][3] = El[o1 + 8];
            }
            #pragma unroll
            for (int nt = 0; nt < 4; nt++) {
                int cc = wn + (nt << 3) + g;
                bhi[nt][0] = Vh[(kk + tg) * BPITCH + cc];
                bhi[nt][1] = Vh[(kk + tg + 4) * BPITCH + cc];
            }
            #pragma unroll
            for (int mt = 0; mt < 2; mt++)
                #pragma unroll
                for (int nt = 0; nt < 4; nt++) {
                    mma_tf32(acc[mt][nt], alo[mt], bhi[nt]);
                    mma_tf32(acc[mt][nt], ahi[mt], bhi[nt]);
                }
        }
        __syncthreads();
    }

    #pragma unroll
    for (int o = 16; o; o >>= 1) lsum += __shfl_xor_sync(0xffffffffu, lsum, o);
    if (lane == 0) red[warp] = lsum;
    __syncthreads();
    if (tid == 0) {
        float s = 0.0f;
        #pragma unroll
        for (int w = 0; w < 8; w++) s += red[w];
        atomicAdd(&g_sum[loff + bh], s);
    }

    #pragma unroll
    for (int mt = 0; mt < 2; mt++) {
        #pragma unroll
        for (int nt = 0; nt < 4; nt++) {
            int d = wn + (nt << 3) + (tg << 1);
            #pragma unroll
            for (int half = 0; half < 2; half++) {
                int j = j0 + wm + (mt << 4) + g + half * 8;
                float2 o;
                o.x = acc[mt][nt][half * 2 + 0];
                o.y = acc[mt][nt][half * 2 + 1];
                *(float2*)&g_att[((size_t)bat * SS + j) * DD + hh * DEP + d] = o;
            }
        }
    }
}

// ---------------- LayerNorm over last dim (512); writes fp32 + tf32 twin ----------------
__global__ __launch_bounds__(128) void ln_kernel(
    const float* __restrict__ in, const float* __restrict__ gam,
    const float* __restrict__ bet, float* __restrict__ out, uint32_t* __restrict__ tout)
{
    __shared__ float red[4];
    __shared__ float bc;
    int row = blockIdx.x, t = threadIdx.x;
    const float* rp = in + (size_t)row * DD;
    float v0 = rp[t], v1 = rp[t + 128], v2 = rp[t + 256], v3 = rp[t + 384];
    float s = v0 + v1 + v2 + v3;
    #pragma unroll
    for (int o = 16; o; o >>= 1) s += __shfl_xor_sync(0xffffffffu, s, o);
    if ((t & 31) == 0) red[t >> 5] = s;
    __syncthreads();
    if (t == 0) bc = (red[0] + red[1] + red[2] + red[3]) * (1.0f / 512.0f);
    __syncthreads();
    float mean = bc;
    float d0 = v0 - mean, d1 = v1 - mean, d2 = v2 - mean, d3 = v3 - mean;
    float ss = d0 * d0 + d1 * d1 + d2 * d2 + d3 * d3;
    #pragma unroll
    for (int o = 16; o; o >>= 1) ss += __shfl_xor_sync(0xffffffffu, ss, o);
    __syncthreads();
    if ((t & 31) == 0) red[t >> 5] = ss;
    __syncthreads();
    if (t == 0) bc = (red[0] + red[1] + red[2] + red[3]) * (1.0f / 512.0f);
    __syncthreads();
    float inv = rsqrtf(bc + 1e-9f);
    float* op = out + (size_t)row * DD;
    uint32_t* tp = tout + (size_t)row * DD;
    float r0 = gam[t]       * d0 * inv + bet[t];
    float r1 = gam[t + 128] * d1 * inv + bet[t + 128];
    float r2 = gam[t + 256] * d2 * inv + bet[t + 256];
    float r3 = gam[t + 384] * d3 * inv + bet[t + 384];
    op[t] = r0; op[t + 128] = r1; op[t + 256] = r2; op[t + 384] = r3;
    tp[t] = f2tf(r0); tp[t + 128] = f2tf(r1); tp[t + 256] = f2tf(r2); tp[t + 384] = f2tf(r3);
}

// ---------------- final aw write: exp(logit - mx) * rc/Z (float4), last layer slice ----------------
__global__ __launch_bounds__(256) void awout_kernel(float4* __restrict__ out, int loff) {
    size_t i = (size_t)blockIdx.x * 256 + threadIdx.x;   // float4 units
    int bh = (int)(i >> 18);                              // 2^18 float4 per (b,h)
    float s = g_rowcount / g_sum[loff + bh];
    float mx = o2f(g_maxbits[loff + bh]);
    float4 v = ((const float4*)g_e)[i];
    v.x = __expf(v.x - mx) * s; v.y = __expf(v.y - mx) * s;
    v.z = __expf(v.z - mx) * s; v.w = __expf(v.w - mx) * s;
    out[i] = v;
}

// ---------------- launch ----------------
extern "C" void kernel_launch(void* const* d_in, const int* in_sizes, int n_in,
                              void* d_out, int out_size)
{
    const float* x_in  = (const float*)d_in[0];
    const float* mask  = (const float*)d_in[1];
    const int*   protok= (const int*)  d_in[2];
    const float* wq_w  = (const float*)d_in[3];
    const float* wq_b  = (const float*)d_in[4];
    const float* wk_w  = (const float*)d_in[5];
    const float* wk_b  = (const float*)d_in[6];
    const float* wv_w  = (const float*)d_in[7];
    const float* wv_b  = (const float*)d_in[8];
    const float* wo_w  = (const float*)d_in[9];
    const float* wo_b  = (const float*)d_in[10];
    const float* w1    = (const float*)d_in[11];
    const float* b1    = (const float*)d_in[12];
    const float* w2    = (const float*)d_in[13];
    const float* b2    = (const float*)d_in[14];
    const float* ln1g  = (const float*)d_in[15];
    const float* ln1b  = (const float*)d_in[16];
    const float* ln2g  = (const float*)d_in[17];
    const float* ln2b  = (const float*)d_in[18];

    float *px, *patt, *py, *po1;
    uint32_t *pxt, *po1t, *pht;
    float *pbqkv;
    uint32_t *pwqkv, *pwo, *pw1, *pw2;
    cudaGetSymbolAddress((void**)&px,    g_x);
    cudaGetSymbolAddress((void**)&pxt,   g_xt);
    cudaGetSymbolAddress((void**)&patt,  g_att);
    cudaGetSymbolAddress((void**)&py,    g_y);
    cudaGetSymbolAddress((void**)&po1,   g_o1);
    cudaGetSymbolAddress((void**)&po1t,  g_o1t);
    cudaGetSymbolAddress((void**)&pht,   g_ht);
    cudaGetSymbolAddress((void**)&pwqkv, g_wqkv);
    cudaGetSymbolAddress((void**)&pwo,   g_wo_t);
    cudaGetSymbolAddress((void**)&pw1,   g_w1t);
    cudaGetSymbolAddress((void**)&pw2,   g_w2t);
    cudaGetSymbolAddress((void**)&pbqkv, g_bqkv);

    cudaFuncSetAttribute(logits_mma, cudaFuncAttributeMaxDynamicSharedMemorySize, LOGITS_SMEM);
    cudaFuncSetAttribute(attv_mma,   cudaFuncAttributeMaxDynamicSharedMemorySize, ATTV_SMEM);

    // one-time prep
    rowcount_kernel<<<1, 1024>>>(protok);
    pack_qkv_kernel<<<3072, 256>>>(wq_w, wk_w, wv_w, wq_b, wk_b, wv_b);
    cvtw_kernel<<<1024, 256>>>(wo_w, pwo, 512 * 512);
    cvtw_kernel<<<4096, 256>>>(w1,   pw1, 512 * 2048);
    cvtw_kernel<<<4096, 256>>>(w2,   pw2, 2048 * 512);
    copyx_kernel<<<XN / 4 / 256, 256>>>((const float4*)x_in);

    for (int l = 0; l < NLAYERS; l++) {
        int loff = l * BB * HH;
        gemm_pt<<<dim3(24, 32), 256>>>(pxt, pwqkv, pbqkv, nullptr, nullptr, nullptr,
                                       BB*SS, 1536, DD, 0, 2);
        logits_mma<<<dim3(16, 8, 32), 256, LOGITS_SMEM>>>(mask, loff);
        attv_mma<<<dim3(8, 32), 256, ATTV_SMEM>>>(loff);
        gemm_pf<<<dim3(8, 32), 256>>>(patt, pwo, wo_b, px, py, BB*SS, DD, DD, loff);
        ln_kernel<<<BB*SS, 128>>>(py, ln1g, ln1b, po1, po1t);
        gemm_pt<<<dim3(32, 32), 256>>>(po1t, pw1, b1, nullptr, nullptr, pht,
                                       BB*SS, DFFN, DD, 1, 4);
        gemm_pt<<<dim3(8, 32), 256>>>(pht, pw2, b2, po1, py, nullptr,
                                      BB*SS, DD, DFFN, 0, 0);
        ln_kernel<<<BB*SS, 128>>>(py, ln2g, ln2b, px, pxt);
    }

    if (out_size >= XN) {
        copy4_kernel<<<XN / 4 / 256, 256>>>((float4*)d_out, (const float4*)px, XN / 4);
    }
    if (out_size >= XN + AWN) {
        awout_kernel<<<AWN / 4 / 256, 256>>>((float4*)((float*)d_out + XN), (NLAYERS - 1) * BB * HH);
    }
}

// round 17
// speedup vs baseline: 1.2611x; 1.0516x over previous
#include <cuda_runtime.h>
#include <math.h>
#include <stdint.h>

#define BB      4
#define SS      1024
#define DD      512
#define HH      8
#define DEP     64
#define DFFN    2048
#define NLAYERS 4

#define XN  (BB*SS*DD)       /* 2097152  */
#define AWN (BB*HH*SS*SS)    /* 33554432 */

// ---------------- device scratch (no allocation allowed) ----------------
__device__ float    g_x   [XN];
__device__ uint32_t g_xt  [XN];            // tf32 copy of g_x
__device__ uint32_t g_qkvhi[3*XN];         // tf32 hi: q | k | v (head-split layout)
__device__ uint32_t g_qkvlo[2*XN];         // tf32 lo: q | k only (V consumed as hi-only)
__device__ float    g_att [XN];
__device__ float    g_y   [XN];
__device__ float    g_o1  [XN];
__device__ uint32_t g_o1t [XN];            // tf32 copy of o1
__device__ uint32_t g_ht  [BB*SS*DFFN];    // tf32 relu(h)
__device__ float    g_e   [AWN];           // logits (exp fused downstream)
__device__ int      g_maxbits[NLAYERS*BB*HH];
__device__ float    g_sum    [NLAYERS*BB*HH];
__device__ float    g_rowcount;
// tf32-packed weights (prepared once per launch)
__device__ uint32_t g_wqkv[512*1536];
__device__ uint32_t g_wo_t[512*512];
__device__ uint32_t g_w1t [512*2048];
__device__ uint32_t g_w2t [2048*512];
__device__ float    g_bqkv[1536];

// ---------------- helpers ----------------
__device__ __forceinline__ int f2o(float f) {
    int i = __float_as_int(f);
    return (i >= 0) ? i : (i ^ 0x7FFFFFFF);
}
__device__ __forceinline__ float o2f(int i) {
    return __int_as_float((i >= 0) ? i : (i ^ 0x7FFFFFFF));
}
__device__ __forceinline__ uint32_t f2tf(float f) {
    uint32_t u;
    asm("cvt.rna.tf32.f32 %0, %1;" : "=r"(u) : "f"(f));
    return u;
}
__device__ __forceinline__ void mma_tf32(float* c, const uint32_t* a, const uint32_t* b) {
    asm volatile(
        "mma.sync.aligned.m16n8k8.row.col.f32.tf32.tf32.f32 "
        "{%0,%1,%2,%3}, {%4,%5,%6,%7}, {%8,%9}, {%0,%1,%2,%3};\n"
        : "+f"(c[0]), "+f"(c[1]), "+f"(c[2]), "+f"(c[3])
        : "r"(a[0]), "r"(a[1]), "r"(a[2]), "r"(a[3]), "r"(b[0]), "r"(b[1]));
}

// ---------------- row_count + all-layer reduction init ----------------
__global__ void rowcount_kernel(const int* __restrict__ protok) {
    __shared__ int red[32];
    int t = threadIdx.x;
    int c = (protok[t] != 0) ? 1 : 0;
    #pragma unroll
    for (int o = 16; o; o >>= 1) c += __shfl_xor_sync(0xffffffffu, c, o);
    if ((t & 31) == 0) red[t >> 5] = c;
    __syncthreads();
    if (t < 32) {
        int v = red[t];
        #pragma unroll
        for (int o = 16; o; o >>= 1) v += __shfl_xor_sync(0xffffffffu, v, o);
        if (t == 0) g_rowcount = (float)v;
    }
    if (t < NLAYERS * BB * HH) { g_maxbits[t] = (int)0x80000000; g_sum[t] = 0.0f; }
}

__global__ void copy4_kernel(float4* __restrict__ dst, const float4* __restrict__ src, int n4) {
    int i = blockIdx.x * blockDim.x + threadIdx.x;
    if (i < n4) dst[i] = src[i];
}

// initial x: write fp32 + tf32 twin
__global__ void copyx_kernel(const float4* __restrict__ src) {
    int i = blockIdx.x * 256 + threadIdx.x;
    float4 v = src[i];
    ((float4*)g_x)[i] = v;
    uint4 t;
    t.x = f2tf(v.x); t.y = f2tf(v.y); t.z = f2tf(v.z); t.w = f2tf(v.w);
    ((uint4*)g_xt)[i] = t;
}

// ---------------- weight preparation (once per launch) ----------------
__global__ void pack_qkv_kernel(const float* __restrict__ wq, const float* __restrict__ wk,
                                const float* __restrict__ wv, const float* __restrict__ bq,
                                const float* __restrict__ bk, const float* __restrict__ bv) {
    int i = blockIdx.x * 256 + threadIdx.x;
    if (i < 512 * 1536) {
        int k = i / 1536, n = i % 1536;
        const float* w = (n < 512) ? wq : (n < 1024) ? wk : wv;
        g_wqkv[i] = f2tf(w[k * 512 + (n & 511)]);
    }
    if (i < 1536) {
        g_bqkv[i] = (i < 512) ? bq[i] : (i < 1024) ? bk[i - 512] : bv[i - 1024];
    }
}
__global__ void cvtw_kernel(const float* __restrict__ w, uint32_t* __restrict__ dst, int n) {
    int i = blockIdx.x * 256 + threadIdx.x;
    if (i < n) dst[i] = f2tf(w[i]);
}

#define KC 32
#define APITCH 36    /* (4g+tg)%32 conflict-free */
#define BPITCH 72    /* (8tg+g)%32 conflict-free */

// ================= gemm_pt: A already tf32 (uint32) — zero-ALU fill =================
// mode: 0 = fp32 C (+R); 2 = QKV head-split (Q,K: hi+lo; V: hi only); 4 = tf32-only out.
__global__ __launch_bounds__(256) void gemm_pt(
    const uint32_t* __restrict__ A, const uint32_t* __restrict__ W,
    const float* __restrict__ bias, const float* __restrict__ R,
    float* __restrict__ C, uint32_t* __restrict__ Ct,
    int M, int N, int K, int relu, int mode)
{
    __shared__ uint32_t As[128 * APITCH];
    __shared__ uint32_t Bs[KC * BPITCH];

    int tid  = threadIdx.x;
    int warp = tid >> 5, lane = tid & 31;
    int wm = (warp & 3) << 5;
    int wn = (warp >> 2) << 5;
    int g  = lane >> 2, tg = lane & 3;

    int m0 = blockIdx.y << 7, n0 = blockIdx.x << 6;

    int arow = tid >> 3, acol = (tid & 7) << 2;    // A: 128 x 32
    int brow = tid >> 4, bcol = (tid & 15) << 2;   // B: 32 x 64

    const uint32_t* Aptr = &A[(size_t)(m0 + arow) * K + acol];
    const uint32_t* Wptr = &W[(size_t)brow * N + n0 + bcol];

    uint4 ra[4];
    uint4 rb[2];

    #pragma unroll
    for (int i = 0; i < 4; i++) ra[i] = *(const uint4*)(Aptr + (size_t)(i << 5) * K);
    #pragma unroll
    for (int i = 0; i < 2; i++) rb[i] = *(const uint4*)(Wptr + (size_t)(i << 4) * N);

    float acc[2][4][4];
    #pragma unroll
    for (int i = 0; i < 2; i++)
        #pragma unroll
        for (int j = 0; j < 4; j++)
            #pragma unroll
            for (int r = 0; r < 4; r++) acc[i][j][r] = 0.0f;

    int nch = K / KC;
    for (int ch = 0; ch < nch; ch++) {
        #pragma unroll
        for (int i = 0; i < 4; i++)
            *(uint4*)&As[(arow + (i << 5)) * APITCH + acol] = ra[i];
        #pragma unroll
        for (int i = 0; i < 2; i++)
            *(uint4*)&Bs[(brow + (i << 4)) * BPITCH + bcol] = rb[i];
        __syncthreads();

        if (ch + 1 < nch) {
            int k0 = (ch + 1) * KC;
            #pragma unroll
            for (int i = 0; i < 4; i++) ra[i] = *(const uint4*)(Aptr + (size_t)(i << 5) * K + k0);
            #pragma unroll
            for (int i = 0; i < 2; i++) rb[i] = *(const uint4*)(Wptr + (size_t)((i << 4) + k0) * N);
        }

        #pragma unroll
        for (int kk = 0; kk < KC; kk += 8) {
            uint32_t af[2][4];
            #pragma unroll
            for (int mt = 0; mt < 2; mt++) {
                int r = wm + (mt << 4) + g;
                af[mt][0] = As[r * APITCH + kk + tg];
                af[mt][1] = As[(r + 8) * APITCH + kk + tg];
                af[mt][2] = As[r * APITCH + kk + tg + 4];
                af[mt][3] = As[(r + 8) * APITCH + kk + tg + 4];
            }
            uint32_t bf[4][2];
            #pragma unroll
            for (int nt = 0; nt < 4; nt++) {
                int cc = wn + (nt << 3) + g;
                bf[nt][0] = Bs[(kk + tg) * BPITCH + cc];
                bf[nt][1] = Bs[(kk + tg + 4) * BPITCH + cc];
            }
            #pragma unroll
            for (int mt = 0; mt < 2; mt++)
                #pragma unroll
                for (int nt = 0; nt < 4; nt++)
                    mma_tf32(acc[mt][nt], af[mt], bf[nt]);
        }
        __syncthreads();
    }

    #pragma unroll
    for (int mt = 0; mt < 2; mt++) {
        #pragma unroll
        for (int nt = 0; nt < 4; nt++) {
            int n = n0 + wn + (nt << 3) + (tg << 1);
            #pragma unroll
            for (int half = 0; half < 2; half++) {
                int mm = m0 + wm + (mt << 4) + g + half * 8;
                float2 v;
                v.x = acc[mt][nt][half * 2 + 0] + bias[n];
                v.y = acc[mt][nt][half * 2 + 1] + bias[n + 1];
                if (R) {
                    const float2 rr = *(const float2*)&R[(size_t)mm * N + n];
                    v.x += rr.x; v.y += rr.y;
                }
                if (relu) { v.x = fmaxf(v.x, 0.0f); v.y = fmaxf(v.y, 0.0f); }
                if (mode == 2) {
                    int which = n >> 9, nl = n & 511;
                    int bb = mm >> 10, s = mm & 1023, hh = nl >> 6, dd = nl & 63;
                    size_t off = (size_t)which * XN +
                                 (((size_t)(bb * HH + hh) << 10) | (size_t)s) * DEP + dd;
                    uint2 hi;
                    hi.x = f2tf(v.x); hi.y = f2tf(v.y);
                    *(uint2*)&g_qkvhi[off] = hi;
                    if (which < 2) {   // lo only for Q,K (attv consumes V as hi-only)
                        uint2 lo;
                        lo.x = f2tf(v.x - __uint_as_float(hi.x));
                        lo.y = f2tf(v.y - __uint_as_float(hi.y));
                        *(uint2*)&g_qkvlo[off] = lo;
                    }
                } else if (mode == 4) {
                    uint2 t;
                    t.x = f2tf(v.x); t.y = f2tf(v.y);
                    *(uint2*)&Ct[(size_t)mm * N + n] = t;
                } else {
                    *(float2*)&C[(size_t)mm * N + n] = v;
                }
            }
        }
    }
}

// ================= gemm_pf: fp32 A with per-(b,h) scaling (O-projection only) =================
__global__ __launch_bounds__(256) void gemm_pf(
    const float* __restrict__ A, const uint32_t* __restrict__ W,
    const float* __restrict__ bias, const float* __restrict__ R,
    float* __restrict__ C, int M, int N, int K, int loff)
{
    __shared__ uint32_t As[128 * APITCH];
    __shared__ uint32_t Bs[KC * BPITCH];

    int tid  = threadIdx.x;
    int warp = tid >> 5, lane = tid & 31;
    int wm = (warp & 3) << 5;
    int wn = (warp >> 2) << 5;
    int g  = lane >> 2, tg = lane & 3;

    int m0 = blockIdx.y << 7, n0 = blockIdx.x << 6;

    int arow = tid >> 3, acol = (tid & 7) << 2;
    int brow = tid >> 4, bcol = (tid & 15) << 2;

    const float* Aptr = &A[(size_t)(m0 + arow) * K + acol];
    const uint32_t* Wptr = &W[(size_t)brow * N + n0 + bcol];

    float sc[8];
    {
        float rc = g_rowcount;
        int b = (m0 + arow) >> 10;
        #pragma unroll
        for (int h = 0; h < 8; h++) sc[h] = rc / g_sum[loff + b * 8 + h];
    }

    float4 ra[4];
    uint4  rb[2];

    #pragma unroll
    for (int i = 0; i < 4; i++) ra[i] = *(const float4*)(Aptr + (size_t)(i << 5) * K);
    #pragma unroll
    for (int i = 0; i < 2; i++) rb[i] = *(const uint4*)(Wptr + (size_t)(i << 4) * N);

    float acc[2][4][4];
    #pragma unroll
    for (int i = 0; i < 2; i++)
        #pragma unroll
        for (int j = 0; j < 4; j++)
            #pragma unroll
            for (int r = 0; r < 4; r++) acc[i][j][r] = 0.0f;

    int nch = K / KC;
    for (int ch = 0; ch < nch; ch++) {
        float s = sc[(ch * KC + acol) >> 6];
        #pragma unroll
        for (int i = 0; i < 4; i++) {
            uint32_t* p = &As[(arow + (i << 5)) * APITCH + acol];
            p[0] = f2tf(ra[i].x * s); p[1] = f2tf(ra[i].y * s);
            p[2] = f2tf(ra[i].z * s); p[3] = f2tf(ra[i].w * s);
        }
        #pragma unroll
        for (int i = 0; i < 2; i++)
            *(uint4*)&Bs[(brow + (i << 4)) * BPITCH + bcol] = rb[i];
        __syncthreads();

        if (ch + 1 < nch) {
            int k0 = (ch + 1) * KC;
            #pragma unroll
            for (int i = 0; i < 4; i++) ra[i] = *(const float4*)(Aptr + (size_t)(i << 5) * K + k0);
            #pragma unroll
            for (int i = 0; i < 2; i++) rb[i] = *(const uint4*)(Wptr + (size_t)((i << 4) + k0) * N);
        }

        #pragma unroll
        for (int kk = 0; kk < KC; kk += 8) {
            uint32_t af[2][4];
            #pragma unroll
            for (int mt = 0; mt < 2; mt++) {
                int r = wm + (mt << 4) + g;
                af[mt][0] = As[r * APITCH + kk + tg];
                af[mt][1] = As[(r + 8) * APITCH + kk + tg];
                af[mt][2] = As[r * APITCH + kk + tg + 4];
                af[mt][3] = As[(r + 8) * APITCH + kk + tg + 4];
            }
            uint32_t bf[4][2];
            #pragma unroll
            for (int nt = 0; nt < 4; nt++) {
                int cc = wn + (nt << 3) + g;
                bf[nt][0] = Bs[(kk + tg) * BPITCH + cc];
                bf[nt][1] = Bs[(kk + tg + 4) * BPITCH + cc];
            }
            #pragma unroll
            for (int mt = 0; mt < 2; mt++)
                #pragma unroll
                for (int nt = 0; nt < 4; nt++)
                    mma_tf32(acc[mt][nt], af[mt], bf[nt]);
        }
        __syncthreads();
    }

    #pragma unroll
    for (int mt = 0; mt < 2; mt++) {
        #pragma unroll
        for (int nt = 0; nt < 4; nt++) {
            int n = n0 + wn + (nt << 3) + (tg << 1);
            #pragma unroll
            for (int half = 0; half < 2; half++) {
                int mm = m0 + wm + (mt << 4) + g + half * 8;
                float2 v;
                v.x = acc[mt][nt][half * 2 + 0] + bias[n];
                v.y = acc[mt][nt][half * 2 + 1] + bias[n + 1];
                const float2 rr = *(const float2*)&R[(size_t)mm * N + n];
                v.x += rr.x; v.y += rr.y;
                *(float2*)&C[(size_t)mm * N + n] = v;
            }
        }
    }
}

// ========== logits (tf32x3, pre-split operands): (Q K^T + mask*-1e9)/8, fused max ==========
// mask[b,i,j] == mask[b,0,j] (broadcast of pad over i) -> read row 0 only.
#define LOGITS_SMEM ((128*APITCH*2 + 64*APITCH*2) * 4)
__global__ __launch_bounds__(256) void logits_mma(const float* __restrict__ mask, int loff) {
    extern __shared__ uint32_t dsm[];
    uint32_t* Qh = dsm;
    uint32_t* Ql = Qh + 128 * APITCH;
    uint32_t* Kh = Ql + 128 * APITCH;
    uint32_t* Kl = Kh + 64 * APITCH;
    __shared__ float red[8];

    int tid  = threadIdx.x;
    int warp = tid >> 5, lane = tid & 31;
    int wm = (warp & 3) << 5;
    int wn = (warp >> 2) << 5;
    int g  = lane >> 2, tg = lane & 3;

    int bh = blockIdx.z; int bi = bh >> 3;
    int i0 = blockIdx.y << 7, j0 = blockIdx.x << 6;
    const uint32_t* qh = g_qkvhi + (size_t)bh * SS * DEP;
    const uint32_t* ql = g_qkvlo + (size_t)bh * SS * DEP;
    const uint32_t* kh = g_qkvhi + XN + (size_t)bh * SS * DEP;
    const uint32_t* kl = g_qkvlo + XN + (size_t)bh * SS * DEP;

    int arow = tid >> 3, acol = (tid & 7) << 2;

    float acc[2][4][4];
    #pragma unroll
    for (int i = 0; i < 2; i++)
        #pragma unroll
        for (int j = 0; j < 4; j++)
            #pragma unroll
            for (int r = 0; r < 4; r++) acc[i][j][r] = 0.0f;

    for (int k0 = 0; k0 < DEP; k0 += KC) {
        #pragma unroll
        for (int i = 0; i < 4; i++) {
            int r = arow + (i << 5);
            size_t src = (size_t)(i0 + r) * DEP + k0 + acol;
            *(uint4*)&Qh[r * APITCH + acol] = *(const uint4*)&qh[src];
            *(uint4*)&Ql[r * APITCH + acol] = *(const uint4*)&ql[src];
        }
        #pragma unroll
        for (int i = 0; i < 2; i++) {
            int r = arow + (i << 5);
            size_t src = (size_t)(j0 + r) * DEP + k0 + acol;
            *(uint4*)&Kh[r * APITCH + acol] = *(const uint4*)&kh[src];
            *(uint4*)&Kl[r * APITCH + acol] = *(const uint4*)&kl[src];
        }
        __syncthreads();

        #pragma unroll
        for (int kk = 0; kk < KC; kk += 8) {
            uint32_t ahi[2][4], alo[2][4], bhi[4][2], blo[4][2];
            #pragma unroll
            for (int mt = 0; mt < 2; mt++) {
                int r = wm + (mt << 4) + g;
                int o0 = r * APITCH + kk + tg, o1 = (r + 8) * APITCH + kk + tg;
                ahi[mt][0] = Qh[o0];     ahi[mt][1] = Qh[o1];
                ahi[mt][2] = Qh[o0 + 4]; ahi[mt][3] = Qh[o1 + 4];
                alo[mt][0] = Ql[o0];     alo[mt][1] = Ql[o1];
                alo[mt][2] = Ql[o0 + 4]; alo[mt][3] = Ql[o1 + 4];
            }
            #pragma unroll
            for (int nt = 0; nt < 4; nt++) {
                int cc = wn + (nt << 3) + g;
                int o0 = cc * APITCH + kk + tg;
                bhi[nt][0] = Kh[o0]; bhi[nt][1] = Kh[o0 + 4];
                blo[nt][0] = Kl[o0]; blo[nt][1] = Kl[o0 + 4];
            }
            #pragma unroll
            for (int mt = 0; mt < 2; mt++)
                #pragma unroll
                for (int nt = 0; nt < 4; nt++) {
                    mma_tf32(acc[mt][nt], alo[mt], bhi[nt]);
                    mma_tf32(acc[mt][nt], ahi[mt], blo[nt]);
                    mma_tf32(acc[mt][nt], ahi[mt], bhi[nt]);
                }
        }
        __syncthreads();
    }

    float* out = g_e + (size_t)bh * SS * SS;
    float lmax = -INFINITY;
    #pragma unroll
    for (int nt = 0; nt < 4; nt++) {
        int j = j0 + wn + (nt << 3) + (tg << 1);
        const float2 mk = *(const float2*)&mask[(size_t)bi * SS * SS + j];
        #pragma unroll
        for (int mt = 0; mt < 2; mt++) {
            #pragma unroll
            for (int half = 0; half < 2; half++) {
                int i = i0 + wm + (mt << 4) + g + half * 8;
                float2 v;
                v.x = (acc[mt][nt][half * 2 + 0] + mk.x * (-1e9f)) * 0.125f;
                v.y = (acc[mt][nt][half * 2 + 1] + mk.y * (-1e9f)) * 0.125f;
                *(float2*)&out[(size_t)i * SS + j] = v;
                lmax = fmaxf(lmax, fmaxf(v.x, v.y));
            }
        }
    }
    #pragma unroll
    for (int o = 16; o; o >>= 1) lmax = fmaxf(lmax, __shfl_xor_sync(0xffffffffu, lmax, o));
    if (lane == 0) red[warp] = lmax;
    __syncthreads();
    if (tid == 0) {
        float m = red[0];
        #pragma unroll
        for (int w = 1; w < 8; w++) m = fmaxf(m, red[w]);
        atomicMax(&g_maxbits[loff + bh], f2o(m));
    }
}

// ========== attv: O = E_hi·V_hi (single-tf32); exp fused; reg-prefetch ==========
#define EPITCH 136
#define ATTV_SMEM ((KC*EPITCH + KC*BPITCH) * 4)
__global__ __launch_bounds__(256) void attv_mma(int loff) {
    extern __shared__ uint32_t dsm[];
    uint32_t* Eh = dsm;
    uint32_t* Vh = Eh + KC * EPITCH;
    __shared__ float red[8];

    int tid  = threadIdx.x;
    int warp = tid >> 5, lane = tid & 31;
    int wm = (warp & 3) << 5;
    int wn = (warp >> 2) << 5;
    int g  = lane >> 2, tg = lane & 3;

    int bh = blockIdx.y; int bat = bh >> 3, hh = bh & 7;
    int j0 = blockIdx.x << 7;
    const float* e = g_e + (size_t)bh * SS * SS;
    const uint32_t* vh = g_qkvhi + 2 * (size_t)XN + (size_t)bh * SS * DEP;
    float mx = o2f(g_maxbits[loff + bh]);

    int erow = tid >> 5, ecol = (tid & 31) << 2;
    int vrow = tid >> 4, vcol = (tid & 15) << 2;

    // prefetch chunk 0
    float4 re[4];
    uint4 rvh[2];
    #pragma unroll
    for (int i = 0; i < 4; i++)
        re[i] = *(const float4*)&e[(size_t)(erow + (i << 3)) * SS + j0 + ecol];
    #pragma unroll
    for (int i = 0; i < 2; i++)
        rvh[i] = *(const uint4*)&vh[(size_t)(vrow + (i << 4)) * DEP + vcol];

    float acc[2][4][4];
    #pragma unroll
    for (int i = 0; i < 2; i++)
        #pragma unroll
        for (int j = 0; j < 4; j++)
            #pragma unroll
            for (int r = 0; r < 4; r++) acc[i][j][r] = 0.0f;

    float lsum = 0.0f;

    for (int i0 = 0; i0 < SS; i0 += KC) {
        #pragma unroll
        for (int i = 0; i < 4; i++) {
            int r = erow + (i << 3);
            float4 le = re[i];
            le.x = __expf(le.x - mx); le.y = __expf(le.y - mx);
            le.z = __expf(le.z - mx); le.w = __expf(le.w - mx);
            lsum += (le.x + le.y) + (le.z + le.w);
            uint4 hi;
            hi.x = f2tf(le.x); hi.y = f2tf(le.y);
            hi.z = f2tf(le.z); hi.w = f2tf(le.w);
            *(uint4*)&Eh[r * EPITCH + ecol] = hi;
        }
        #pragma unroll
        for (int i = 0; i < 2; i++)
            *(uint4*)&Vh[(vrow + (i << 4)) * BPITCH + vcol] = rvh[i];
        __syncthreads();

        if (i0 + KC < SS) {
            int ib = i0 + KC;
            #pragma unroll
            for (int i = 0; i < 4; i++)
                re[i] = *(const float4*)&e[(size_t)(ib + erow + (i << 3)) * SS + j0 + ecol];
            #pragma unroll
            for (int i = 0; i < 2; i++)
                rvh[i] = *(const uint4*)&vh[(size_t)(ib + vrow + (i << 4)) * DEP + vcol];
        }

        #pragma unroll
        for (int kk = 0; kk < KC; kk += 8) {
            uint32_t ahi[2][4], bhi[4][2];
            #pragma unroll
            for (int mt = 0; mt < 2; mt++) {
                int r = wm + (mt << 4) + g;
                int o0 = (kk + tg) * EPITCH + r, o1 = (kk + tg + 4) * EPITCH + r;
                ahi[mt][0] = Eh[o0];     ahi[mt][1] = Eh[o0 + 8];
                ahi[mt][2] = Eh[o1];     ahi[mt][3] = Eh[o1 + 8];
            }
            #pragma unroll
            for (int nt = 0; nt < 4; nt++) {
                int cc = wn + (nt << 3) + g;
                bhi[nt][0] = Vh[(kk + tg) * BPITCH + cc];
                bhi[nt][1] = Vh[(kk + tg + 4) * BPITCH + cc];
            }
            #pragma unroll
            for (int mt = 0; mt < 2; mt++)
                #pragma unroll
                for (int nt = 0; nt < 4; nt++)
                    mma_tf32(acc[mt][nt], ahi[mt], bhi[nt]);
        }
        __syncthreads();
    }

    #pragma unroll
    for (int o = 16; o; o >>= 1) lsum += __shfl_xor_sync(0xffffffffu, lsum, o);
    if (lane == 0) red[warp] = lsum;
    __syncthreads();
    if (tid == 0) {
        float s = 0.0f;
        #pragma unroll
        for (int w = 0; w < 8; w++) s += red[w];
        atomicAdd(&g_sum[loff + bh], s);
    }

    #pragma unroll
    for (int mt = 0; mt < 2; mt++) {
        #pragma unroll
        for (int nt = 0; nt < 4; nt++) {
            int d = wn + (nt << 3) + (tg << 1);
            #pragma unroll
            for (int half = 0; half < 2; half++) {
                int j = j0 + wm + (mt << 4) + g + half * 8;
                float2 o;
                o.x = acc[mt][nt][half * 2 + 0];
                o.y = acc[mt][nt][half * 2 + 1];
                *(float2*)&g_att[((size_t)bat * SS + j) * DD + hh * DEP + d] = o;
            }
        }
    }
}

// ---------------- LayerNorm over last dim (512); writes fp32 + tf32 twin ----------------
__global__ __launch_bounds__(128) void ln_kernel(
    const float* __restrict__ in, const float* __restrict__ gam,
    const float* __restrict__ bet, float* __restrict__ out, uint32_t* __restrict__ tout)
{
    __shared__ float red[4];
    __shared__ float bc;
    int row = blockIdx.x, t = threadIdx.x;
    const float* rp = in + (size_t)row * DD;
    float v0 = rp[t], v1 = rp[t + 128], v2 = rp[t + 256], v3 = rp[t + 384];
    float s = v0 + v1 + v2 + v3;
    #pragma unroll
    for (int o = 16; o; o >>= 1) s += __shfl_xor_sync(0xffffffffu, s, o);
    if ((t & 31) == 0) red[t >> 5] = s;
    __syncthreads();
    if (t == 0) bc = (red[0] + red[1] + red[2] + red[3]) * (1.0f / 512.0f);
    __syncthreads();
    float mean = bc;
    float d0 = v0 - mean, d1 = v1 - mean, d2 = v2 - mean, d3 = v3 - mean;
    float ss = d0 * d0 + d1 * d1 + d2 * d2 + d3 * d3;
    #pragma unroll
    for (int o = 16; o; o >>= 1) ss += __shfl_xor_sync(0xffffffffu, ss, o);
    __syncthreads();
    if ((t & 31) == 0) red[t >> 5] = ss;
    __syncthreads();
    if (t == 0) bc = (red[0] + red[1] + red[2] + red[3]) * (1.0f / 512.0f);
    __syncthreads();
    float inv = rsqrtf(bc + 1e-9f);
    float* op = out + (size_t)row * DD;
    uint32_t* tp = tout + (size_t)row * DD;
    float r0 = gam[t]       * d0 * inv + bet[t];
    float r1 = gam[t + 128] * d1 * inv + bet[t + 128];
    float r2 = gam[t + 256] * d2 * inv + bet[t + 256];
    float r3 = gam[t + 384] * d3 * inv + bet[t + 384];
    op[t] = r0; op[t + 128] = r1; op[t + 256] = r2; op[t + 384] = r3;
    tp[t] = f2tf(r0); tp[t + 128] = f2tf(r1); tp[t + 256] = f2tf(r2); tp[t + 384] = f2tf(r3);
}

// ---------------- final aw write: exp(logit - mx) * rc/Z (float4), last layer slice ----------------
__global__ __launch_bounds__(256) void awout_kernel(float4* __restrict__ out, int loff) {
    size_t i = (size_t)blockIdx.x * 256 + threadIdx.x;   // float4 units
    int bh = (int)(i >> 18);                              // 2^18 float4 per (b,h)
    float s = g_rowcount / g_sum[loff + bh];
    float mx = o2f(g_maxbits[loff + bh]);
    float4 v = ((const float4*)g_e)[i];
    v.x = __expf(v.x - mx) * s; v.y = __expf(v.y - mx) * s;
    v.z = __expf(v.z - mx) * s; v.w = __expf(v.w - mx) * s;
    out[i] = v;
}

// ---------------- launch ----------------
extern "C" void kernel_launch(void* const* d_in, const int* in_sizes, int n_in,
                              void* d_out, int out_size)
{
    const float* x_in  = (const float*)d_in[0];
    const float* mask  = (const float*)d_in[1];
    const int*   protok= (const int*)  d_in[2];
    const float* wq_w  = (const float*)d_in[3];
    const float* wq_b  = (const float*)d_in[4];
    const float* wk_w  = (const float*)d_in[5];
    const float* wk_b  = (const float*)d_in[6];
    const float* wv_w  = (const float*)d_in[7];
    const float* wv_b  = (const float*)d_in[8];
    const float* wo_w  = (const float*)d_in[9];
    const float* wo_b  = (const float*)d_in[10];
    const float* w1    = (const float*)d_in[11];
    const float* b1    = (const float*)d_in[12];
    const float* w2    = (const float*)d_in[13];
    const float* b2    = (const float*)d_in[14];
    const float* ln1g  = (const float*)d_in[15];
    const float* ln1b  = (const float*)d_in[16];
    const float* ln2g  = (const float*)d_in[17];
    const float* ln2b  = (const float*)d_in[18];

    float *px, *patt, *py, *po1;
    uint32_t *pxt, *po1t, *pht;
    float *pbqkv;
    uint32_t *pwqkv, *pwo, *pw1, *pw2;
    cudaGetSymbolAddress((void**)&px,    g_x);
    cudaGetSymbolAddress((void**)&pxt,   g_xt);
    cudaGetSymbolAddress((void**)&patt,  g_att);
    cudaGetSymbolAddress((void**)&py,    g_y);
    cudaGetSymbolAddress((void**)&po1,   g_o1);
    cudaGetSymbolAddress((void**)&po1t,  g_o1t);
    cudaGetSymbolAddress((void**)&pht,   g_ht);
    cudaGetSymbolAddress((void**)&pwqkv, g_wqkv);
    cudaGetSymbolAddress((void**)&pwo,   g_wo_t);
    cudaGetSymbolAddress((void**)&pw1,   g_w1t);
    cudaGetSymbolAddress((void**)&pw2,   g_w2t);
    cudaGetSymbolAddress((void**)&pbqkv, g_bqkv);

    cudaFuncSetAttribute(logits_mma, cudaFuncAttributeMaxDynamicSharedMemorySize, LOGITS_SMEM);
    cudaFuncSetAttribute(attv_mma,   cudaFuncAttributeMaxDynamicSharedMemorySize, ATTV_SMEM);

    // one-time prep
    rowcount_kernel<<<1, 1024>>>(protok);
    pack_qkv_kernel<<<3072, 256>>>(wq_w, wk_w, wv_w, wq_b, wk_b, wv_b);
    cvtw_kernel<<<1024, 256>>>(wo_w, pwo, 512 * 512);
    cvtw_kernel<<<4096, 256>>>(w1,   pw1, 512 * 2048);
    cvtw_kernel<<<4096, 256>>>(w2,   pw2, 2048 * 512);
    copyx_kernel<<<XN / 4 / 256, 256>>>((const float4*)x_in);

    for (int l = 0; l < NLAYERS; l++) {
        int loff = l * BB * HH;
        gemm_pt<<<dim3(24, 32), 256>>>(pxt, pwqkv, pbqkv, nullptr, nullptr, nullptr,
                                       BB*SS, 1536, DD, 0, 2);
        logits_mma<<<dim3(16, 8, 32), 256, LOGITS_SMEM>>>(mask, loff);
        attv_mma<<<dim3(8, 32), 256, ATTV_SMEM>>>(loff);
        gemm_pf<<<dim3(8, 32), 256>>>(patt, pwo, wo_b, px, py, BB*SS, DD, DD, loff);
        ln_kernel<<<BB*SS, 128>>>(py, ln1g, ln1b, po1, po1t);
        gemm_pt<<<dim3(32, 32), 256>>>(po1t, pw1, b1, nullptr, nullptr, pht,
                                       BB*SS, DFFN, DD, 1, 4);
        gemm_pt<<<dim3(8, 32), 256>>>(pht, pw2, b2, po1, py, nullptr,
                                      BB*SS, DD, DFFN, 0, 0);
        ln_kernel<<<BB*SS, 128>>>(py, ln2g, ln2b, px, pxt);
    }

    if (out_size >= XN) {
        copy4_kernel<<<XN / 4 / 256, 256>>>((float4*)d_out, (const float4*)px, XN / 4);
    }
    if (out_size >= XN + AWN) {
        awout_kernel<<<AWN / 4 / 256, 256>>>((float4*)((float*)d_out + XN), (NLAYERS - 1) * BB * HH);
    }
}